// round 3
// baseline (speedup 1.0000x reference)
#include <cuda_runtime.h>

#define NN     50000
#define ER     1600000
#define ET     1650000      // edges + self loops
#define INCH   128
#define J1     96           // HEADS*HID
#define HEADS  3
#define HID    32
#define OC     32
#define NEG    0.2f

// ---------------- scratch (device globals; no allocation allowed) ----------------
__device__ int      g_fmt;          // 0 = int64 edge buffer, 1 = int32
__device__ int      g_src[ET];
__device__ int      g_dst[ET];
__device__ float    g_h1 [NN * J1];
__device__ float    g_as1[NN * HEADS];
__device__ float    g_ad1[NN * HEADS];
__device__ unsigned g_m1 [NN * HEADS];
__device__ float    g_s1 [NN * HEADS];
__device__ float    g_e1 [ET * HEADS];
__device__ float    g_o1 [NN * J1];
__device__ float    g_h2 [NN * OC];
__device__ float    g_as2[NN];
__device__ float    g_ad2[NN];
__device__ unsigned g_m2 [NN];
__device__ float    g_s2 [NN];
__device__ float    g_e2 [ET];
__device__ float    g_o2 [NN * OC];

// ---------------- helpers ----------------
__device__ __forceinline__ unsigned encf(float f) {
    int i = __float_as_int(f);
    return (i >= 0) ? ((unsigned)i | 0x80000000u) : (unsigned)(~i);
}
__device__ __forceinline__ float decf(unsigned u) {
    int i = (u & 0x80000000u) ? (int)(u & 0x7fffffffu) : ~(int)u;
    return __int_as_float(i);
}
__device__ __forceinline__ float wsum(float v) {
    v += __shfl_down_sync(0xffffffffu, v, 16);
    v += __shfl_down_sync(0xffffffffu, v, 8);
    v += __shfl_down_sync(0xffffffffu, v, 4);
    v += __shfl_down_sync(0xffffffffu, v, 2);
    v += __shfl_down_sync(0xffffffffu, v, 1);
    return v;
}
__device__ __forceinline__ int clampi(int v) {
    return v < 0 ? 0 : (v >= NN ? NN - 1 : v);
}

// ---------------- kernels ----------------
// Detect whether the edge buffer is int64 or int32.
// int64 values < 50000 => every odd int32 slot is exactly 0.
__global__ void k_detect(const int* __restrict__ ei32) {
    __shared__ int nz;
    if (threadIdx.x == 0) nz = 0;
    __syncthreads();
    for (int i = threadIdx.x; i < 2048; i += blockDim.x) {
        if (ei32[2 * i * 391 + 1] != 0) atomicOr(&nz, 1);
    }
    __syncthreads();
    if (threadIdx.x == 0) g_fmt = nz ? 1 : 0;   // nonzero odd slot -> int32
}

__global__ void k_conv(const void* __restrict__ eiv) {
    int e = blockIdx.x * blockDim.x + threadIdx.x;
    if (e >= ET) return;
    if (e < ER) {
        int s, d;
        if (g_fmt == 0) {
            const long long* ei = (const long long*)eiv;
            s = (int)ei[e]; d = (int)ei[ER + e];
        } else {
            const int* ei = (const int*)eiv;
            s = ei[e]; d = ei[ER + e];
        }
        g_src[e] = clampi(s);
        g_dst[e] = clampi(d);
    } else {
        int i = e - ER;
        g_src[e] = i;
        g_dst[e] = i;
    }
}

__global__ void k_zero1() {
    int i = blockIdx.x * blockDim.x + threadIdx.x;
    if (i < NN * J1) g_o1[i] = 0.f;
    if (i < NN * HEADS) { g_m1[i] = 0u; g_s1[i] = 0.f; }
}
__global__ void k_zero2() {
    int i = blockIdx.x * blockDim.x + threadIdx.x;
    if (i < NN * OC) g_o2[i] = 0.f;
    if (i < NN) { g_m2[i] = 0u; g_s2[i] = 0.f; }
}

// h1 = x @ W1 ; a_s1/a_d1 per node per head. blockDim = 96 (one thread per col).
__global__ void k_gemm1(const float* __restrict__ x, const float* __restrict__ W,
                        const float* __restrict__ aS, const float* __restrict__ aD) {
    __shared__ float Xsh[16 * INCH];   // 8 KB
    const int R = 16;
    int j = threadIdx.x;
    int hh = j >> 5, lane = j & 31;
    float aws = aS[hh * HID + lane];
    float awd = aD[hh * HID + lane];

    for (int tile = blockIdx.x; tile < NN / R; tile += gridDim.x) {
        int base = tile * R;
        __syncthreads();
        for (int i = j; i < R * INCH; i += J1) Xsh[i] = x[base * INCH + i];
        __syncthreads();
        #pragma unroll
        for (int r = 0; r < R; r += 4) {
            float a0 = 0.f, a1 = 0.f, a2 = 0.f, a3 = 0.f;
            #pragma unroll 16
            for (int k = 0; k < INCH; k++) {
                float w = __ldg(&W[k * J1 + j]);
                a0 += Xsh[(r + 0) * INCH + k] * w;
                a1 += Xsh[(r + 1) * INCH + k] * w;
                a2 += Xsh[(r + 2) * INCH + k] * w;
                a3 += Xsh[(r + 3) * INCH + k] * w;
            }
            g_h1[(base + r + 0) * J1 + j] = a0;
            g_h1[(base + r + 1) * J1 + j] = a1;
            g_h1[(base + r + 2) * J1 + j] = a2;
            g_h1[(base + r + 3) * J1 + j] = a3;
            float v;
            v = wsum(a0 * aws); if (lane == 0) g_as1[(base + r + 0) * HEADS + hh] = v;
            v = wsum(a0 * awd); if (lane == 0) g_ad1[(base + r + 0) * HEADS + hh] = v;
            v = wsum(a1 * aws); if (lane == 0) g_as1[(base + r + 1) * HEADS + hh] = v;
            v = wsum(a1 * awd); if (lane == 0) g_ad1[(base + r + 1) * HEADS + hh] = v;
            v = wsum(a2 * aws); if (lane == 0) g_as1[(base + r + 2) * HEADS + hh] = v;
            v = wsum(a2 * awd); if (lane == 0) g_ad1[(base + r + 2) * HEADS + hh] = v;
            v = wsum(a3 * aws); if (lane == 0) g_as1[(base + r + 3) * HEADS + hh] = v;
            v = wsum(a3 * awd); if (lane == 0) g_ad1[(base + r + 3) * HEADS + hh] = v;
        }
    }
}

__global__ void k_max1() {
    int e = blockIdx.x * blockDim.x + threadIdx.x;
    if (e >= ET) return;
    int s = g_src[e], d = g_dst[e];
    #pragma unroll
    for (int h = 0; h < HEADS; h++) {
        float v = g_as1[s * HEADS + h] + g_ad1[d * HEADS + h];
        v = v > 0.f ? v : NEG * v;
        g_e1[e * HEADS + h] = v;
        atomicMax(&g_m1[d * HEADS + h], encf(v));
    }
}

__global__ void k_sum1() {
    int e = blockIdx.x * blockDim.x + threadIdx.x;
    if (e >= ET) return;
    int d = g_dst[e];
    #pragma unroll
    for (int h = 0; h < HEADS; h++) {
        float m = decf(g_m1[d * HEADS + h]);
        float p = __expf(g_e1[e * HEADS + h] - m);
        g_e1[e * HEADS + h] = p;
        atomicAdd(&g_s1[d * HEADS + h], p);
    }
}

// warp per edge: gather h1[src] row, scale by alpha, atomically add into out1[dst]
__global__ void k_agg1() {
    long long t = (long long)blockIdx.x * blockDim.x + threadIdx.x;
    int w = (int)(t >> 5);
    int lane = threadIdx.x & 31;
    if (w >= ET) return;
    int s = g_src[w], d = g_dst[w];
    #pragma unroll
    for (int h = 0; h < HEADS; h++) {
        float alpha = g_e1[w * HEADS + h] / (g_s1[d * HEADS + h] + 1e-16f);
        float v = g_h1[s * J1 + h * HID + lane] * alpha;
        atomicAdd(&g_o1[d * J1 + h * HID + lane], v);
    }
}

__global__ void k_elu(const float* __restrict__ b1) {
    int i = blockIdx.x * blockDim.x + threadIdx.x;
    if (i >= NN * J1) return;
    int c = i % J1;
    float v = g_o1[i] + b1[c];
    g_o1[i] = v > 0.f ? v : (__expf(v) - 1.f);
}

// h2 = elu(out1) @ W2 ; a_s2/a_d2. blockDim 256 = 8 rows x 32 cols per block.
__global__ void k_gemm2(const float* __restrict__ W, const float* __restrict__ aS,
                        const float* __restrict__ aD) {
    __shared__ float Wsh[J1 * OC];   // 12 KB
    __shared__ float Xsh[8 * J1];
    int tid = threadIdx.x;
    for (int i = tid; i < J1 * OC; i += 256) Wsh[i] = W[i];
    int r = tid >> 5, lane = tid & 31;
    float aws = aS[lane], awd = aD[lane];
    for (int base = blockIdx.x * 8; base < NN; base += gridDim.x * 8) {
        __syncthreads();
        for (int i = tid; i < 8 * J1; i += 256) {
            int rr = i / J1, k = i - rr * J1;
            int row = base + rr;
            Xsh[i] = (row < NN) ? g_o1[row * J1 + k] : 0.f;
        }
        __syncthreads();
        int row = base + r;
        float acc = 0.f;
        #pragma unroll 16
        for (int k = 0; k < J1; k++) acc += Xsh[r * J1 + k] * Wsh[k * OC + lane];
        if (row < NN) {
            g_h2[row * OC + lane] = acc;
            float vs = wsum(acc * aws);
            float vd = wsum(acc * awd);
            if (lane == 0) { g_as2[row] = vs; g_ad2[row] = vd; }
        }
    }
}

__global__ void k_max2() {
    int e = blockIdx.x * blockDim.x + threadIdx.x;
    if (e >= ET) return;
    int s = g_src[e], d = g_dst[e];
    float v = g_as2[s] + g_ad2[d];
    v = v > 0.f ? v : NEG * v;
    g_e2[e] = v;
    atomicMax(&g_m2[d], encf(v));
}

__global__ void k_sum2() {
    int e = blockIdx.x * blockDim.x + threadIdx.x;
    if (e >= ET) return;
    int d = g_dst[e];
    float p = __expf(g_e2[e] - decf(g_m2[d]));
    g_e2[e] = p;
    atomicAdd(&g_s2[d], p);
}

__global__ void k_agg2() {
    long long t = (long long)blockIdx.x * blockDim.x + threadIdx.x;
    int w = (int)(t >> 5);
    int lane = threadIdx.x & 31;
    if (w >= ET) return;
    int s = g_src[w], d = g_dst[w];
    float alpha = g_e2[w] / (g_s2[d] + 1e-16f);
    atomicAdd(&g_o2[d * OC + lane], g_h2[s * OC + lane] * alpha);
}

// prob = sigmoid((out2 + b2) @ Wp + bp), warp per node
__global__ void k_final(const float* __restrict__ b2, const float* __restrict__ Wp,
                        const float* __restrict__ bp, float* __restrict__ out) {
    int w = (int)((blockIdx.x * blockDim.x + threadIdx.x) >> 5);
    int lane = threadIdx.x & 31;
    if (w >= NN) return;
    float v = (g_o2[w * OC + lane] + b2[lane]) * Wp[lane];
    v = wsum(v);
    if (lane == 0) out[w] = 1.f / (1.f + __expf(-v - bp[0]));
}

// ---------------- launch ----------------
extern "C" void kernel_launch(void* const* d_in, const int* in_sizes, int n_in,
                              void* d_out, int out_size) {
    const float* x   = (const float*)d_in[0];
    const void*  ei  = d_in[1];
    const float* W1  = (const float*)d_in[2];
    const float* as1 = (const float*)d_in[3];
    const float* ad1 = (const float*)d_in[4];
    const float* b1  = (const float*)d_in[5];
    const float* W2  = (const float*)d_in[6];
    const float* as2 = (const float*)d_in[7];
    const float* ad2 = (const float*)d_in[8];
    const float* b2  = (const float*)d_in[9];
    const float* Wp  = (const float*)d_in[10];
    const float* bp  = (const float*)d_in[11];
    float* out = (float*)d_out;

    // warp-per-edge kernels need ET*32 threads (this was the R2 bug: ET*8)
    const long long aggT = (long long)ET * 32;
    const int aggBlocks = (int)((aggT + 255) / 256);

    k_detect<<<1, 256>>>((const int*)ei);
    k_conv<<<(ET + 255) / 256, 256>>>(ei);
    k_zero1<<<(NN * J1 + 255) / 256, 256>>>();
    k_zero2<<<(NN * OC + 255) / 256, 256>>>();
    k_gemm1<<<625, J1>>>(x, W1, as1, ad1);
    k_max1<<<(ET + 255) / 256, 256>>>();
    k_sum1<<<(ET + 255) / 256, 256>>>();
    k_agg1<<<aggBlocks, 256>>>();
    k_elu<<<(NN * J1 + 255) / 256, 256>>>(b1);
    k_gemm2<<<1250, 256>>>(W2, as2, ad2);
    k_max2<<<(ET + 255) / 256, 256>>>();
    k_sum2<<<(ET + 255) / 256, 256>>>();
    k_agg2<<<aggBlocks, 256>>>();
    k_final<<<(NN * 32 + 255) / 256, 256>>>(b2, Wp, bp, out);
}

// round 5
// speedup vs baseline: 1.7473x; 1.7473x over previous
#include <cuda_runtime.h>

#define NN     50000
#define ER     1600000
#define ET     1650000      // edges + self loops
#define INCH   128
#define J1     96           // HEADS*HID
#define HEADS  3
#define HID    32
#define OC     32
#define NEG    0.2f

// ---------------- scratch (device globals; no allocation allowed) ----------------
__device__ int   g_fmt;                       // 0 = int64 edge buffer, 1 = int32
__device__ __align__(16) int   g_src[ET];
__device__ __align__(16) int   g_dst[ET];
__device__ __align__(16) float g_h1 [NN * J1];
__device__ __align__(16) float g_as1[NN * HEADS];
__device__ __align__(16) float g_ad1[NN * HEADS];
__device__ __align__(16) float g_s1 [NN * HEADS];
__device__ __align__(16) float g_p1 [ET * HEADS];
__device__ __align__(16) float g_o1 [NN * J1];
__device__ __align__(16) float g_h2 [NN * OC];
__device__ __align__(16) float g_as2[NN];
__device__ __align__(16) float g_ad2[NN];
__device__ __align__(16) float g_s2 [NN];
__device__ __align__(16) float g_p2 [ET];
__device__ __align__(16) float g_o2 [NN * OC];

// ---------------- helpers ----------------
__device__ __forceinline__ float wsum(float v) {
    v += __shfl_down_sync(0xffffffffu, v, 16);
    v += __shfl_down_sync(0xffffffffu, v, 8);
    v += __shfl_down_sync(0xffffffffu, v, 4);
    v += __shfl_down_sync(0xffffffffu, v, 2);
    v += __shfl_down_sync(0xffffffffu, v, 1);
    return v;
}
__device__ __forceinline__ int clampi(int v) {
    return v < 0 ? 0 : (v >= NN ? NN - 1 : v);
}
__device__ __forceinline__ void red4(float* addr, float x, float y, float z, float w) {
#if __CUDA_ARCH__ >= 900
    asm volatile("red.global.add.v4.f32 [%0], {%1,%2,%3,%4};"
                 :: "l"(addr), "f"(x), "f"(y), "f"(z), "f"(w) : "memory");
#else
    atomicAdd(addr + 0, x); atomicAdd(addr + 1, y);
    atomicAdd(addr + 2, z); atomicAdd(addr + 3, w);
#endif
}

// ---------------- kernels ----------------
// Detect int64 vs int32 edge buffer: int64 values < 50000 => odd int32 slots all 0.
__global__ void k_detect(const int* __restrict__ ei32) {
    __shared__ int nz;
    if (threadIdx.x == 0) nz = 0;
    __syncthreads();
    for (int i = threadIdx.x; i < 2048; i += blockDim.x)
        if (ei32[2 * i * 391 + 1] != 0) atomicOr(&nz, 1);
    __syncthreads();
    if (threadIdx.x == 0) g_fmt = nz ? 1 : 0;
}

__global__ void k_conv(const void* __restrict__ eiv) {
    int e = blockIdx.x * blockDim.x + threadIdx.x;
    if (e >= ET) return;
    if (e < ER) {
        int s, d;
        if (g_fmt == 0) {
            const long long* ei = (const long long*)eiv;
            s = (int)ei[e]; d = (int)ei[ER + e];
        } else {
            const int* ei = (const int*)eiv;
            s = ei[e]; d = ei[ER + e];
        }
        g_src[e] = clampi(s);
        g_dst[e] = clampi(d);
    } else {
        int i = e - ER;
        g_src[e] = i;
        g_dst[e] = i;
    }
}

// zero o1, o2, s1, s2 in one pass (indexed over the largest, NN*J1)
__global__ void k_zero() {
    int i = blockIdx.x * blockDim.x + threadIdx.x;
    if (i < NN * J1) g_o1[i] = 0.f;
    if (i < NN * OC) g_o2[i] = 0.f;
    if (i < NN * HEADS) g_s1[i] = 0.f;
    if (i < NN) g_s2[i] = 0.f;
}

// h1 = x @ W1 ; a_s1/a_d1 per node per head. blockDim = 96 (one thread per col).
__global__ void k_gemm1(const float* __restrict__ x, const float* __restrict__ W,
                        const float* __restrict__ aS, const float* __restrict__ aD) {
    __shared__ float Xsh[16 * INCH];   // 8 KB
    const int R = 16;
    int j = threadIdx.x;
    int hh = j >> 5, lane = j & 31;
    float aws = aS[hh * HID + lane];
    float awd = aD[hh * HID + lane];

    for (int tile = blockIdx.x; tile < NN / R; tile += gridDim.x) {
        int base = tile * R;
        __syncthreads();
        for (int i = j; i < R * INCH; i += J1) Xsh[i] = x[base * INCH + i];
        __syncthreads();
        #pragma unroll
        for (int r = 0; r < R; r += 4) {
            float a0 = 0.f, a1 = 0.f, a2 = 0.f, a3 = 0.f;
            #pragma unroll 16
            for (int k = 0; k < INCH; k++) {
                float w = __ldg(&W[k * J1 + j]);
                a0 += Xsh[(r + 0) * INCH + k] * w;
                a1 += Xsh[(r + 1) * INCH + k] * w;
                a2 += Xsh[(r + 2) * INCH + k] * w;
                a3 += Xsh[(r + 3) * INCH + k] * w;
            }
            g_h1[(base + r + 0) * J1 + j] = a0;
            g_h1[(base + r + 1) * J1 + j] = a1;
            g_h1[(base + r + 2) * J1 + j] = a2;
            g_h1[(base + r + 3) * J1 + j] = a3;
            float v;
            v = wsum(a0 * aws); if (lane == 0) g_as1[(base + r + 0) * HEADS + hh] = v;
            v = wsum(a0 * awd); if (lane == 0) g_ad1[(base + r + 0) * HEADS + hh] = v;
            v = wsum(a1 * aws); if (lane == 0) g_as1[(base + r + 1) * HEADS + hh] = v;
            v = wsum(a1 * awd); if (lane == 0) g_ad1[(base + r + 1) * HEADS + hh] = v;
            v = wsum(a2 * aws); if (lane == 0) g_as1[(base + r + 2) * HEADS + hh] = v;
            v = wsum(a2 * awd); if (lane == 0) g_ad1[(base + r + 2) * HEADS + hh] = v;
            v = wsum(a3 * aws); if (lane == 0) g_as1[(base + r + 3) * HEADS + hh] = v;
            v = wsum(a3 * awd); if (lane == 0) g_ad1[(base + r + 3) * HEADS + hh] = v;
        }
    }
}

// Edge attention layer 1: p = exp(leaky_relu(as[s]+ad[d])); s1[d] += p.
// No max pass: logits are O(0.2) here, direct exp is numerically safe and
// algebraically identical after normalization.
__global__ void k_att1() {
    int e = blockIdx.x * blockDim.x + threadIdx.x;
    if (e >= ET) return;
    int s = g_src[e], d = g_dst[e];
    #pragma unroll
    for (int h = 0; h < HEADS; h++) {
        float v = g_as1[s * HEADS + h] + g_ad1[d * HEADS + h];
        v = v > 0.f ? v : NEG * v;
        float p = __expf(v);
        g_p1[e * HEADS + h] = p;
        atomicAdd(&g_s1[d * HEADS + h], p);
    }
}

// s1 -> 1/s1 ONLY (s2 is handled by k_recip2 AFTER k_att2 fills it; touching it
// here was the R4 bug: it turned the zero-initialized s2 into 1e16).
__global__ void k_recip1() {
    int i = blockIdx.x * blockDim.x + threadIdx.x;
    if (i < NN * HEADS) g_s1[i] = 1.f / (g_s1[i] + 1e-16f);
}
__global__ void k_recip2() {
    int i = blockIdx.x * blockDim.x + threadIdx.x;
    if (i < NN) g_s2[i] = 1.f / (g_s2[i] + 1e-16f);
}

// Aggregation layer 1: 4 edges per warp, 8 lanes per edge, 3 float4 per lane.
// Gather h1[src] (128B per 8-lane group per head), scale, red.v4 into o1[dst].
__global__ void k_agg1() {
    long long t = (long long)blockIdx.x * blockDim.x + threadIdx.x;
    int lane = threadIdx.x & 31;
    int sub  = lane >> 3;          // edge within warp
    int l8   = lane & 7;           // lane within edge group
    long long w = t >> 5;
    int e = (int)(w * 4 + sub);
    if (e >= ET) return;
    int s = g_src[e], d = g_dst[e];
    const float4* hsrc = (const float4*)&g_h1[s * J1];
    float*        odst = &g_o1[d * J1];
    #pragma unroll
    for (int h = 0; h < HEADS; h++) {
        float alpha = g_p1[e * HEADS + h] * g_s1[d * HEADS + h];
        float4 v = hsrc[h * 8 + l8];
        red4(odst + h * 32 + l8 * 4, v.x * alpha, v.y * alpha, v.z * alpha, v.w * alpha);
    }
}

// h2 = elu(o1 + b1) @ W2 ; a_s2/a_d2. bias+ELU fused into the X-tile load.
__global__ void k_gemm2(const float* __restrict__ W, const float* __restrict__ b1,
                        const float* __restrict__ aS, const float* __restrict__ aD) {
    __shared__ float Wsh[J1 * OC];   // 12 KB
    __shared__ float Xsh[8 * J1];
    int tid = threadIdx.x;
    for (int i = tid; i < J1 * OC; i += 256) Wsh[i] = W[i];
    int r = tid >> 5, lane = tid & 31;
    float aws = aS[lane], awd = aD[lane];
    for (int base = blockIdx.x * 8; base < NN; base += gridDim.x * 8) {
        __syncthreads();
        for (int i = tid; i < 8 * J1; i += 256) {
            int rr = i / J1, k = i - rr * J1;
            int row = base + rr;
            float v = 0.f;
            if (row < NN) {
                v = g_o1[row * J1 + k] + b1[k];
                v = v > 0.f ? v : (__expf(v) - 1.f);
            }
            Xsh[i] = v;
        }
        __syncthreads();
        int row = base + r;
        float acc = 0.f;
        #pragma unroll 16
        for (int k = 0; k < J1; k++) acc += Xsh[r * J1 + k] * Wsh[k * OC + lane];
        if (row < NN) {
            g_h2[row * OC + lane] = acc;
            float vs = wsum(acc * aws);
            float vd = wsum(acc * awd);
            if (lane == 0) { g_as2[row] = vs; g_ad2[row] = vd; }
        }
    }
}

// Edge attention layer 2
__global__ void k_att2() {
    int e = blockIdx.x * blockDim.x + threadIdx.x;
    if (e >= ET) return;
    int s = g_src[e], d = g_dst[e];
    float v = g_as2[s] + g_ad2[d];
    v = v > 0.f ? v : NEG * v;
    float p = __expf(v);
    g_p2[e] = p;
    atomicAdd(&g_s2[d], p);
}

// Aggregation layer 2: 4 edges per warp, 8 lanes per edge, 1 float4 per lane.
__global__ void k_agg2() {
    long long t = (long long)blockIdx.x * blockDim.x + threadIdx.x;
    int lane = threadIdx.x & 31;
    int sub  = lane >> 3;
    int l8   = lane & 7;
    long long w = t >> 5;
    int e = (int)(w * 4 + sub);
    if (e >= ET) return;
    int s = g_src[e], d = g_dst[e];
    float alpha = g_p2[e] * g_s2[d];
    float4 v = ((const float4*)&g_h2[s * OC])[l8];
    red4(&g_o2[d * OC] + l8 * 4, v.x * alpha, v.y * alpha, v.z * alpha, v.w * alpha);
}

// prob = sigmoid((o2 + b2) @ Wp + bp), warp per node
__global__ void k_final(const float* __restrict__ b2, const float* __restrict__ Wp,
                        const float* __restrict__ bp, float* __restrict__ out) {
    int w = (int)((blockIdx.x * blockDim.x + threadIdx.x) >> 5);
    int lane = threadIdx.x & 31;
    if (w >= NN) return;
    float v = (g_o2[w * OC + lane] + b2[lane]) * Wp[lane];
    v = wsum(v);
    if (lane == 0) out[w] = 1.f / (1.f + __expf(-v - bp[0]));
}

// ---------------- launch ----------------
extern "C" void kernel_launch(void* const* d_in, const int* in_sizes, int n_in,
                              void* d_out, int out_size) {
    const float* x   = (const float*)d_in[0];
    const void*  ei  = d_in[1];
    const float* W1  = (const float*)d_in[2];
    const float* as1 = (const float*)d_in[3];
    const float* ad1 = (const float*)d_in[4];
    const float* b1  = (const float*)d_in[5];
    const float* W2  = (const float*)d_in[6];
    const float* as2 = (const float*)d_in[7];
    const float* ad2 = (const float*)d_in[8];
    const float* b2  = (const float*)d_in[9];
    const float* Wp  = (const float*)d_in[10];
    const float* bp  = (const float*)d_in[11];
    float* out = (float*)d_out;

    // 8 lanes per edge, 4 edges per warp -> ET*8 threads
    const int aggBlocks = (int)(((long long)ET * 8 + 255) / 256);

    k_detect<<<1, 256>>>((const int*)ei);
    k_conv<<<(ET + 255) / 256, 256>>>(ei);
    k_zero<<<(NN * J1 + 255) / 256, 256>>>();
    k_gemm1<<<625, J1>>>(x, W1, as1, ad1);
    k_att1<<<(ET + 255) / 256, 256>>>();
    k_recip1<<<(NN * HEADS + 255) / 256, 256>>>();
    k_agg1<<<aggBlocks, 256>>>();
    k_gemm2<<<1250, 256>>>(W2, b1, as2, ad2);
    k_att2<<<(ET + 255) / 256, 256>>>();
    k_recip2<<<(NN + 255) / 256, 256>>>();
    k_agg2<<<aggBlocks, 256>>>();
    k_final<<<(NN * 32 + 255) / 256, 256>>>(b2, Wp, bp, out);
}

// round 6
// speedup vs baseline: 1.7841x; 1.0210x over previous
#include <cuda_runtime.h>

#define NN     50000
#define ER     1600000
#define ET     1650000      // edges + self loops
#define INCH   128
#define J1     96           // HEADS*HID
#define HEADS  3
#define HID    32
#define OC     32
#define NEG    0.2f

// ---------------- scratch (device globals; no allocation allowed) ----------------
__device__ int   g_fmt;                       // 0 = int64 edge buffer, 1 = int32
__device__ __align__(16) int   g_src[ET];
__device__ __align__(16) int   g_dst[ET];
__device__ __align__(16) float g_h1 [NN * J1];
__device__ __align__(16) float g_as1[NN * HEADS];
__device__ __align__(16) float g_ad1[NN * HEADS];
__device__ __align__(16) float g_s1 [NN * HEADS];
__device__ __align__(16) float g_p1 [ET * HEADS];
__device__ __align__(16) float g_o1 [NN * J1];
__device__ __align__(16) float g_h2 [NN * OC];
__device__ __align__(16) float g_as2[NN];
__device__ __align__(16) float g_ad2[NN];
__device__ __align__(16) float g_s2 [NN];
__device__ __align__(16) float g_p2 [ET];
__device__ __align__(16) float g_o2 [NN * OC];

// ---------------- helpers ----------------
__device__ __forceinline__ float wsum(float v) {
    v += __shfl_down_sync(0xffffffffu, v, 16);
    v += __shfl_down_sync(0xffffffffu, v, 8);
    v += __shfl_down_sync(0xffffffffu, v, 4);
    v += __shfl_down_sync(0xffffffffu, v, 2);
    v += __shfl_down_sync(0xffffffffu, v, 1);
    return v;
}
__device__ __forceinline__ int clampi(int v) {
    return v < 0 ? 0 : (v >= NN ? NN - 1 : v);
}
__device__ __forceinline__ void red4(float* addr, float x, float y, float z, float w) {
#if __CUDA_ARCH__ >= 900
    asm volatile("red.global.add.v4.f32 [%0], {%1,%2,%3,%4};"
                 :: "l"(addr), "f"(x), "f"(y), "f"(z), "f"(w) : "memory");
#else
    atomicAdd(addr + 0, x); atomicAdd(addr + 1, y);
    atomicAdd(addr + 2, z); atomicAdd(addr + 3, w);
#endif
}

// ---------------- kernels ----------------
// Detect int64 vs int32 edge buffer: int64 values < 50000 => odd int32 slots all 0.
__global__ void k_detect(const int* __restrict__ ei32) {
    __shared__ int nz;
    if (threadIdx.x == 0) nz = 0;
    __syncthreads();
    for (int i = threadIdx.x; i < 2048; i += blockDim.x)
        if (ei32[2 * i * 391 + 1] != 0) atomicOr(&nz, 1);
    __syncthreads();
    if (threadIdx.x == 0) g_fmt = nz ? 1 : 0;
}

__global__ void k_conv(const void* __restrict__ eiv) {
    int e = blockIdx.x * blockDim.x + threadIdx.x;
    if (e >= ET) return;
    if (e < ER) {
        int s, d;
        if (g_fmt == 0) {
            const long long* ei = (const long long*)eiv;
            s = (int)ei[e]; d = (int)ei[ER + e];
        } else {
            const int* ei = (const int*)eiv;
            s = ei[e]; d = ei[ER + e];
        }
        g_src[e] = clampi(s);
        g_dst[e] = clampi(d);
    } else {
        int i = e - ER;
        g_src[e] = i;
        g_dst[e] = i;
    }
}

// zero o1, o2, s1, s2 in one pass (indexed over the largest, NN*J1)
__global__ void k_zero() {
    int i = blockIdx.x * blockDim.x + threadIdx.x;
    if (i < NN * J1) g_o1[i] = 0.f;
    if (i < NN * OC) g_o2[i] = 0.f;
    if (i < NN * HEADS) g_s1[i] = 0.f;
    if (i < NN) g_s2[i] = 0.f;
}

// h1 = x @ W1 ; a_s1/a_d1 per node per head. One 16-row tile per block,
// grid = NN/16 = 3125 (R5 fix: 625 persistent blocks -> 19% occupancy).
__global__ void k_gemm1(const float* __restrict__ x, const float* __restrict__ W,
                        const float* __restrict__ aS, const float* __restrict__ aD) {
    __shared__ float Xsh[16 * INCH];   // 8 KB
    const int R = 16;
    int j = threadIdx.x;
    int hh = j >> 5, lane = j & 31;
    float aws = aS[hh * HID + lane];
    float awd = aD[hh * HID + lane];

    int base = blockIdx.x * R;
    for (int i = j; i < R * INCH; i += J1) Xsh[i] = x[base * INCH + i];
    __syncthreads();
    #pragma unroll
    for (int r = 0; r < R; r += 4) {
        float a0 = 0.f, a1 = 0.f, a2 = 0.f, a3 = 0.f;
        #pragma unroll 16
        for (int k = 0; k < INCH; k++) {
            float w = __ldg(&W[k * J1 + j]);
            a0 += Xsh[(r + 0) * INCH + k] * w;
            a1 += Xsh[(r + 1) * INCH + k] * w;
            a2 += Xsh[(r + 2) * INCH + k] * w;
            a3 += Xsh[(r + 3) * INCH + k] * w;
        }
        g_h1[(base + r + 0) * J1 + j] = a0;
        g_h1[(base + r + 1) * J1 + j] = a1;
        g_h1[(base + r + 2) * J1 + j] = a2;
        g_h1[(base + r + 3) * J1 + j] = a3;
        float v;
        v = wsum(a0 * aws); if (lane == 0) g_as1[(base + r + 0) * HEADS + hh] = v;
        v = wsum(a0 * awd); if (lane == 0) g_ad1[(base + r + 0) * HEADS + hh] = v;
        v = wsum(a1 * aws); if (lane == 0) g_as1[(base + r + 1) * HEADS + hh] = v;
        v = wsum(a1 * awd); if (lane == 0) g_ad1[(base + r + 1) * HEADS + hh] = v;
        v = wsum(a2 * aws); if (lane == 0) g_as1[(base + r + 2) * HEADS + hh] = v;
        v = wsum(a2 * awd); if (lane == 0) g_ad1[(base + r + 2) * HEADS + hh] = v;
        v = wsum(a3 * aws); if (lane == 0) g_as1[(base + r + 3) * HEADS + hh] = v;
        v = wsum(a3 * awd); if (lane == 0) g_ad1[(base + r + 3) * HEADS + hh] = v;
    }
}

// Edge attention layer 1: p = exp(leaky_relu(as[s]+ad[d])); s1[d] += p.
__global__ void k_att1() {
    int e = blockIdx.x * blockDim.x + threadIdx.x;
    if (e >= ET) return;
    int s = g_src[e], d = g_dst[e];
    #pragma unroll
    for (int h = 0; h < HEADS; h++) {
        float v = g_as1[s * HEADS + h] + g_ad1[d * HEADS + h];
        v = v > 0.f ? v : NEG * v;
        float p = __expf(v);
        g_p1[e * HEADS + h] = p;
        atomicAdd(&g_s1[d * HEADS + h], p);
    }
}

__global__ void k_recip1() {
    int i = blockIdx.x * blockDim.x + threadIdx.x;
    if (i < NN * HEADS) g_s1[i] = 1.f / (g_s1[i] + 1e-16f);
}
__global__ void k_recip2() {
    int i = blockIdx.x * blockDim.x + threadIdx.x;
    if (i < NN) g_s2[i] = 1.f / (g_s2[i] + 1e-16f);
}

// Aggregation layer 1: 4 edges per warp, 8 lanes per edge, 3 float4 per lane.
__global__ void k_agg1() {
    long long t = (long long)blockIdx.x * blockDim.x + threadIdx.x;
    int lane = threadIdx.x & 31;
    int sub  = lane >> 3;          // edge within warp
    int l8   = lane & 7;           // lane within edge group
    long long w = t >> 5;
    int e = (int)(w * 4 + sub);
    if (e >= ET) return;
    int s = g_src[e], d = g_dst[e];
    const float4* hsrc = (const float4*)&g_h1[s * J1];
    float*        odst = &g_o1[d * J1];
    #pragma unroll
    for (int h = 0; h < HEADS; h++) {
        float alpha = g_p1[e * HEADS + h] * g_s1[d * HEADS + h];
        float4 v = hsrc[h * 8 + l8];
        red4(odst + h * 32 + l8 * 4, v.x * alpha, v.y * alpha, v.z * alpha, v.w * alpha);
    }
}

// h2 = elu(o1 + b1) @ W2 ; a_s2/a_d2. One 8-row tile per block, grid = NN/8 = 6250.
__global__ void k_gemm2(const float* __restrict__ W, const float* __restrict__ b1,
                        const float* __restrict__ aS, const float* __restrict__ aD) {
    __shared__ float Wsh[J1 * OC];   // 12 KB
    __shared__ float Xsh[8 * J1];
    int tid = threadIdx.x;
    for (int i = tid; i < J1 * OC; i += 256) Wsh[i] = W[i];
    int r = tid >> 5, lane = tid & 31;
    float aws = aS[lane], awd = aD[lane];
    int base = blockIdx.x * 8;
    for (int i = tid; i < 8 * J1; i += 256) {
        int rr = i / J1, k = i - rr * J1;
        float v = g_o1[(base + rr) * J1 + k] + b1[k];
        v = v > 0.f ? v : (__expf(v) - 1.f);
        Xsh[i] = v;
    }
    __syncthreads();
    int row = base + r;
    float acc = 0.f;
    #pragma unroll 16
    for (int k = 0; k < J1; k++) acc += Xsh[r * J1 + k] * Wsh[k * OC + lane];
    g_h2[row * OC + lane] = acc;
    float vs = wsum(acc * aws);
    float vd = wsum(acc * awd);
    if (lane == 0) { g_as2[row] = vs; g_ad2[row] = vd; }
}

// Edge attention layer 2
__global__ void k_att2() {
    int e = blockIdx.x * blockDim.x + threadIdx.x;
    if (e >= ET) return;
    int s = g_src[e], d = g_dst[e];
    float v = g_as2[s] + g_ad2[d];
    v = v > 0.f ? v : NEG * v;
    float p = __expf(v);
    g_p2[e] = p;
    atomicAdd(&g_s2[d], p);
}

// Aggregation layer 2: 4 edges per warp, 8 lanes per edge, 1 float4 per lane.
__global__ void k_agg2() {
    long long t = (long long)blockIdx.x * blockDim.x + threadIdx.x;
    int lane = threadIdx.x & 31;
    int sub  = lane >> 3;
    int l8   = lane & 7;
    long long w = t >> 5;
    int e = (int)(w * 4 + sub);
    if (e >= ET) return;
    int s = g_src[e], d = g_dst[e];
    float alpha = g_p2[e] * g_s2[d];
    float4 v = ((const float4*)&g_h2[s * OC])[l8];
    red4(&g_o2[d * OC] + l8 * 4, v.x * alpha, v.y * alpha, v.z * alpha, v.w * alpha);
}

// prob = sigmoid((o2 + b2) @ Wp + bp), warp per node
__global__ void k_final(const float* __restrict__ b2, const float* __restrict__ Wp,
                        const float* __restrict__ bp, float* __restrict__ out) {
    int w = (int)((blockIdx.x * blockDim.x + threadIdx.x) >> 5);
    int lane = threadIdx.x & 31;
    if (w >= NN) return;
    float v = (g_o2[w * OC + lane] + b2[lane]) * Wp[lane];
    v = wsum(v);
    if (lane == 0) out[w] = 1.f / (1.f + __expf(-v - bp[0]));
}

// ---------------- launch ----------------
extern "C" void kernel_launch(void* const* d_in, const int* in_sizes, int n_in,
                              void* d_out, int out_size) {
    const float* x   = (const float*)d_in[0];
    const void*  ei  = d_in[1];
    const float* W1  = (const float*)d_in[2];
    const float* as1 = (const float*)d_in[3];
    const float* ad1 = (const float*)d_in[4];
    const float* b1  = (const float*)d_in[5];
    const float* W2  = (const float*)d_in[6];
    const float* as2 = (const float*)d_in[7];
    const float* ad2 = (const float*)d_in[8];
    const float* b2  = (const float*)d_in[9];
    const float* Wp  = (const float*)d_in[10];
    const float* bp  = (const float*)d_in[11];
    float* out = (float*)d_out;

    const int aggBlocks = (int)(((long long)ET * 8 + 255) / 256);

    k_detect<<<1, 256>>>((const int*)ei);
    k_conv<<<(ET + 255) / 256, 256>>>(ei);
    k_zero<<<(NN * J1 + 255) / 256, 256>>>();
    k_gemm1<<<NN / 16, J1>>>(x, W1, as1, ad1);        // 3125 blocks
    k_att1<<<(ET + 255) / 256, 256>>>();
    k_recip1<<<(NN * HEADS + 255) / 256, 256>>>();
    k_agg1<<<aggBlocks, 256>>>();
    k_gemm2<<<NN / 8, 256>>>(W2, b1, as2, ad2);       // 6250 blocks
    k_att2<<<(ET + 255) / 256, 256>>>();
    k_recip2<<<(NN + 255) / 256, 256>>>();
    k_agg2<<<aggBlocks, 256>>>();
    k_final<<<(NN * 32 + 255) / 256, 256>>>(b2, Wp, bp, out);
}

// round 7
// speedup vs baseline: 1.9843x; 1.1122x over previous
#include <cuda_runtime.h>

#define NN     50000
#define ER     1600000
#define ET     1650000      // edges + self loops
#define INCH   128
#define J1     96           // HEADS*HID
#define HEADS  3
#define HID    32
#define OC     32
#define NEG    0.2f

// ---------------- scratch (device globals; no allocation allowed) ----------------
__device__ int   g_fmt;                       // 0 = int64 edge buffer, 1 = int32
__device__ __align__(16) int   g_src[ET];
__device__ __align__(16) int   g_dst[ET];
__device__ __align__(16) float g_h1 [NN * J1];
__device__ __align__(16) float g_as1[NN * HEADS];
__device__ __align__(16) float g_ad1[NN * HEADS];
__device__ __align__(16) float g_s1 [NN * HEADS];
__device__ __align__(16) float g_p1 [ET * HEADS];
__device__ __align__(16) float g_o1 [NN * J1];
__device__ __align__(16) float g_h2 [NN * OC];
__device__ __align__(16) float g_as2[NN];
__device__ __align__(16) float g_ad2[NN];
__device__ __align__(16) float g_s2 [NN];
__device__ __align__(16) float g_p2 [ET];
__device__ __align__(16) float g_o2 [NN * OC];

// ---------------- helpers ----------------
__device__ __forceinline__ float wsum(float v) {
    v += __shfl_down_sync(0xffffffffu, v, 16);
    v += __shfl_down_sync(0xffffffffu, v, 8);
    v += __shfl_down_sync(0xffffffffu, v, 4);
    v += __shfl_down_sync(0xffffffffu, v, 2);
    v += __shfl_down_sync(0xffffffffu, v, 1);
    return v;
}
__device__ __forceinline__ int clampi(int v) {
    return v < 0 ? 0 : (v >= NN ? NN - 1 : v);
}
__device__ __forceinline__ void red4(float* addr, float x, float y, float z, float w) {
#if __CUDA_ARCH__ >= 900
    asm volatile("red.global.add.v4.f32 [%0], {%1,%2,%3,%4};"
                 :: "l"(addr), "f"(x), "f"(y), "f"(z), "f"(w) : "memory");
#else
    atomicAdd(addr + 0, x); atomicAdd(addr + 1, y);
    atomicAdd(addr + 2, z); atomicAdd(addr + 3, w);
#endif
}

// ---------------- kernels ----------------
// Detect int64 vs int32 edge buffer: int64 values < 50000 => odd int32 slots all 0.
__global__ void k_detect(const int* __restrict__ ei32) {
    __shared__ int nz;
    if (threadIdx.x == 0) nz = 0;
    __syncthreads();
    for (int i = threadIdx.x; i < 2048; i += blockDim.x)
        if (ei32[2 * i * 391 + 1] != 0) atomicOr(&nz, 1);
    __syncthreads();
    if (threadIdx.x == 0) g_fmt = nz ? 1 : 0;
}

__global__ void k_conv(const void* __restrict__ eiv) {
    int e = blockIdx.x * blockDim.x + threadIdx.x;
    if (e >= ET) return;
    if (e < ER) {
        int s, d;
        if (g_fmt == 0) {
            const long long* ei = (const long long*)eiv;
            s = (int)ei[e]; d = (int)ei[ER + e];
        } else {
            const int* ei = (const int*)eiv;
            s = ei[e]; d = ei[ER + e];
        }
        g_src[e] = clampi(s);
        g_dst[e] = clampi(d);
    } else {
        int i = e - ER;
        g_src[e] = i;
        g_dst[e] = i;
    }
}

// zero o1, o2, s1, s2 in one pass (indexed over the largest, NN*J1)
__global__ void k_zero() {
    int i = blockIdx.x * blockDim.x + threadIdx.x;
    if (i < NN * J1) g_o1[i] = 0.f;
    if (i < NN * OC) g_o2[i] = 0.f;
    if (i < NN * HEADS) g_s1[i] = 0.f;
    if (i < NN) g_s2[i] = 0.f;
}

// h1 = x @ W1 + fused attention dots. 2D register-blocked:
// 256 threads, tile M=64 x N=96, K chunks of 64. Thread (tx,ty) computes
// 8 rows (ty+8i) x 3 cols (tx, tx+32, tx+64 -> one col per head).
// 0.46 LDS per FMA (was 1.25 mem-ops/FMA -> L1-bound at 80%).
__global__ void k_gemm1(const float* __restrict__ x, const float* __restrict__ W,
                        const float* __restrict__ aS, const float* __restrict__ aD) {
    __shared__ float Xsh[64][65];    // padded: conflict-free column reads
    __shared__ float Wsh[64][96];
    int tid = threadIdx.x;
    int tx = tid & 31, ty = tid >> 5;        // ty 0..7
    int base = blockIdx.x * 64;
    float acc[8][3] = {};
    float aSv[3], aDv[3];
    #pragma unroll
    for (int c = 0; c < 3; c++) { aSv[c] = aS[c * 32 + tx]; aDv[c] = aD[c * 32 + tx]; }

    #pragma unroll
    for (int kc = 0; kc < 2; kc++) {
        __syncthreads();
        // X chunk: 64 rows x 64 k, 16 floats/thread, coalesced 256B segments
        #pragma unroll
        for (int i = 0; i < 16; i++) {
            int idx = tid + 256 * i;
            int row = idx >> 6, kk = idx & 63;
            int gr = base + row;
            Xsh[row][kk] = (gr < NN) ? x[gr * INCH + kc * 64 + kk] : 0.f;
        }
        // W chunk: 64 k x 96 cols, 24 floats/thread
        #pragma unroll
        for (int i = 0; i < 24; i++) {
            int idx = tid + 256 * i;
            int row = idx / 96, col = idx - row * 96;
            Wsh[row][col] = W[(kc * 64 + row) * J1 + col];
        }
        __syncthreads();
        #pragma unroll 8
        for (int k = 0; k < 64; k++) {
            float w0 = Wsh[k][tx], w1 = Wsh[k][tx + 32], w2 = Wsh[k][tx + 64];
            #pragma unroll
            for (int i = 0; i < 8; i++) {
                float xv = Xsh[ty + 8 * i][k];
                acc[i][0] += xv * w0;
                acc[i][1] += xv * w1;
                acc[i][2] += xv * w2;
            }
        }
    }
    // epilogue: store h1 + per-head attention dots (warp = fixed ty, lanes = head cols)
    #pragma unroll
    for (int i = 0; i < 8; i++) {
        int row = base + ty + 8 * i;
        if (row >= NN) continue;
        g_h1[row * J1 + tx]      = acc[i][0];
        g_h1[row * J1 + tx + 32] = acc[i][1];
        g_h1[row * J1 + tx + 64] = acc[i][2];
        #pragma unroll
        for (int h = 0; h < HEADS; h++) {
            float vs = wsum(acc[i][h] * aSv[h]);
            float vd = wsum(acc[i][h] * aDv[h]);
            if (tx == 0) { g_as1[row * HEADS + h] = vs; g_ad1[row * HEADS + h] = vd; }
        }
    }
}

// Edge attention layer 1: p = exp(leaky_relu(as[s]+ad[d])); s1[d] += p.
__global__ void k_att1() {
    int e = blockIdx.x * blockDim.x + threadIdx.x;
    if (e >= ET) return;
    int s = g_src[e], d = g_dst[e];
    #pragma unroll
    for (int h = 0; h < HEADS; h++) {
        float v = g_as1[s * HEADS + h] + g_ad1[d * HEADS + h];
        v = v > 0.f ? v : NEG * v;
        float p = __expf(v);
        g_p1[e * HEADS + h] = p;
        atomicAdd(&g_s1[d * HEADS + h], p);
    }
}

__global__ void k_recip1() {
    int i = blockIdx.x * blockDim.x + threadIdx.x;
    if (i < NN * HEADS) g_s1[i] = 1.f / (g_s1[i] + 1e-16f);
}
__global__ void k_recip2() {
    int i = blockIdx.x * blockDim.x + threadIdx.x;
    if (i < NN) g_s2[i] = 1.f / (g_s2[i] + 1e-16f);
}

// Aggregation layer 1: 4 edges per warp, 8 lanes per edge, 3 float4 per lane.
__global__ void k_agg1() {
    long long t = (long long)blockIdx.x * blockDim.x + threadIdx.x;
    int lane = threadIdx.x & 31;
    int sub  = lane >> 3;          // edge within warp
    int l8   = lane & 7;           // lane within edge group
    long long w = t >> 5;
    int e = (int)(w * 4 + sub);
    if (e >= ET) return;
    int s = g_src[e], d = g_dst[e];
    const float4* hsrc = (const float4*)&g_h1[s * J1];
    float*        odst = &g_o1[d * J1];
    #pragma unroll
    for (int h = 0; h < HEADS; h++) {
        float alpha = g_p1[e * HEADS + h] * g_s1[d * HEADS + h];
        float4 v = hsrc[h * 8 + l8];
        red4(odst + h * 32 + l8 * 4, v.x * alpha, v.y * alpha, v.z * alpha, v.w * alpha);
    }
}

// h2 = elu(o1 + b1) @ W2 ; a_s2/a_d2. One 8-row tile per block, grid = NN/8 = 6250.
__global__ void k_gemm2(const float* __restrict__ W, const float* __restrict__ b1,
                        const float* __restrict__ aS, const float* __restrict__ aD) {
    __shared__ float Wsh[J1 * OC];   // 12 KB
    __shared__ float Xsh[8 * J1];
    int tid = threadIdx.x;
    for (int i = tid; i < J1 * OC; i += 256) Wsh[i] = W[i];
    int r = tid >> 5, lane = tid & 31;
    float aws = aS[lane], awd = aD[lane];
    int base = blockIdx.x * 8;
    for (int i = tid; i < 8 * J1; i += 256) {
        int rr = i / J1, k = i - rr * J1;
        float v = g_o1[(base + rr) * J1 + k] + b1[k];
        v = v > 0.f ? v : (__expf(v) - 1.f);
        Xsh[i] = v;
    }
    __syncthreads();
    int row = base + r;
    float acc = 0.f;
    #pragma unroll 16
    for (int k = 0; k < J1; k++) acc += Xsh[r * J1 + k] * Wsh[k * OC + lane];
    g_h2[row * OC + lane] = acc;
    float vs = wsum(acc * aws);
    float vd = wsum(acc * awd);
    if (lane == 0) { g_as2[row] = vs; g_ad2[row] = vd; }
}

// Edge attention layer 2
__global__ void k_att2() {
    int e = blockIdx.x * blockDim.x + threadIdx.x;
    if (e >= ET) return;
    int s = g_src[e], d = g_dst[e];
    float v = g_as2[s] + g_ad2[d];
    v = v > 0.f ? v : NEG * v;
    float p = __expf(v);
    g_p2[e] = p;
    atomicAdd(&g_s2[d], p);
}

// Aggregation layer 2: 4 edges per warp, 8 lanes per edge, 1 float4 per lane.
__global__ void k_agg2() {
    long long t = (long long)blockIdx.x * blockDim.x + threadIdx.x;
    int lane = threadIdx.x & 31;
    int sub  = lane >> 3;
    int l8   = lane & 7;
    long long w = t >> 5;
    int e = (int)(w * 4 + sub);
    if (e >= ET) return;
    int s = g_src[e], d = g_dst[e];
    float alpha = g_p2[e] * g_s2[d];
    float4 v = ((const float4*)&g_h2[s * OC])[l8];
    red4(&g_o2[d * OC] + l8 * 4, v.x * alpha, v.y * alpha, v.z * alpha, v.w * alpha);
}

// prob = sigmoid((o2 + b2) @ Wp + bp), warp per node
__global__ void k_final(const float* __restrict__ b2, const float* __restrict__ Wp,
                        const float* __restrict__ bp, float* __restrict__ out) {
    int w = (int)((blockIdx.x * blockDim.x + threadIdx.x) >> 5);
    int lane = threadIdx.x & 31;
    if (w >= NN) return;
    float v = (g_o2[w * OC + lane] + b2[lane]) * Wp[lane];
    v = wsum(v);
    if (lane == 0) out[w] = 1.f / (1.f + __expf(-v - bp[0]));
}

// ---------------- launch ----------------
extern "C" void kernel_launch(void* const* d_in, const int* in_sizes, int n_in,
                              void* d_out, int out_size) {
    const float* x   = (const float*)d_in[0];
    const void*  ei  = d_in[1];
    const float* W1  = (const float*)d_in[2];
    const float* as1 = (const float*)d_in[3];
    const float* ad1 = (const float*)d_in[4];
    const float* b1  = (const float*)d_in[5];
    const float* W2  = (const float*)d_in[6];
    const float* as2 = (const float*)d_in[7];
    const float* ad2 = (const float*)d_in[8];
    const float* b2  = (const float*)d_in[9];
    const float* Wp  = (const float*)d_in[10];
    const float* bp  = (const float*)d_in[11];
    float* out = (float*)d_out;

    const int aggBlocks = (int)(((long long)ET * 8 + 255) / 256);

    k_detect<<<1, 256>>>((const int*)ei);
    k_conv<<<(ET + 255) / 256, 256>>>(ei);
    k_zero<<<(NN * J1 + 255) / 256, 256>>>();
    k_gemm1<<<(NN + 63) / 64, 256>>>(x, W1, as1, ad1);   // 782 blocks
    k_att1<<<(ET + 255) / 256, 256>>>();
    k_recip1<<<(NN * HEADS + 255) / 256, 256>>>();
    k_agg1<<<aggBlocks, 256>>>();
    k_gemm2<<<NN / 8, 256>>>(W2, b1, as2, ad2);          // 6250 blocks
    k_att2<<<(ET + 255) / 256, 256>>>();
    k_recip2<<<(NN + 255) / 256, 256>>>();
    k_agg2<<<aggBlocks, 256>>>();
    k_final<<<(NN * 32 + 255) / 256, 256>>>(b2, Wp, bp, out);
}

// round 8
// speedup vs baseline: 2.2415x; 1.1296x over previous
#include <cuda_runtime.h>

#define NN     50000
#define ER     1600000
#define ET     1650000      // edges + self loops
#define INCH   128
#define J1     96           // HEADS*HID
#define HEADS  3
#define HID    32
#define OC     32
#define NEG    0.2f

// ---------------- scratch (device globals; no allocation allowed) ----------------
__device__ int   g_fmt;                       // 0 = int64 edge buffer, 1 = int32
__device__ __align__(16) int   g_src [ET];
__device__ __align__(16) int   g_dst [ET];
__device__ __align__(16) int   g_deg [NN];
__device__ __align__(16) int   g_off [NN + 1];
__device__ __align__(16) int   g_cur [NN];
__device__ __align__(16) int   g_csrc[ET];     // CSR: src ids sorted by dst
__device__ __align__(16) float g_h1  [NN * J1];
__device__ __align__(16) float g_as1 [NN * 4]; // padded float4 per node (3 heads)
__device__ __align__(16) float g_ad1 [NN * 4];
__device__ __align__(16) float g_o1  [NN * J1];
__device__ __align__(16) float g_h2  [NN * OC];
__device__ __align__(16) float g_as2 [NN];
__device__ __align__(16) float g_ad2 [NN];

// ---------------- helpers ----------------
__device__ __forceinline__ float bsum(float v) {          // all lanes get the sum
    v += __shfl_xor_sync(0xffffffffu, v, 16);
    v += __shfl_xor_sync(0xffffffffu, v, 8);
    v += __shfl_xor_sync(0xffffffffu, v, 4);
    v += __shfl_xor_sync(0xffffffffu, v, 2);
    v += __shfl_xor_sync(0xffffffffu, v, 1);
    return v;
}
__device__ __forceinline__ int clampi(int v) {
    return v < 0 ? 0 : (v >= NN ? NN - 1 : v);
}
__device__ __forceinline__ float lrelu_exp(float v) {
    v = v > 0.f ? v : NEG * v;
    return __expf(v);
}

// ---------------- kernels ----------------
// Detect int64 vs int32 edge buffer: int64 values < 50000 => odd int32 slots all 0.
__global__ void k_detect(const int* __restrict__ ei32) {
    __shared__ int nz;
    if (threadIdx.x == 0) nz = 0;
    __syncthreads();
    for (int i = threadIdx.x; i < 2048; i += blockDim.x)
        if (ei32[2 * i * 391 + 1] != 0) atomicOr(&nz, 1);
    __syncthreads();
    if (threadIdx.x == 0) g_fmt = nz ? 1 : 0;
}

__global__ void k_zerodeg() {
    int i = blockIdx.x * blockDim.x + threadIdx.x;
    if (i < NN) g_deg[i] = 0;
}

// convert edge list + histogram of dst degrees
__global__ void k_conv(const void* __restrict__ eiv) {
    int e = blockIdx.x * blockDim.x + threadIdx.x;
    if (e >= ET) return;
    int s, d;
    if (e < ER) {
        if (g_fmt == 0) {
            const long long* ei = (const long long*)eiv;
            s = (int)ei[e]; d = (int)ei[ER + e];
        } else {
            const int* ei = (const int*)eiv;
            s = ei[e]; d = ei[ER + e];
        }
        s = clampi(s); d = clampi(d);
    } else {
        s = e - ER; d = s;
    }
    g_src[e] = s;
    g_dst[e] = d;
    atomicAdd(&g_deg[d], 1);
}

// exclusive prefix sum of g_deg -> g_off, g_cur. Single block, 1024 threads.
__global__ void k_scan() {
    __shared__ int warpsums[32];
    __shared__ int carry;
    int tid = threadIdx.x, lane = tid & 31, wid = tid >> 5;
    if (tid == 0) carry = 0;
    __syncthreads();
    for (int base = 0; base < NN; base += 1024) {
        int i = base + tid;
        int v = (i < NN) ? g_deg[i] : 0;
        int x = v;
        #pragma unroll
        for (int o = 1; o < 32; o <<= 1) {
            int y = __shfl_up_sync(0xffffffffu, x, o);
            if (lane >= o) x += y;
        }
        if (lane == 31) warpsums[wid] = x;
        __syncthreads();
        if (wid == 0) {
            int sv = warpsums[lane];
            #pragma unroll
            for (int o = 1; o < 32; o <<= 1) {
                int y = __shfl_up_sync(0xffffffffu, sv, o);
                if (lane >= o) sv += y;
            }
            warpsums[lane] = sv;
        }
        __syncthreads();
        int incl = x + (wid > 0 ? warpsums[wid - 1] : 0) + carry;
        if (i < NN) { g_off[i] = incl - v; g_cur[i] = incl - v; }
        __syncthreads();
        if (tid == 1023) carry = incl;
        __syncthreads();
    }
    if (threadIdx.x == 0) g_off[NN] = carry;
}

__global__ void k_scatter() {
    int e = blockIdx.x * blockDim.x + threadIdx.x;
    if (e >= ET) return;
    int d = g_dst[e];
    int pos = atomicAdd(&g_cur[d], 1);
    g_csrc[pos] = g_src[e];
}

// h1 = x @ W1 + fused attention dots. 256 threads, tile M=64 x N=96, K chunks 64.
// Thread (tx,ty): 8 rows x 3 cols (tx, tx+32, tx+64 -> one col per head).
// Xsh rows float4-aligned (pad 68) so the k-loop reads 4 k at a time.
__global__ void k_gemm1(const float* __restrict__ x, const float* __restrict__ W,
                        const float* __restrict__ aS, const float* __restrict__ aD) {
    __shared__ float Xsh[64][68];
    __shared__ float Wsh[64][96];
    int tid = threadIdx.x;
    int tx = tid & 31, ty = tid >> 5;
    int base = blockIdx.x * 64;
    float acc[8][3] = {};
    float aSv[3], aDv[3];
    #pragma unroll
    for (int c = 0; c < 3; c++) { aSv[c] = aS[c * 32 + tx]; aDv[c] = aD[c * 32 + tx]; }

    #pragma unroll
    for (int kc = 0; kc < 2; kc++) {
        __syncthreads();
        #pragma unroll
        for (int i = 0; i < 16; i++) {
            int idx = tid + 256 * i;
            int row = idx >> 6, kk = idx & 63;
            int gr = base + row;
            Xsh[row][kk] = (gr < NN) ? x[gr * INCH + kc * 64 + kk] : 0.f;
        }
        #pragma unroll
        for (int i = 0; i < 24; i++) {
            int idx = tid + 256 * i;
            int row = idx / 96, col = idx - row * 96;
            Wsh[row][col] = W[(kc * 64 + row) * J1 + col];
        }
        __syncthreads();
        for (int k = 0; k < 64; k += 4) {
            float4 xv[8];
            #pragma unroll
            for (int i = 0; i < 8; i++) xv[i] = *(const float4*)&Xsh[ty + 8 * i][k];
            #pragma unroll
            for (int kk = 0; kk < 4; kk++) {
                float w0 = Wsh[k + kk][tx];
                float w1 = Wsh[k + kk][tx + 32];
                float w2 = Wsh[k + kk][tx + 64];
                #pragma unroll
                for (int i = 0; i < 8; i++) {
                    float xvv = ((const float*)&xv[i])[kk];
                    acc[i][0] += xvv * w0;
                    acc[i][1] += xvv * w1;
                    acc[i][2] += xvv * w2;
                }
            }
        }
    }
    #pragma unroll
    for (int i = 0; i < 8; i++) {
        int row = base + ty + 8 * i;
        if (row >= NN) continue;
        g_h1[row * J1 + tx]      = acc[i][0];
        g_h1[row * J1 + tx + 32] = acc[i][1];
        g_h1[row * J1 + tx + 64] = acc[i][2];
        #pragma unroll
        for (int h = 0; h < HEADS; h++) {
            float vs = bsum(acc[i][h] * aSv[h]);
            float vd = bsum(acc[i][h] * aDv[h]);
            if (tx == 0) { g_as1[row * 4 + h] = vs; g_ad1[row * 4 + h] = vd; }
        }
    }
}

// Fused layer-1 softmax + aggregation. Warp per dst node:
// per edge compute p in-register (no max pass; logits are O(0.2)),
// accumulate sum(p) and sum(p*h1[src]) in registers, normalize, plain store.
__global__ void k_fagg1() {
    int d = (int)((blockIdx.x * blockDim.x + threadIdx.x) >> 5);
    int lane = threadIdx.x & 31;
    if (d >= NN) return;
    int beg = g_off[d], end = g_off[d + 1];
    float4 adv = *(const float4*)&g_ad1[d * 4];
    float acc0 = 0.f, acc1 = 0.f, acc2 = 0.f;
    float sp0 = 0.f, sp1 = 0.f, sp2 = 0.f;
    for (int j = beg; j < end; j += 32) {
        int n = end - j; if (n > 32) n = 32;
        int s = 0; float p0 = 0.f, p1 = 0.f, p2 = 0.f;
        if (lane < n) {
            s = g_csrc[j + lane];
            float4 a = *(const float4*)&g_as1[s * 4];
            p0 = lrelu_exp(a.x + adv.x);
            p1 = lrelu_exp(a.y + adv.y);
            p2 = lrelu_exp(a.z + adv.z);
            sp0 += p0; sp1 += p1; sp2 += p2;
        }
        for (int i = 0; i < n; i++) {
            int   si = __shfl_sync(0xffffffffu, s,  i);
            float q0 = __shfl_sync(0xffffffffu, p0, i);
            float q1 = __shfl_sync(0xffffffffu, p1, i);
            float q2 = __shfl_sync(0xffffffffu, p2, i);
            const float* hp = &g_h1[si * J1];
            acc0 += q0 * hp[lane];
            acc1 += q1 * hp[lane + 32];
            acc2 += q2 * hp[lane + 64];
        }
    }
    sp0 = bsum(sp0); sp1 = bsum(sp1); sp2 = bsum(sp2);
    float r0 = 1.f / (sp0 + 1e-16f);
    float r1 = 1.f / (sp1 + 1e-16f);
    float r2 = 1.f / (sp2 + 1e-16f);
    g_o1[d * J1 + lane]      = acc0 * r0;
    g_o1[d * J1 + lane + 32] = acc1 * r1;
    g_o1[d * J1 + lane + 64] = acc2 * r2;
}

// h2 = elu(o1 + b1) @ W2 ; a_s2/a_d2. One 8-row tile per block, grid = NN/8.
__global__ void k_gemm2(const float* __restrict__ W, const float* __restrict__ b1,
                        const float* __restrict__ aS, const float* __restrict__ aD) {
    __shared__ float Wsh[J1 * OC];
    __shared__ float Xsh[8 * J1];
    int tid = threadIdx.x;
    for (int i = tid; i < J1 * OC; i += 256) Wsh[i] = W[i];
    int r = tid >> 5, lane = tid & 31;
    float aws = aS[lane], awd = aD[lane];
    int base = blockIdx.x * 8;
    for (int i = tid; i < 8 * J1; i += 256) {
        int rr = i / J1, k = i - rr * J1;
        float v = g_o1[(base + rr) * J1 + k] + b1[k];
        v = v > 0.f ? v : (__expf(v) - 1.f);
        Xsh[i] = v;
    }
    __syncthreads();
    int row = base + r;
    float acc = 0.f;
    #pragma unroll 16
    for (int k = 0; k < J1; k++) acc += Xsh[r * J1 + k] * Wsh[k * OC + lane];
    g_h2[row * OC + lane] = acc;
    float vs = bsum(acc * aws);
    float vd = bsum(acc * awd);
    if (lane == 0) { g_as2[row] = vs; g_ad2[row] = vd; }
}

// Fused layer-2 softmax + aggregation + bias + project + sigmoid. Warp per node.
__global__ void k_fagg2(const float* __restrict__ b2, const float* __restrict__ Wp,
                        const float* __restrict__ bp, float* __restrict__ out) {
    int d = (int)((blockIdx.x * blockDim.x + threadIdx.x) >> 5);
    int lane = threadIdx.x & 31;
    if (d >= NN) return;
    int beg = g_off[d], end = g_off[d + 1];
    float adv = g_ad2[d];
    float acc = 0.f, sp = 0.f;
    for (int j = beg; j < end; j += 32) {
        int n = end - j; if (n > 32) n = 32;
        int s = 0; float p = 0.f;
        if (lane < n) {
            s = g_csrc[j + lane];
            p = lrelu_exp(g_as2[s] + adv);
            sp += p;
        }
        for (int i = 0; i < n; i++) {
            int   si = __shfl_sync(0xffffffffu, s, i);
            float q  = __shfl_sync(0xffffffffu, p, i);
            acc += q * g_h2[si * OC + lane];
        }
    }
    sp = bsum(sp);
    float o2 = acc * (1.f / (sp + 1e-16f)) + b2[lane];
    float t = bsum(o2 * Wp[lane]);
    if (lane == 0) out[d] = 1.f / (1.f + __expf(-t - bp[0]));
}

// ---------------- launch ----------------
extern "C" void kernel_launch(void* const* d_in, const int* in_sizes, int n_in,
                              void* d_out, int out_size) {
    const float* x   = (const float*)d_in[0];
    const void*  ei  = d_in[1];
    const float* W1  = (const float*)d_in[2];
    const float* as1 = (const float*)d_in[3];
    const float* ad1 = (const float*)d_in[4];
    const float* b1  = (const float*)d_in[5];
    const float* W2  = (const float*)d_in[6];
    const float* as2 = (const float*)d_in[7];
    const float* ad2 = (const float*)d_in[8];
    const float* b2  = (const float*)d_in[9];
    const float* Wp  = (const float*)d_in[10];
    const float* bp  = (const float*)d_in[11];
    float* out = (float*)d_out;

    const int nodeWarpBlocks = (NN * 32 + 255) / 256;   // warp per node

    k_detect<<<1, 256>>>((const int*)ei);
    k_zerodeg<<<(NN + 255) / 256, 256>>>();
    k_conv<<<(ET + 255) / 256, 256>>>(ei);
    k_scan<<<1, 1024>>>();
    k_scatter<<<(ET + 255) / 256, 256>>>();
    k_gemm1<<<(NN + 63) / 64, 256>>>(x, W1, as1, ad1);
    k_fagg1<<<nodeWarpBlocks, 256>>>();
    k_gemm2<<<NN / 8, 256>>>(W2, b1, as2, ad2);
    k_fagg2<<<nodeWarpBlocks, 256>>>(b2, Wp, bp, out);
}

// round 9
// speedup vs baseline: 2.4883x; 1.1101x over previous
#include <cuda_runtime.h>

#define NN     50000
#define ER     1600000
#define ET     1650000      // edges + self loops
#define INCH   128
#define J1     96           // HEADS*HID
#define HEADS  3
#define HID    32
#define OC     32
#define NEG    0.2f

#define SCAN_CHUNK 1024
#define NCHUNK ((NN + SCAN_CHUNK - 1) / SCAN_CHUNK)   // 49

// ---------------- scratch (device globals; no allocation allowed) ----------------
__device__ int   g_fmt;                       // 0 = int64 edge buffer, 1 = int32
__device__ __align__(16) int   g_src [ET];
__device__ __align__(16) int   g_dst [ET];
__device__ __align__(16) int   g_deg [NN];
__device__ __align__(16) int   g_off [NN + 1];
__device__ __align__(16) int   g_cur [NN];
__device__ __align__(16) int   g_csum[NCHUNK];   // per-chunk totals -> offsets
__device__ __align__(16) int   g_csrc[ET];       // CSR: src ids sorted by dst
__device__ __align__(16) float g_h1  [NN * J1];
__device__ __align__(16) float g_as1 [NN * 4];   // padded float4 per node (3 heads)
__device__ __align__(16) float g_ad1 [NN * 4];
__device__ __align__(16) float g_o1  [NN * J1];
__device__ __align__(16) float g_h2  [NN * OC];
__device__ __align__(16) float g_as2 [NN];
__device__ __align__(16) float g_ad2 [NN];

// ---------------- helpers ----------------
__device__ __forceinline__ float bsum(float v) {          // all lanes get the sum
    v += __shfl_xor_sync(0xffffffffu, v, 16);
    v += __shfl_xor_sync(0xffffffffu, v, 8);
    v += __shfl_xor_sync(0xffffffffu, v, 4);
    v += __shfl_xor_sync(0xffffffffu, v, 2);
    v += __shfl_xor_sync(0xffffffffu, v, 1);
    return v;
}
__device__ __forceinline__ int clampi(int v) {
    return v < 0 ? 0 : (v >= NN ? NN - 1 : v);
}
__device__ __forceinline__ float lrelu_exp(float v) {
    v = v > 0.f ? v : NEG * v;
    return __expf(v);
}

// ---------------- kernels ----------------
// Detect int64 vs int32 edge buffer: int64 values < 50000 => odd int32 slots all 0.
__global__ void k_detect(const int* __restrict__ ei32) {
    __shared__ int nz;
    if (threadIdx.x == 0) nz = 0;
    __syncthreads();
    for (int i = threadIdx.x; i < 2048; i += blockDim.x)
        if (ei32[2 * i * 391 + 1] != 0) atomicOr(&nz, 1);
    __syncthreads();
    if (threadIdx.x == 0) g_fmt = nz ? 1 : 0;
}

__global__ void k_zerodeg() {
    int i = blockIdx.x * blockDim.x + threadIdx.x;
    if (i < NN) g_deg[i] = 0;
}

// convert edge list + histogram of dst degrees
__global__ void k_conv(const void* __restrict__ eiv) {
    int e = blockIdx.x * blockDim.x + threadIdx.x;
    if (e >= ET) return;
    int s, d;
    if (e < ER) {
        if (g_fmt == 0) {
            const long long* ei = (const long long*)eiv;
            s = (int)ei[e]; d = (int)ei[ER + e];
        } else {
            const int* ei = (const int*)eiv;
            s = ei[e]; d = ei[ER + e];
        }
        s = clampi(s); d = clampi(d);
    } else {
        s = e - ER; d = s;
    }
    g_src[e] = s;
    g_dst[e] = d;
    atomicAdd(&g_deg[d], 1);
}

// ---- two-level exclusive scan of g_deg -> g_off (R8 fix: single-block scan was 49us) ----
// Phase A: each block scans its 1024-chunk, stores exclusive-within-chunk into g_off,
//          writes chunk total into g_csum.
__global__ void k_scan_a() {
    __shared__ int warpsums[32];
    int tid = threadIdx.x, lane = tid & 31, wid = tid >> 5;
    int i = blockIdx.x * SCAN_CHUNK + tid;
    int v = (i < NN) ? g_deg[i] : 0;
    int x = v;
    #pragma unroll
    for (int o = 1; o < 32; o <<= 1) {
        int y = __shfl_up_sync(0xffffffffu, x, o);
        if (lane >= o) x += y;
    }
    if (lane == 31) warpsums[wid] = x;
    __syncthreads();
    if (wid == 0) {
        int sv = warpsums[lane];
        #pragma unroll
        for (int o = 1; o < 32; o <<= 1) {
            int y = __shfl_up_sync(0xffffffffu, sv, o);
            if (lane >= o) sv += y;
        }
        warpsums[lane] = sv;
    }
    __syncthreads();
    int incl = x + (wid > 0 ? warpsums[wid - 1] : 0);
    if (i < NN) g_off[i] = incl - v;          // exclusive within chunk
    if (tid == SCAN_CHUNK - 1) g_csum[blockIdx.x] = incl;
}

// Phase B: one small block turns g_csum into exclusive chunk offsets.
__global__ void k_scan_b() {
    __shared__ int sh[NCHUNK];
    int tid = threadIdx.x;
    if (tid < NCHUNK) sh[tid] = g_csum[tid];
    __syncthreads();
    if (tid == 0) {
        int run = 0;
        #pragma unroll
        for (int c = 0; c < NCHUNK; c++) { int t = sh[c]; sh[c] = run; run += t; }
        g_off[NN] = run;
    }
    __syncthreads();
    if (tid < NCHUNK) g_csum[tid] = sh[tid];
}

// Phase C: add chunk offsets; fill g_cur.
__global__ void k_scan_c() {
    int i = blockIdx.x * SCAN_CHUNK + threadIdx.x;
    if (i >= NN) return;
    int o = g_off[i] + g_csum[blockIdx.x];
    g_off[i] = o;
    g_cur[i] = o;
}

__global__ void k_scatter() {
    int e = blockIdx.x * blockDim.x + threadIdx.x;
    if (e >= ET) return;
    int d = g_dst[e];
    int pos = atomicAdd(&g_cur[d], 1);
    g_csrc[pos] = g_src[e];
}

// h1 = x @ W1 + fused attention dots. 256 threads, tile M=64 x N=96, K chunks 64.
__global__ void k_gemm1(const float* __restrict__ x, const float* __restrict__ W,
                        const float* __restrict__ aS, const float* __restrict__ aD) {
    __shared__ float Xsh[64][68];
    __shared__ float Wsh[64][96];
    int tid = threadIdx.x;
    int tx = tid & 31, ty = tid >> 5;
    int base = blockIdx.x * 64;
    float acc[8][3] = {};
    float aSv[3], aDv[3];
    #pragma unroll
    for (int c = 0; c < 3; c++) { aSv[c] = aS[c * 32 + tx]; aDv[c] = aD[c * 32 + tx]; }

    #pragma unroll
    for (int kc = 0; kc < 2; kc++) {
        __syncthreads();
        #pragma unroll
        for (int i = 0; i < 16; i++) {
            int idx = tid + 256 * i;
            int row = idx >> 6, kk = idx & 63;
            int gr = base + row;
            Xsh[row][kk] = (gr < NN) ? x[gr * INCH + kc * 64 + kk] : 0.f;
        }
        #pragma unroll
        for (int i = 0; i < 24; i++) {
            int idx = tid + 256 * i;
            int row = idx / 96, col = idx - row * 96;
            Wsh[row][col] = W[(kc * 64 + row) * J1 + col];
        }
        __syncthreads();
        for (int k = 0; k < 64; k += 4) {
            float4 xv[8];
            #pragma unroll
            for (int i = 0; i < 8; i++) xv[i] = *(const float4*)&Xsh[ty + 8 * i][k];
            #pragma unroll
            for (int kk = 0; kk < 4; kk++) {
                float w0 = Wsh[k + kk][tx];
                float w1 = Wsh[k + kk][tx + 32];
                float w2 = Wsh[k + kk][tx + 64];
                #pragma unroll
                for (int i = 0; i < 8; i++) {
                    float xvv = ((const float*)&xv[i])[kk];
                    acc[i][0] += xvv * w0;
                    acc[i][1] += xvv * w1;
                    acc[i][2] += xvv * w2;
                }
            }
        }
    }
    #pragma unroll
    for (int i = 0; i < 8; i++) {
        int row = base + ty + 8 * i;
        if (row >= NN) continue;
        g_h1[row * J1 + tx]      = acc[i][0];
        g_h1[row * J1 + tx + 32] = acc[i][1];
        g_h1[row * J1 + tx + 64] = acc[i][2];
        #pragma unroll
        for (int h = 0; h < HEADS; h++) {
            float vs = bsum(acc[i][h] * aSv[h]);
            float vd = bsum(acc[i][h] * aDv[h]);
            if (tx == 0) { g_as1[row * 4 + h] = vs; g_ad1[row * 4 + h] = vd; }
        }
    }
}

// Fused layer-1 softmax + aggregation. Warp per dst node.
__global__ void k_fagg1() {
    int d = (int)((blockIdx.x * blockDim.x + threadIdx.x) >> 5);
    int lane = threadIdx.x & 31;
    if (d >= NN) return;
    int beg = g_off[d], end = g_off[d + 1];
    float4 adv = *(const float4*)&g_ad1[d * 4];
    float acc0 = 0.f, acc1 = 0.f, acc2 = 0.f;
    float sp0 = 0.f, sp1 = 0.f, sp2 = 0.f;
    for (int j = beg; j < end; j += 32) {
        int n = end - j; if (n > 32) n = 32;
        int s = 0; float p0 = 0.f, p1 = 0.f, p2 = 0.f;
        if (lane < n) {
            s = g_csrc[j + lane];
            float4 a = *(const float4*)&g_as1[s * 4];
            p0 = lrelu_exp(a.x + adv.x);
            p1 = lrelu_exp(a.y + adv.y);
            p2 = lrelu_exp(a.z + adv.z);
            sp0 += p0; sp1 += p1; sp2 += p2;
        }
        for (int i = 0; i < n; i++) {
            int   si = __shfl_sync(0xffffffffu, s,  i);
            float q0 = __shfl_sync(0xffffffffu, p0, i);
            float q1 = __shfl_sync(0xffffffffu, p1, i);
            float q2 = __shfl_sync(0xffffffffu, p2, i);
            const float* hp = &g_h1[si * J1];
            acc0 += q0 * hp[lane];
            acc1 += q1 * hp[lane + 32];
            acc2 += q2 * hp[lane + 64];
        }
    }
    sp0 = bsum(sp0); sp1 = bsum(sp1); sp2 = bsum(sp2);
    float r0 = 1.f / (sp0 + 1e-16f);
    float r1 = 1.f / (sp1 + 1e-16f);
    float r2 = 1.f / (sp2 + 1e-16f);
    g_o1[d * J1 + lane]      = acc0 * r0;
    g_o1[d * J1 + lane + 32] = acc1 * r1;
    g_o1[d * J1 + lane + 64] = acc2 * r2;
}

// h2 = elu(o1 + b1) @ W2 ; a_s2/a_d2. One 8-row tile per block, grid = NN/8.
__global__ void k_gemm2(const float* __restrict__ W, const float* __restrict__ b1,
                        const float* __restrict__ aS, const float* __restrict__ aD) {
    __shared__ float Wsh[J1 * OC];
    __shared__ float Xsh[8 * J1];
    int tid = threadIdx.x;
    for (int i = tid; i < J1 * OC; i += 256) Wsh[i] = W[i];
    int r = tid >> 5, lane = tid & 31;
    float aws = aS[lane], awd = aD[lane];
    int base = blockIdx.x * 8;
    for (int i = tid; i < 8 * J1; i += 256) {
        int rr = i / J1, k = i - rr * J1;
        float v = g_o1[(base + rr) * J1 + k] + b1[k];
        v = v > 0.f ? v : (__expf(v) - 1.f);
        Xsh[i] = v;
    }
    __syncthreads();
    int row = base + r;
    float acc = 0.f;
    #pragma unroll 16
    for (int k = 0; k < J1; k++) acc += Xsh[r * J1 + k] * Wsh[k * OC + lane];
    g_h2[row * OC + lane] = acc;
    float vs = bsum(acc * aws);
    float vd = bsum(acc * awd);
    if (lane == 0) { g_as2[row] = vs; g_ad2[row] = vd; }
}

// Fused layer-2 softmax + aggregation + bias + project + sigmoid. Warp per node.
__global__ void k_fagg2(const float* __restrict__ b2, const float* __restrict__ Wp,
                        const float* __restrict__ bp, float* __restrict__ out) {
    int d = (int)((blockIdx.x * blockDim.x + threadIdx.x) >> 5);
    int lane = threadIdx.x & 31;
    if (d >= NN) return;
    int beg = g_off[d], end = g_off[d + 1];
    float adv = g_ad2[d];
    float acc = 0.f, sp = 0.f;
    for (int j = beg; j < end; j += 32) {
        int n = end - j; if (n > 32) n = 32;
        int s = 0; float p = 0.f;
        if (lane < n) {
            s = g_csrc[j + lane];
            p = lrelu_exp(g_as2[s] + adv);
            sp += p;
        }
        for (int i = 0; i < n; i++) {
            int   si = __shfl_sync(0xffffffffu, s, i);
            float q  = __shfl_sync(0xffffffffu, p, i);
            acc += q * g_h2[si * OC + lane];
        }
    }
    sp = bsum(sp);
    float o2 = acc * (1.f / (sp + 1e-16f)) + b2[lane];
    float t = bsum(o2 * Wp[lane]);
    if (lane == 0) out[d] = 1.f / (1.f + __expf(-t - bp[0]));
}

// ---------------- launch ----------------
extern "C" void kernel_launch(void* const* d_in, const int* in_sizes, int n_in,
                              void* d_out, int out_size) {
    const float* x   = (const float*)d_in[0];
    const void*  ei  = d_in[1];
    const float* W1  = (const float*)d_in[2];
    const float* as1 = (const float*)d_in[3];
    const float* ad1 = (const float*)d_in[4];
    const float* b1  = (const float*)d_in[5];
    const float* W2  = (const float*)d_in[6];
    const float* as2 = (const float*)d_in[7];
    const float* ad2 = (const float*)d_in[8];
    const float* b2  = (const float*)d_in[9];
    const float* Wp  = (const float*)d_in[10];
    const float* bp  = (const float*)d_in[11];
    float* out = (float*)d_out;

    const int nodeWarpBlocks = (NN * 32 + 255) / 256;   // warp per node

    k_detect<<<1, 256>>>((const int*)ei);
    k_zerodeg<<<(NN + 255) / 256, 256>>>();
    k_conv<<<(ET + 255) / 256, 256>>>(ei);
    k_scan_a<<<NCHUNK, SCAN_CHUNK>>>();
    k_scan_b<<<1, 64>>>();
    k_scan_c<<<NCHUNK, SCAN_CHUNK>>>();
    k_scatter<<<(ET + 255) / 256, 256>>>();
    k_gemm1<<<(NN + 63) / 64, 256>>>(x, W1, as1, ad1);
    k_fagg1<<<nodeWarpBlocks, 256>>>();
    k_gemm2<<<NN / 8, 256>>>(W2, b1, as2, ad2);
    k_fagg2<<<nodeWarpBlocks, 256>>>(b2, Wp, bp, out);
}

// round 10
// speedup vs baseline: 2.7550x; 1.1072x over previous
#include <cuda_runtime.h>
#include <cuda_bf16.h>

#define NN     50000
#define ER     1600000
#define ET     1650000      // edges + self loops
#define INCH   128
#define J1     96           // HEADS*HID
#define HEADS  3
#define HID    32
#define OC     32
#define NEG    0.2f

#define NW1    48            // h1 bf16x2 words per node (96 ch)
#define NW2    16            // h2 bf16x2 words per node (32 ch)

#define SCAN_CHUNK 1024
#define NCHUNK ((NN + SCAN_CHUNK - 1) / SCAN_CHUNK)   // 49

// ---------------- scratch (device globals; no allocation allowed) ----------------
__device__ int   g_fmt;                       // 0 = int64 edge buffer, 1 = int32
__device__ __align__(16) int      g_src [ET];
__device__ __align__(16) int      g_dst [ET];
__device__ __align__(16) int      g_deg [NN];
__device__ __align__(16) int      g_off [NN + 1];
__device__ __align__(16) int      g_cur [NN];
__device__ __align__(16) int      g_csum[NCHUNK];
__device__ __align__(16) int      g_csrc[ET];       // CSR: src ids sorted by dst
__device__ __align__(16) unsigned g_h1b [NN * NW1]; // h1 packed bf16x2
__device__ __align__(16) float    g_as1 [NN * 4];   // padded float4 per node (3 heads)
__device__ __align__(16) float    g_ad1 [NN * 4];
__device__ __align__(16) float    g_o1  [NN * J1];
__device__ __align__(16) unsigned g_h2b [NN * NW2]; // h2 packed bf16x2
__device__ __align__(16) float    g_as2 [NN];
__device__ __align__(16) float    g_ad2 [NN];

// ---------------- helpers ----------------
__device__ __forceinline__ float bsum(float v) {          // all lanes get the sum
    v += __shfl_xor_sync(0xffffffffu, v, 16);
    v += __shfl_xor_sync(0xffffffffu, v, 8);
    v += __shfl_xor_sync(0xffffffffu, v, 4);
    v += __shfl_xor_sync(0xffffffffu, v, 2);
    v += __shfl_xor_sync(0xffffffffu, v, 1);
    return v;
}
__device__ __forceinline__ int clampi(int v) {
    return v < 0 ? 0 : (v >= NN ? NN - 1 : v);
}
__device__ __forceinline__ float lrelu_exp(float v) {
    v = v > 0.f ? v : NEG * v;
    return __expf(v);
}
__device__ __forceinline__ unsigned packbf(float a, float b) {
    __nv_bfloat162 t = __floats2bfloat162_rn(a, b);
    return *(unsigned*)&t;
}
__device__ __forceinline__ float2 unpackbf(unsigned u) {
    __nv_bfloat162 t = *(__nv_bfloat162*)&u;
    return __bfloat1622float2(t);
}

// ---------------- kernels ----------------
// Detect int64 vs int32 edge buffer: int64 values < 50000 => odd int32 slots all 0.
__global__ void k_detect(const int* __restrict__ ei32) {
    __shared__ int nz;
    if (threadIdx.x == 0) nz = 0;
    __syncthreads();
    for (int i = threadIdx.x; i < 2048; i += blockDim.x)
        if (ei32[2 * i * 391 + 1] != 0) atomicOr(&nz, 1);
    __syncthreads();
    if (threadIdx.x == 0) g_fmt = nz ? 1 : 0;
}

__global__ void k_zerodeg() {
    int i = blockIdx.x * blockDim.x + threadIdx.x;
    if (i < NN) g_deg[i] = 0;
}

// convert edge list + histogram of dst degrees
__global__ void k_conv(const void* __restrict__ eiv) {
    int e = blockIdx.x * blockDim.x + threadIdx.x;
    if (e >= ET) return;
    int s, d;
    if (e < ER) {
        if (g_fmt == 0) {
            const long long* ei = (const long long*)eiv;
            s = (int)ei[e]; d = (int)ei[ER + e];
        } else {
            const int* ei = (const int*)eiv;
            s = ei[e]; d = ei[ER + e];
        }
        s = clampi(s); d = clampi(d);
    } else {
        s = e - ER; d = s;
    }
    g_src[e] = s;
    g_dst[e] = d;
    atomicAdd(&g_deg[d], 1);
}

// ---- two-level exclusive scan of g_deg -> g_off ----
__global__ void k_scan_a() {
    __shared__ int warpsums[32];
    int tid = threadIdx.x, lane = tid & 31, wid = tid >> 5;
    int i = blockIdx.x * SCAN_CHUNK + tid;
    int v = (i < NN) ? g_deg[i] : 0;
    int x = v;
    #pragma unroll
    for (int o = 1; o < 32; o <<= 1) {
        int y = __shfl_up_sync(0xffffffffu, x, o);
        if (lane >= o) x += y;
    }
    if (lane == 31) warpsums[wid] = x;
    __syncthreads();
    if (wid == 0) {
        int sv = warpsums[lane];
        #pragma unroll
        for (int o = 1; o < 32; o <<= 1) {
            int y = __shfl_up_sync(0xffffffffu, sv, o);
            if (lane >= o) sv += y;
        }
        warpsums[lane] = sv;
    }
    __syncthreads();
    int incl = x + (wid > 0 ? warpsums[wid - 1] : 0);
    if (i < NN) g_off[i] = incl - v;          // exclusive within chunk
    if (tid == SCAN_CHUNK - 1) g_csum[blockIdx.x] = incl;
}

__global__ void k_scan_b() {
    __shared__ int sh[NCHUNK];
    int tid = threadIdx.x;
    if (tid < NCHUNK) sh[tid] = g_csum[tid];
    __syncthreads();
    if (tid == 0) {
        int run = 0;
        #pragma unroll
        for (int c = 0; c < NCHUNK; c++) { int t = sh[c]; sh[c] = run; run += t; }
        g_off[NN] = run;
    }
    __syncthreads();
    if (tid < NCHUNK) g_csum[tid] = sh[tid];
}

__global__ void k_scan_c() {
    int i = blockIdx.x * SCAN_CHUNK + threadIdx.x;
    if (i >= NN) return;
    int o = g_off[i] + g_csum[blockIdx.x];
    g_off[i] = o;
    g_cur[i] = o;
}

__global__ void k_scatter() {
    int e = blockIdx.x * blockDim.x + threadIdx.x;
    if (e >= ET) return;
    int d = g_dst[e];
    int pos = atomicAdd(&g_cur[d], 1);
    g_csrc[pos] = g_src[e];
}

// h1 = x @ W1 + fused attention dots; h1 stored as packed bf16x2
// (word w of node = channels (2w,2w+1), head = w/16).
__global__ void k_gemm1(const float* __restrict__ x, const float* __restrict__ W,
                        const float* __restrict__ aS, const float* __restrict__ aD) {
    __shared__ float Xsh[64][68];
    __shared__ float Wsh[64][96];
    int tid = threadIdx.x;
    int tx = tid & 31, ty = tid >> 5;
    int base = blockIdx.x * 64;
    float acc[8][3] = {};
    float aSv[3], aDv[3];
    #pragma unroll
    for (int c = 0; c < 3; c++) { aSv[c] = aS[c * 32 + tx]; aDv[c] = aD[c * 32 + tx]; }

    #pragma unroll
    for (int kc = 0; kc < 2; kc++) {
        __syncthreads();
        #pragma unroll
        for (int i = 0; i < 16; i++) {
            int idx = tid + 256 * i;
            int row = idx >> 6, kk = idx & 63;
            int gr = base + row;
            Xsh[row][kk] = (gr < NN) ? x[gr * INCH + kc * 64 + kk] : 0.f;
        }
        #pragma unroll
        for (int i = 0; i < 24; i++) {
            int idx = tid + 256 * i;
            int row = idx / 96, col = idx - row * 96;
            Wsh[row][col] = W[(kc * 64 + row) * J1 + col];
        }
        __syncthreads();
        for (int k = 0; k < 64; k += 4) {
            float4 xv[8];
            #pragma unroll
            for (int i = 0; i < 8; i++) xv[i] = *(const float4*)&Xsh[ty + 8 * i][k];
            #pragma unroll
            for (int kk = 0; kk < 4; kk++) {
                float w0 = Wsh[k + kk][tx];
                float w1 = Wsh[k + kk][tx + 32];
                float w2 = Wsh[k + kk][tx + 64];
                #pragma unroll
                for (int i = 0; i < 8; i++) {
                    float xvv = ((const float*)&xv[i])[kk];
                    acc[i][0] += xvv * w0;
                    acc[i][1] += xvv * w1;
                    acc[i][2] += xvv * w2;
                }
            }
        }
    }
    #pragma unroll
    for (int i = 0; i < 8; i++) {
        int row = base + ty + 8 * i;
        if (row >= NN) continue;                         // warp-uniform
        #pragma unroll
        for (int c = 0; c < 3; c++) {
            float hi = __shfl_down_sync(0xffffffffu, acc[i][c], 1);
            if (!(tx & 1))
                g_h1b[row * NW1 + c * 16 + (tx >> 1)] = packbf(acc[i][c], hi);
            float vs = bsum(acc[i][c] * aSv[c]);
            float vd = bsum(acc[i][c] * aDv[c]);
            if (tx == 0) { g_as1[row * 4 + c] = vs; g_ad1[row * 4 + c] = vd; }
        }
    }
}

// Fused layer-1 softmax + aggregation. Warp per dst node; bf16 gathers:
// lane l accumulates word l (heads 0/1) and, for l<16, word 32+l (head 2).
__global__ void k_fagg1() {
    int d = (int)((blockIdx.x * blockDim.x + threadIdx.x) >> 5);
    int lane = threadIdx.x & 31;
    if (d >= NN) return;
    int beg = g_off[d], end = g_off[d + 1];
    float4 adv = *(const float4*)&g_ad1[d * 4];
    float2 accA = {0.f, 0.f}, accB = {0.f, 0.f};
    float sp0 = 0.f, sp1 = 0.f, sp2 = 0.f;
    for (int j = beg; j < end; j += 32) {
        int n = end - j; if (n > 32) n = 32;
        int s = 0; float p0 = 0.f, p1 = 0.f, p2 = 0.f;
        if (lane < n) {
            s = g_csrc[j + lane];
            float4 a = *(const float4*)&g_as1[s * 4];
            p0 = lrelu_exp(a.x + adv.x);
            p1 = lrelu_exp(a.y + adv.y);
            p2 = lrelu_exp(a.z + adv.z);
            sp0 += p0; sp1 += p1; sp2 += p2;
        }
        for (int i = 0; i < n; i++) {
            int   si = __shfl_sync(0xffffffffu, s,  i);
            float q0 = __shfl_sync(0xffffffffu, p0, i);
            float q1 = __shfl_sync(0xffffffffu, p1, i);
            float q2 = __shfl_sync(0xffffffffu, p2, i);
            const unsigned* hw = &g_h1b[si * NW1];
            float2 va = unpackbf(hw[lane]);
            float qa = (lane < 16) ? q0 : q1;
            accA.x += qa * va.x; accA.y += qa * va.y;
            if (lane < 16) {
                float2 vb = unpackbf(hw[32 + lane]);
                accB.x += q2 * vb.x; accB.y += q2 * vb.y;
            }
        }
    }
    sp0 = bsum(sp0); sp1 = bsum(sp1); sp2 = bsum(sp2);
    float r0 = 1.f / (sp0 + 1e-16f);
    float r1 = 1.f / (sp1 + 1e-16f);
    float r2 = 1.f / (sp2 + 1e-16f);
    float ra = (lane < 16) ? r0 : r1;
    int head = lane >> 4, jj = lane & 15;
    float2 oa = { accA.x * ra, accA.y * ra };
    *(float2*)&g_o1[d * J1 + head * 32 + 2 * jj] = oa;
    if (lane < 16) {
        float2 ob = { accB.x * r2, accB.y * r2 };
        *(float2*)&g_o1[d * J1 + 64 + 2 * lane] = ob;
    }
}

// h2 = elu(o1 + b1) @ W2 ; a_s2/a_d2; h2 stored packed bf16x2.
__global__ void k_gemm2(const float* __restrict__ W, const float* __restrict__ b1,
                        const float* __restrict__ aS, const float* __restrict__ aD) {
    __shared__ float Wsh[J1 * OC];
    __shared__ float Xsh[8 * J1];
    int tid = threadIdx.x;
    for (int i = tid; i < J1 * OC; i += 256) Wsh[i] = W[i];
    int r = tid >> 5, lane = tid & 31;
    float aws = aS[lane], awd = aD[lane];
    int base = blockIdx.x * 8;
    for (int i = tid; i < 8 * J1; i += 256) {
        int rr = i / J1, k = i - rr * J1;
        float v = g_o1[(base + rr) * J1 + k] + b1[k];
        v = v > 0.f ? v : (__expf(v) - 1.f);
        Xsh[i] = v;
    }
    __syncthreads();
    int row = base + r;
    float acc = 0.f;
    #pragma unroll 16
    for (int k = 0; k < J1; k++) acc += Xsh[r * J1 + k] * Wsh[k * OC + lane];
    float hi = __shfl_down_sync(0xffffffffu, acc, 1);
    if (!(lane & 1)) g_h2b[row * NW2 + (lane >> 1)] = packbf(acc, hi);
    float vs = bsum(acc * aws);
    float vd = bsum(acc * awd);
    if (lane == 0) { g_as2[row] = vs; g_ad2[row] = vd; }
}

// Fused layer-2 softmax + aggregation + bias + project + sigmoid. Warp per node.
__global__ void k_fagg2(const float* __restrict__ b2, const float* __restrict__ Wp,
                        const float* __restrict__ bp, float* __restrict__ out) {
    int d = (int)((blockIdx.x * blockDim.x + threadIdx.x) >> 5);
    int lane = threadIdx.x & 31;
    if (d >= NN) return;
    int beg = g_off[d], end = g_off[d + 1];
    float adv = g_ad2[d];
    float2 acc = {0.f, 0.f};
    float sp = 0.f;
    for (int j = beg; j < end; j += 32) {
        int n = end - j; if (n > 32) n = 32;
        int s = 0; float p = 0.f;
        if (lane < n) {
            s = g_csrc[j + lane];
            p = lrelu_exp(g_as2[s] + adv);
            sp += p;
        }
        for (int i = 0; i < n; i++) {
            int   si = __shfl_sync(0xffffffffu, s, i);
            float q  = __shfl_sync(0xffffffffu, p, i);
            if (lane < 16) {
                float2 v = unpackbf(g_h2b[si * NW2 + lane]);
                acc.x += q * v.x; acc.y += q * v.y;
            }
        }
    }
    sp = bsum(sp);
    float r = 1.f / (sp + 1e-16f);
    float t = 0.f;
    if (lane < 16) {
        float ox = acc.x * r + b2[2 * lane];
        float oy = acc.y * r + b2[2 * lane + 1];
        t = ox * Wp[2 * lane] + oy * Wp[2 * lane + 1];
    }
    t = bsum(t);
    if (lane == 0) out[d] = 1.f / (1.f + __expf(-t - bp[0]));
}

// ---------------- launch ----------------
extern "C" void kernel_launch(void* const* d_in, const int* in_sizes, int n_in,
                              void* d_out, int out_size) {
    const float* x   = (const float*)d_in[0];
    const void*  ei  = d_in[1];
    const float* W1  = (const float*)d_in[2];
    const float* as1 = (const float*)d_in[3];
    const float* ad1 = (const float*)d_in[4];
    const float* b1  = (const float*)d_in[5];
    const float* W2  = (const float*)d_in[6];
    const float* as2 = (const float*)d_in[7];
    const float* ad2 = (const float*)d_in[8];
    const float* b2  = (const float*)d_in[9];
    const float* Wp  = (const float*)d_in[10];
    const float* bp  = (const float*)d_in[11];
    float* out = (float*)d_out;

    const int nodeWarpBlocks = (NN * 32 + 255) / 256;   // warp per node

    k_detect<<<1, 256>>>((const int*)ei);
    k_zerodeg<<<(NN + 255) / 256, 256>>>();
    k_conv<<<(ET + 255) / 256, 256>>>(ei);
    k_scan_a<<<NCHUNK, SCAN_CHUNK>>>();
    k_scan_b<<<1, 64>>>();
    k_scan_c<<<NCHUNK, SCAN_CHUNK>>>();
    k_scatter<<<(ET + 255) / 256, 256>>>();
    k_gemm1<<<(NN + 63) / 64, 256>>>(x, W1, as1, ad1);
    k_fagg1<<<nodeWarpBlocks, 256>>>();
    k_gemm2<<<NN / 8, 256>>>(W2, b1, as2, ad2);
    k_fagg2<<<nodeWarpBlocks, 256>>>(b2, Wp, bp, out);
}

// round 11
// speedup vs baseline: 2.7965x; 1.0151x over previous
#include <cuda_runtime.h>
#include <cuda_bf16.h>
#include <mma.h>
using namespace nvcuda;

#define NN     50000
#define PADN   50048          // 64-row padded for wmma tiles
#define ER     1600000
#define ET     1650000        // edges + self loops
#define INCH   128
#define J1     96             // HEADS*HID
#define HEADS  3
#define HID    32
#define OC     32
#define NEG    0.2f

#define NW1    48             // h1 bf16x2 words per node (96 ch)
#define NW2    16             // h2 bf16x2 words per node (32 ch)

#define SCAN_CHUNK 1024
#define NCHUNK ((NN + SCAN_CHUNK - 1) / SCAN_CHUNK)   // 49

// ---------------- scratch (device globals; no allocation allowed) ----------------
__device__ int   g_fmt;                       // 0 = int64 edge buffer, 1 = int32
__device__ __align__(16) int           g_src [ET];
__device__ __align__(16) int           g_dst [ET];
__device__ __align__(16) int           g_deg [NN];
__device__ __align__(16) int           g_off [NN + 1];
__device__ __align__(16) int           g_cur [NN];
__device__ __align__(16) int           g_csum[NCHUNK];
__device__ __align__(16) int           g_csrc[ET];        // CSR: src ids sorted by dst
__device__ __align__(16) __nv_bfloat16 g_xb  [PADN * INCH]; // x in bf16 (padded)
__device__ __align__(16) __nv_bfloat16 g_W1b [INCH * J1];   // W1 in bf16
__device__ __align__(16) unsigned      g_h1b [NN * NW1];    // h1 packed bf16x2
__device__ __align__(16) float         g_as1 [NN * 4];      // padded float4 (3 heads)
__device__ __align__(16) float         g_ad1 [NN * 4];
__device__ __align__(16) float         g_o1  [NN * J1];
__device__ __align__(16) unsigned      g_h2b [NN * NW2];    // h2 packed bf16x2
__device__ __align__(16) float         g_as2 [NN];
__device__ __align__(16) float         g_ad2 [NN];

// ---------------- helpers ----------------
__device__ __forceinline__ float bsum(float v) {          // all lanes get the sum
    v += __shfl_xor_sync(0xffffffffu, v, 16);
    v += __shfl_xor_sync(0xffffffffu, v, 8);
    v += __shfl_xor_sync(0xffffffffu, v, 4);
    v += __shfl_xor_sync(0xffffffffu, v, 2);
    v += __shfl_xor_sync(0xffffffffu, v, 1);
    return v;
}
__device__ __forceinline__ int clampi(int v) {
    return v < 0 ? 0 : (v >= NN ? NN - 1 : v);
}
__device__ __forceinline__ float lrelu_exp(float v) {
    v = v > 0.f ? v : NEG * v;
    return __expf(v);
}
__device__ __forceinline__ unsigned packbf(float a, float b) {
    __nv_bfloat162 t = __floats2bfloat162_rn(a, b);
    return *(unsigned*)&t;
}
__device__ __forceinline__ float2 unpackbf(unsigned u) {
    __nv_bfloat162 t = *(__nv_bfloat162*)&u;
    return __bfloat1622float2(t);
}

// ---------------- kernels ----------------
// Detect int64 vs int32 edge buffer: int64 values < 50000 => odd int32 slots all 0.
__global__ void k_detect(const int* __restrict__ ei32) {
    __shared__ int nz;
    if (threadIdx.x == 0) nz = 0;
    __syncthreads();
    for (int i = threadIdx.x; i < 2048; i += blockDim.x)
        if (ei32[2 * i * 391 + 1] != 0) atomicOr(&nz, 1);
    __syncthreads();
    if (threadIdx.x == 0) g_fmt = nz ? 1 : 0;
}

__global__ void k_zerodeg() {
    int i = blockIdx.x * blockDim.x + threadIdx.x;
    if (i < NN) g_deg[i] = 0;
}

// convert edge list + histogram of dst degrees
__global__ void k_conv(const void* __restrict__ eiv) {
    int e = blockIdx.x * blockDim.x + threadIdx.x;
    if (e >= ET) return;
    int s, d;
    if (e < ER) {
        if (g_fmt == 0) {
            const long long* ei = (const long long*)eiv;
            s = (int)ei[e]; d = (int)ei[ER + e];
        } else {
            const int* ei = (const int*)eiv;
            s = ei[e]; d = ei[ER + e];
        }
        s = clampi(s); d = clampi(d);
    } else {
        s = e - ER; d = s;
    }
    g_src[e] = s;
    g_dst[e] = d;
    atomicAdd(&g_deg[d], 1);
}

// convert x and W1 to bf16 (4 elements per thread)
__global__ void k_cvt(const float* __restrict__ x, const float* __restrict__ W1) {
    int i4 = blockIdx.x * blockDim.x + threadIdx.x;
    int i = i4 * 4;
    if (i < PADN * INCH) {
        float4 v;
        if (i < NN * INCH) v = *(const float4*)&x[i];
        else v = make_float4(0.f, 0.f, 0.f, 0.f);
        unsigned lo = packbf(v.x, v.y), hi = packbf(v.z, v.w);
        *(uint2*)&g_xb[i] = make_uint2(lo, hi);
    }
    if (i < INCH * J1) {
        float4 w = *(const float4*)&W1[i];
        *(uint2*)&g_W1b[i] = make_uint2(packbf(w.x, w.y), packbf(w.z, w.w));
    }
}

// ---- two-level exclusive scan of g_deg -> g_off ----
__global__ void k_scan_a() {
    __shared__ int warpsums[32];
    int tid = threadIdx.x, lane = tid & 31, wid = tid >> 5;
    int i = blockIdx.x * SCAN_CHUNK + tid;
    int v = (i < NN) ? g_deg[i] : 0;
    int x = v;
    #pragma unroll
    for (int o = 1; o < 32; o <<= 1) {
        int y = __shfl_up_sync(0xffffffffu, x, o);
        if (lane >= o) x += y;
    }
    if (lane == 31) warpsums[wid] = x;
    __syncthreads();
    if (wid == 0) {
        int sv = warpsums[lane];
        #pragma unroll
        for (int o = 1; o < 32; o <<= 1) {
            int y = __shfl_up_sync(0xffffffffu, sv, o);
            if (lane >= o) sv += y;
        }
        warpsums[lane] = sv;
    }
    __syncthreads();
    int incl = x + (wid > 0 ? warpsums[wid - 1] : 0);
    if (i < NN) g_off[i] = incl - v;          // exclusive within chunk
    if (tid == SCAN_CHUNK - 1) g_csum[blockIdx.x] = incl;
}

__global__ void k_scan_b() {
    __shared__ int sh[NCHUNK];
    int tid = threadIdx.x;
    if (tid < NCHUNK) sh[tid] = g_csum[tid];
    __syncthreads();
    if (tid == 0) {
        int run = 0;
        #pragma unroll
        for (int c = 0; c < NCHUNK; c++) { int t = sh[c]; sh[c] = run; run += t; }
        g_off[NN] = run;
    }
    __syncthreads();
    if (tid < NCHUNK) g_csum[tid] = sh[tid];
}

__global__ void k_scan_c() {
    int i = blockIdx.x * SCAN_CHUNK + threadIdx.x;
    if (i >= NN) return;
    int o = g_off[i] + g_csum[blockIdx.x];
    g_off[i] = o;
    g_cur[i] = o;
}

__global__ void k_scatter() {
    int e = blockIdx.x * blockDim.x + threadIdx.x;
    if (e >= ET) return;
    int d = g_dst[e];
    int pos = atomicAdd(&g_cur[d], 1);
    g_csrc[pos] = g_src[e];
}

// h1 = x @ W1 via wmma bf16 (tensor pipe), fp32 accum; fused attention dots.
// Block = 256 thr (8 warps), tile M=64 x N=96. Warp wid: m-stripe wid>>1,
// n-tiles 3*(wid&1)..+3. Fragments loaded straight from global (L1-resident).
__global__ void k_gemm1(const float* __restrict__ aS, const float* __restrict__ aD) {
    __shared__ float Csh[64][96];
    int tid = threadIdx.x;
    int wid = tid >> 5, tx = tid & 31;
    int base = blockIdx.x * 64;
    int mt  = wid >> 1;            // 0..3
    int nt0 = (wid & 1) * 3;       // 0 or 3

    wmma::fragment<wmma::matrix_a, 16, 16, 16, __nv_bfloat16, wmma::row_major> fa;
    wmma::fragment<wmma::matrix_b, 16, 16, 16, __nv_bfloat16, wmma::row_major> fb;
    wmma::fragment<wmma::accumulator, 16, 16, 16, float> fc[3];
    #pragma unroll
    for (int t = 0; t < 3; t++) wmma::fill_fragment(fc[t], 0.f);

    const __nv_bfloat16* A = g_xb + (base + mt * 16) * INCH;
    #pragma unroll
    for (int k0 = 0; k0 < INCH; k0 += 16) {
        wmma::load_matrix_sync(fa, A + k0, INCH);
        #pragma unroll
        for (int t = 0; t < 3; t++) {
            wmma::load_matrix_sync(fb, g_W1b + k0 * J1 + (nt0 + t) * 16, J1);
            wmma::mma_sync(fc[t], fa, fb, fc[t]);
        }
    }
    #pragma unroll
    for (int t = 0; t < 3; t++)
        wmma::store_matrix_sync(&Csh[mt * 16][(nt0 + t) * 16], fc[t], J1, wmma::mem_row_major);
    __syncthreads();

    // epilogue: warp wid handles rows wid*8 .. wid*8+7
    float aSv[3], aDv[3];
    #pragma unroll
    for (int c = 0; c < 3; c++) { aSv[c] = aS[c * 32 + tx]; aDv[c] = aD[c * 32 + tx]; }
    #pragma unroll
    for (int i = 0; i < 8; i++) {
        int lrow = wid * 8 + i;
        int row = base + lrow;
        if (row >= NN) continue;            // warp-uniform
        #pragma unroll
        for (int c = 0; c < 3; c++) {
            float v = Csh[lrow][c * 32 + tx];
            float hi = __shfl_down_sync(0xffffffffu, v, 1);
            if (!(tx & 1))
                g_h1b[row * NW1 + c * 16 + (tx >> 1)] = packbf(v, hi);
            float vs = bsum(v * aSv[c]);
            float vd = bsum(v * aDv[c]);
            if (tx == 0) { g_as1[row * 4 + c] = vs; g_ad1[row * 4 + c] = vd; }
        }
    }
}

// Fused layer-1 softmax + aggregation. Warp per dst node; bf16 gathers.
__global__ void k_fagg1() {
    int d = (int)((blockIdx.x * blockDim.x + threadIdx.x) >> 5);
    int lane = threadIdx.x & 31;
    if (d >= NN) return;
    int beg = g_off[d], end = g_off[d + 1];
    float4 adv = *(const float4*)&g_ad1[d * 4];
    float2 accA = {0.f, 0.f}, accB = {0.f, 0.f};
    float sp0 = 0.f, sp1 = 0.f, sp2 = 0.f;
    for (int j = beg; j < end; j += 32) {
        int n = end - j; if (n > 32) n = 32;
        int s = 0; float p0 = 0.f, p1 = 0.f, p2 = 0.f;
        if (lane < n) {
            s = g_csrc[j + lane];
            float4 a = *(const float4*)&g_as1[s * 4];
            p0 = lrelu_exp(a.x + adv.x);
            p1 = lrelu_exp(a.y + adv.y);
            p2 = lrelu_exp(a.z + adv.z);
            sp0 += p0; sp1 += p1; sp2 += p2;
        }
        for (int i = 0; i < n; i++) {
            int   si = __shfl_sync(0xffffffffu, s,  i);
            float q0 = __shfl_sync(0xffffffffu, p0, i);
            float q1 = __shfl_sync(0xffffffffu, p1, i);
            float q2 = __shfl_sync(0xffffffffu, p2, i);
            const unsigned* hw = &g_h1b[si * NW1];
            float2 va = unpackbf(hw[lane]);
            float qa = (lane < 16) ? q0 : q1;
            accA.x += qa * va.x; accA.y += qa * va.y;
            if (lane < 16) {
                float2 vb = unpackbf(hw[32 + lane]);
                accB.x += q2 * vb.x; accB.y += q2 * vb.y;
            }
        }
    }
    sp0 = bsum(sp0); sp1 = bsum(sp1); sp2 = bsum(sp2);
    float r0 = 1.f / (sp0 + 1e-16f);
    float r1 = 1.f / (sp1 + 1e-16f);
    float r2 = 1.f / (sp2 + 1e-16f);
    float ra = (lane < 16) ? r0 : r1;
    int head = lane >> 4, jj = lane & 15;
    float2 oa = { accA.x * ra, accA.y * ra };
    *(float2*)&g_o1[d * J1 + head * 32 + 2 * jj] = oa;
    if (lane < 16) {
        float2 ob = { accB.x * r2, accB.y * r2 };
        *(float2*)&g_o1[d * J1 + 64 + 2 * lane] = ob;
    }
}

// h2 = elu(o1 + b1) @ W2 ; a_s2/a_d2; h2 stored packed bf16x2.
__global__ void k_gemm2(const float* __restrict__ W, const float* __restrict__ b1,
                        const float* __restrict__ aS, const float* __restrict__ aD) {
    __shared__ float Wsh[J1 * OC];
    __shared__ float Xsh[8 * J1];
    int tid = threadIdx.x;
    for (int i = tid; i < J1 * OC; i += 256) Wsh[i] = W[i];
    int r = tid >> 5, lane = tid & 31;
    float aws = aS[lane], awd = aD[lane];
    int base = blockIdx.x * 8;
    for (int i = tid; i < 8 * J1; i += 256) {
        int rr = i / J1, k = i - rr * J1;
        float v = g_o1[(base + rr) * J1 + k] + b1[k];
        v = v > 0.f ? v : (__expf(v) - 1.f);
        Xsh[i] = v;
    }
    __syncthreads();
    int row = base + r;
    float acc = 0.f;
    #pragma unroll 16
    for (int k = 0; k < J1; k++) acc += Xsh[r * J1 + k] * Wsh[k * OC + lane];
    float hi = __shfl_down_sync(0xffffffffu, acc, 1);
    if (!(lane & 1)) g_h2b[row * NW2 + (lane >> 1)] = packbf(acc, hi);
    float vs = bsum(acc * aws);
    float vd = bsum(acc * awd);
    if (lane == 0) { g_as2[row] = vs; g_ad2[row] = vd; }
}

// Fused layer-2 softmax + aggregation + bias + project + sigmoid. Warp per node.
__global__ void k_fagg2(const float* __restrict__ b2, const float* __restrict__ Wp,
                        const float* __restrict__ bp, float* __restrict__ out) {
    int d = (int)((blockIdx.x * blockDim.x + threadIdx.x) >> 5);
    int lane = threadIdx.x & 31;
    if (d >= NN) return;
    int beg = g_off[d], end = g_off[d + 1];
    float adv = g_ad2[d];
    float2 acc = {0.f, 0.f};
    float sp = 0.f;
    for (int j = beg; j < end; j += 32) {
        int n = end - j; if (n > 32) n = 32;
        int s = 0; float p = 0.f;
        if (lane < n) {
            s = g_csrc[j + lane];
            p = lrelu_exp(g_as2[s] + adv);
            sp += p;
        }
        for (int i = 0; i < n; i++) {
            int   si = __shfl_sync(0xffffffffu, s, i);
            float q  = __shfl_sync(0xffffffffu, p, i);
            if (lane < 16) {
                float2 v = unpackbf(g_h2b[si * NW2 + lane]);
                acc.x += q * v.x; acc.y += q * v.y;
            }
        }
    }
    sp = bsum(sp);
    float r = 1.f / (sp + 1e-16f);
    float t = 0.f;
    if (lane < 16) {
        float ox = acc.x * r + b2[2 * lane];
        float oy = acc.y * r + b2[2 * lane + 1];
        t = ox * Wp[2 * lane] + oy * Wp[2 * lane + 1];
    }
    t = bsum(t);
    if (lane == 0) out[d] = 1.f / (1.f + __expf(-t - bp[0]));
}

// ---------------- launch ----------------
extern "C" void kernel_launch(void* const* d_in, const int* in_sizes, int n_in,
                              void* d_out, int out_size) {
    const float* x   = (const float*)d_in[0];
    const void*  ei  = d_in[1];
    const float* W1  = (const float*)d_in[2];
    const float* as1 = (const float*)d_in[3];
    const float* ad1 = (const float*)d_in[4];
    const float* b1  = (const float*)d_in[5];
    const float* W2  = (const float*)d_in[6];
    const float* as2 = (const float*)d_in[7];
    const float* ad2 = (const float*)d_in[8];
    const float* b2  = (const float*)d_in[9];
    const float* Wp  = (const float*)d_in[10];
    const float* bp  = (const float*)d_in[11];
    float* out = (float*)d_out;

    const int nodeWarpBlocks = (NN * 32 + 255) / 256;   // warp per node
    const int cvtBlocks = (PADN * INCH / 4 + 255) / 256;

    k_detect<<<1, 256>>>((const int*)ei);
    k_zerodeg<<<(NN + 255) / 256, 256>>>();
    k_conv<<<(ET + 255) / 256, 256>>>(ei);
    k_cvt<<<cvtBlocks, 256>>>(x, W1);
    k_scan_a<<<NCHUNK, SCAN_CHUNK>>>();
    k_scan_b<<<1, 64>>>();
    k_scan_c<<<NCHUNK, SCAN_CHUNK>>>();
    k_scatter<<<(ET + 255) / 256, 256>>>();
    k_gemm1<<<PADN / 64, 256>>>(as1, ad1);
    k_fagg1<<<nodeWarpBlocks, 256>>>();
    k_gemm2<<<NN / 8, 256>>>(W2, b1, as2, ad2);
    k_fagg2<<<nodeWarpBlocks, 256>>>(b2, Wp, bp, out);
}

// round 12
// speedup vs baseline: 3.2482x; 1.1615x over previous
#include <cuda_runtime.h>
#include <cuda_bf16.h>
#include <cuda_fp16.h>
#include <mma.h>
using namespace nvcuda;

#define NN     50000
#define PADN   50048          // 64-row padded for wmma tiles
#define ER     1600000
#define ET     1650000        // edges + self loops
#define INCH   128
#define J1     96             // HEADS*HID
#define HEADS  3
#define HID    32
#define OC     32
#define NEG    0.2f

#define NW1    24             // h1 fp8x4 words per node (96 ch)
#define NW2    8              // h2 fp8x4 words per node (32 ch)

#define SCAN_CHUNK 1024
#define NCHUNK ((NN + SCAN_CHUNK - 1) / SCAN_CHUNK)   // 49

// ---------------- scratch (device globals; no allocation allowed) ----------------
__device__ int   g_fmt;                       // 0 = int64 edge buffer, 1 = int32
__device__ __align__(16) int           g_src [ET];
__device__ __align__(16) int           g_dst [ET];
__device__ __align__(16) int           g_deg [NN];
__device__ __align__(16) int           g_off [NN + 1];
__device__ __align__(16) int           g_cur [NN];
__device__ __align__(16) int           g_csum[NCHUNK];
__device__ __align__(16) int           g_csrc[ET];        // CSR: src ids sorted by dst
__device__ __align__(16) __nv_bfloat16 g_W1b [INCH * J1]; // W1 in bf16
__device__ __align__(16) unsigned      g_h1b [NN * NW1];  // h1 packed fp8x4 (e4m3)
__device__ __align__(16) float         g_as1 [NN * 4];    // padded float4 (3 heads)
__device__ __align__(16) float         g_ad1 [NN * 4];
__device__ __align__(16) float         g_o1  [NN * J1];
__device__ __align__(16) unsigned      g_h2b [NN * NW2];  // h2 packed fp8x4 (e4m3)
__device__ __align__(16) float         g_as2 [NN];
__device__ __align__(16) float         g_ad2 [NN];

// ---------------- helpers ----------------
__device__ __forceinline__ float bsum(float v) {
    v += __shfl_xor_sync(0xffffffffu, v, 16);
    v += __shfl_xor_sync(0xffffffffu, v, 8);
    v += __shfl_xor_sync(0xffffffffu, v, 4);
    v += __shfl_xor_sync(0xffffffffu, v, 2);
    v += __shfl_xor_sync(0xffffffffu, v, 1);
    return v;
}
__device__ __forceinline__ int clampi(int v) {
    return v < 0 ? 0 : (v >= NN ? NN - 1 : v);
}
__device__ __forceinline__ float lrelu_exp(float v) {
    v = v > 0.f ? v : NEG * v;
    return __expf(v);
}
__device__ __forceinline__ unsigned packbf(float a, float b) {
    __nv_bfloat162 t = __floats2bfloat162_rn(a, b);
    return *(unsigned*)&t;
}
// pack 4 floats (c0 lowest byte) into e4m3x4
__device__ __forceinline__ unsigned pack4_fp8(float c0, float c1, float c2, float c3) {
    unsigned short lo, hi;
    asm("cvt.rn.satfinite.e4m3x2.f32 %0, %1, %2;" : "=h"(lo) : "f"(c1), "f"(c0));
    asm("cvt.rn.satfinite.e4m3x2.f32 %0, %1, %2;" : "=h"(hi) : "f"(c3), "f"(c2));
    return ((unsigned)hi << 16) | (unsigned)lo;
}
__device__ __forceinline__ float4 unpack4_fp8(unsigned u) {
    unsigned h0, h1;
    unsigned short lo = (unsigned short)(u & 0xffffu), hi = (unsigned short)(u >> 16);
    asm("cvt.rn.f16x2.e4m3x2 %0, %1;" : "=r"(h0) : "h"(lo));
    asm("cvt.rn.f16x2.e4m3x2 %0, %1;" : "=r"(h1) : "h"(hi));
    __half2 a = *(__half2*)&h0, b = *(__half2*)&h1;
    float2 fa = __half22float2(a), fb = __half22float2(b);
    return make_float4(fa.x, fa.y, fb.x, fb.y);
}

// ---------------- kernels ----------------
// init: zero degrees; block 0 additionally detects int64 vs int32 edge buffer.
__global__ void k_init(const int* __restrict__ ei32) {
    int i = blockIdx.x * blockDim.x + threadIdx.x;
    if (i < NN) g_deg[i] = 0;
    if (blockIdx.x == 0) {
        __shared__ int nz;
        if (threadIdx.x == 0) nz = 0;
        __syncthreads();
        for (int k = threadIdx.x; k < 2048; k += blockDim.x)
            if (ei32[2 * k * 391 + 1] != 0) atomicOr(&nz, 1);
        __syncthreads();
        if (threadIdx.x == 0) g_fmt = nz ? 1 : 0;
    }
}

// convert edge list + histogram of dst degrees
__global__ void k_conv(const void* __restrict__ eiv) {
    int e = blockIdx.x * blockDim.x + threadIdx.x;
    if (e >= ET) return;
    int s, d;
    if (e < ER) {
        if (g_fmt == 0) {
            const long long* ei = (const long long*)eiv;
            s = (int)ei[e]; d = (int)ei[ER + e];
        } else {
            const int* ei = (const int*)eiv;
            s = ei[e]; d = ei[ER + e];
        }
        s = clampi(s); d = clampi(d);
    } else {
        s = e - ER; d = s;
    }
    g_src[e] = s;
    g_dst[e] = d;
    atomicAdd(&g_deg[d], 1);
}

// convert W1 to bf16
__global__ void k_cvtW(const float* __restrict__ W1) {
    int i4 = blockIdx.x * blockDim.x + threadIdx.x;
    int i = i4 * 4;
    if (i < INCH * J1) {
        float4 w = *(const float4*)&W1[i];
        *(uint2*)&g_W1b[i] = make_uint2(packbf(w.x, w.y), packbf(w.z, w.w));
    }
}

// ---- two-level exclusive scan of g_deg -> g_off ----
__global__ void k_scan_a() {
    __shared__ int warpsums[32];
    int tid = threadIdx.x, lane = tid & 31, wid = tid >> 5;
    int i = blockIdx.x * SCAN_CHUNK + tid;
    int v = (i < NN) ? g_deg[i] : 0;
    int x = v;
    #pragma unroll
    for (int o = 1; o < 32; o <<= 1) {
        int y = __shfl_up_sync(0xffffffffu, x, o);
        if (lane >= o) x += y;
    }
    if (lane == 31) warpsums[wid] = x;
    __syncthreads();
    if (wid == 0) {
        int sv = warpsums[lane];
        #pragma unroll
        for (int o = 1; o < 32; o <<= 1) {
            int y = __shfl_up_sync(0xffffffffu, sv, o);
            if (lane >= o) sv += y;
        }
        warpsums[lane] = sv;
    }
    __syncthreads();
    int incl = x + (wid > 0 ? warpsums[wid - 1] : 0);
    if (i < NN) g_off[i] = incl - v;
    if (tid == SCAN_CHUNK - 1) g_csum[blockIdx.x] = incl;
}

__global__ void k_scan_b() {
    __shared__ int sh[NCHUNK];
    int tid = threadIdx.x;
    if (tid < NCHUNK) sh[tid] = g_csum[tid];
    __syncthreads();
    if (tid == 0) {
        int run = 0;
        #pragma unroll
        for (int c = 0; c < NCHUNK; c++) { int t = sh[c]; sh[c] = run; run += t; }
        g_off[NN] = run;
    }
    __syncthreads();
    if (tid < NCHUNK) g_csum[tid] = sh[tid];
}

__global__ void k_scan_c() {
    int i = blockIdx.x * SCAN_CHUNK + threadIdx.x;
    if (i >= NN) return;
    int o = g_off[i] + g_csum[blockIdx.x];
    g_off[i] = o;
    g_cur[i] = o;
}

__global__ void k_scatter() {
    int e = blockIdx.x * blockDim.x + threadIdx.x;
    if (e >= ET) return;
    int d = g_dst[e];
    int pos = atomicAdd(&g_cur[d], 1);
    g_csrc[pos] = g_src[e];
}

// h1 = x @ W1 via wmma bf16; x converted fp32->bf16 in-kernel (smem stage).
// Block 256 thr / 8 warps, tile M=64 x N=96. Warp: m-stripe wid>>1, n-half (wid&1)*3.
__global__ void k_gemm1(const float* __restrict__ x,
                        const float* __restrict__ aS, const float* __restrict__ aD) {
    __shared__ __nv_bfloat16 Ash[64][136];   // padded (272B rows) for ldmatrix
    __shared__ float Csh[64][96];
    int tid = threadIdx.x;
    int wid = tid >> 5, tx = tid & 31;
    int base = blockIdx.x * 64;

    // stage A: 64 rows x 128 cols fp32 -> bf16, 8 float4 per thread
    #pragma unroll
    for (int i = 0; i < 8; i++) {
        int idx4 = tid + 256 * i;                // 2048 float4s
        int row = idx4 >> 5, c4 = (idx4 & 31) * 4;
        int gr = base + row;
        float4 v = (gr < NN) ? *(const float4*)&x[gr * INCH + c4]
                             : make_float4(0.f, 0.f, 0.f, 0.f);
        *(uint2*)&Ash[row][c4] = make_uint2(packbf(v.x, v.y), packbf(v.z, v.w));
    }
    __syncthreads();

    int mt  = wid >> 1;
    int nt0 = (wid & 1) * 3;
    wmma::fragment<wmma::matrix_a, 16, 16, 16, __nv_bfloat16, wmma::row_major> fa;
    wmma::fragment<wmma::matrix_b, 16, 16, 16, __nv_bfloat16, wmma::row_major> fb;
    wmma::fragment<wmma::accumulator, 16, 16, 16, float> fc[3];
    #pragma unroll
    for (int t = 0; t < 3; t++) wmma::fill_fragment(fc[t], 0.f);
    #pragma unroll
    for (int k0 = 0; k0 < INCH; k0 += 16) {
        wmma::load_matrix_sync(fa, &Ash[mt * 16][k0], 136);
        #pragma unroll
        for (int t = 0; t < 3; t++) {
            wmma::load_matrix_sync(fb, g_W1b + k0 * J1 + (nt0 + t) * 16, J1);
            wmma::mma_sync(fc[t], fa, fb, fc[t]);
        }
    }
    #pragma unroll
    for (int t = 0; t < 3; t++)
        wmma::store_matrix_sync(&Csh[mt * 16][(nt0 + t) * 16], fc[t], J1, wmma::mem_row_major);
    __syncthreads();

    // epilogue: warp wid -> rows wid*8..+7; fp8 pack + attention dots
    float aSv[3], aDv[3];
    #pragma unroll
    for (int c = 0; c < 3; c++) { aSv[c] = aS[c * 32 + tx]; aDv[c] = aD[c * 32 + tx]; }
    #pragma unroll
    for (int i = 0; i < 8; i++) {
        int lrow = wid * 8 + i;
        int row = base + lrow;
        if (row >= NN) continue;            // warp-uniform
        #pragma unroll
        for (int c = 0; c < 3; c++) {
            float v0 = Csh[lrow][c * 32 + tx];
            float v1 = __shfl_down_sync(0xffffffffu, v0, 1);
            float v2 = __shfl_down_sync(0xffffffffu, v0, 2);
            float v3 = __shfl_down_sync(0xffffffffu, v0, 3);
            if (!(tx & 3))
                g_h1b[row * NW1 + c * 8 + (tx >> 2)] = pack4_fp8(v0, v1, v2, v3);
            float vs = bsum(v0 * aSv[c]);
            float vd = bsum(v0 * aDv[c]);
            if (tx == 0) { g_as1[row * 4 + c] = vs; g_ad1[row * 4 + c] = vd; }
        }
    }
}

// Fused layer-1 softmax + aggregation. Warp per dst node; fp8 gathers:
// lane l<24 owns word l (channels 4l..4l+3), head = l>>3.
__global__ void k_fagg1() {
    int d = (int)((blockIdx.x * blockDim.x + threadIdx.x) >> 5);
    int lane = threadIdx.x & 31;
    if (d >= NN) return;
    int beg = g_off[d], end = g_off[d + 1];
    float4 adv = *(const float4*)&g_ad1[d * 4];
    float4 acc = {0.f, 0.f, 0.f, 0.f};
    float sp0 = 0.f, sp1 = 0.f, sp2 = 0.f;
    for (int j = beg; j < end; j += 32) {
        int n = end - j; if (n > 32) n = 32;
        int s = 0; float p0 = 0.f, p1 = 0.f, p2 = 0.f;
        if (lane < n) {
            s = g_csrc[j + lane];
            float4 a = *(const float4*)&g_as1[s * 4];
            p0 = lrelu_exp(a.x + adv.x);
            p1 = lrelu_exp(a.y + adv.y);
            p2 = lrelu_exp(a.z + adv.z);
            sp0 += p0; sp1 += p1; sp2 += p2;
        }
        for (int i = 0; i < n; i++) {
            int   si = __shfl_sync(0xffffffffu, s,  i);
            float q0 = __shfl_sync(0xffffffffu, p0, i);
            float q1 = __shfl_sync(0xffffffffu, p1, i);
            float q2 = __shfl_sync(0xffffffffu, p2, i);
            if (lane < 24) {
                float qh = (lane < 8) ? q0 : (lane < 16 ? q1 : q2);
                float4 v = unpack4_fp8(g_h1b[si * NW1 + lane]);
                acc.x += qh * v.x; acc.y += qh * v.y;
                acc.z += qh * v.z; acc.w += qh * v.w;
            }
        }
    }
    sp0 = bsum(sp0); sp1 = bsum(sp1); sp2 = bsum(sp2);
    float r0 = 1.f / (sp0 + 1e-16f);
    float r1 = 1.f / (sp1 + 1e-16f);
    float r2 = 1.f / (sp2 + 1e-16f);
    if (lane < 24) {
        float rh = (lane < 8) ? r0 : (lane < 16 ? r1 : r2);
        float4 o = { acc.x * rh, acc.y * rh, acc.z * rh, acc.w * rh };
        *(float4*)&g_o1[d * J1 + 4 * lane] = o;
    }
}

// h2 = elu(o1 + b1) @ W2 ; a_s2/a_d2; h2 stored fp8x4.
__global__ void k_gemm2(const float* __restrict__ W, const float* __restrict__ b1,
                        const float* __restrict__ aS, const float* __restrict__ aD) {
    __shared__ float Wsh[J1 * OC];
    __shared__ float Xsh[8 * J1];
    int tid = threadIdx.x;
    for (int i = tid; i < J1 * OC; i += 256) Wsh[i] = W[i];
    int r = tid >> 5, lane = tid & 31;
    float aws = aS[lane], awd = aD[lane];
    int base = blockIdx.x * 8;
    for (int i = tid; i < 8 * J1; i += 256) {
        int rr = i / J1, k = i - rr * J1;
        float v = g_o1[(base + rr) * J1 + k] + b1[k];
        v = v > 0.f ? v : (__expf(v) - 1.f);
        Xsh[i] = v;
    }
    __syncthreads();
    int row = base + r;
    float acc = 0.f;
    #pragma unroll 16
    for (int k = 0; k < J1; k++) acc += Xsh[r * J1 + k] * Wsh[k * OC + lane];
    float v1 = __shfl_down_sync(0xffffffffu, acc, 1);
    float v2 = __shfl_down_sync(0xffffffffu, acc, 2);
    float v3 = __shfl_down_sync(0xffffffffu, acc, 3);
    if (!(lane & 3)) g_h2b[row * NW2 + (lane >> 2)] = pack4_fp8(acc, v1, v2, v3);
    float vs = bsum(acc * aws);
    float vd = bsum(acc * awd);
    if (lane == 0) { g_as2[row] = vs; g_ad2[row] = vd; }
}

// Fused layer-2: softmax + aggregation + bias + project + sigmoid.
// Warp per node; 4 edges per inner iteration (8 lanes / edge, fp8 words).
__global__ void k_fagg2(const float* __restrict__ b2, const float* __restrict__ Wp,
                        const float* __restrict__ bp, float* __restrict__ out) {
    int d = (int)((blockIdx.x * blockDim.x + threadIdx.x) >> 5);
    int lane = threadIdx.x & 31;
    if (d >= NN) return;
    int sub = lane >> 3, l8 = lane & 7;
    int beg = g_off[d], end = g_off[d + 1];
    float adv = g_ad2[d];
    float4 acc = {0.f, 0.f, 0.f, 0.f};
    float sp = 0.f;
    for (int j = beg; j < end; j += 32) {
        int n = end - j; if (n > 32) n = 32;
        int s = 0; float p = 0.f;
        if (lane < n) {
            s = g_csrc[j + lane];
            p = lrelu_exp(g_as2[s] + adv);
            sp += p;
        }
        for (int i = 0; i < n; i += 4) {
            int e2 = i + sub;
            int   si = __shfl_sync(0xffffffffu, s, e2 & 31);
            float q  = __shfl_sync(0xffffffffu, p, e2 & 31);
            if (e2 < n) {
                float4 v = unpack4_fp8(g_h2b[si * NW2 + l8]);
                acc.x += q * v.x; acc.y += q * v.y;
                acc.z += q * v.z; acc.w += q * v.w;
            }
        }
    }
    sp = bsum(sp);
    // combine the 4 sub-accumulators (lanes with equal l8)
    #pragma unroll
    for (int o = 8; o <= 16; o <<= 1) {
        acc.x += __shfl_xor_sync(0xffffffffu, acc.x, o);
        acc.y += __shfl_xor_sync(0xffffffffu, acc.y, o);
        acc.z += __shfl_xor_sync(0xffffffffu, acc.z, o);
        acc.w += __shfl_xor_sync(0xffffffffu, acc.w, o);
    }
    float r = 1.f / (sp + 1e-16f);
    float t = 0.f;
    if (sub == 0) {
        float o0 = acc.x * r + b2[4 * l8 + 0];
        float o1 = acc.y * r + b2[4 * l8 + 1];
        float o2 = acc.z * r + b2[4 * l8 + 2];
        float o3 = acc.w * r + b2[4 * l8 + 3];
        t = o0 * Wp[4 * l8 + 0] + o1 * Wp[4 * l8 + 1]
          + o2 * Wp[4 * l8 + 2] + o3 * Wp[4 * l8 + 3];
    }
    t = bsum(t);
    if (lane == 0) out[d] = 1.f / (1.f + __expf(-t - bp[0]));
}

// ---------------- launch ----------------
extern "C" void kernel_launch(void* const* d_in, const int* in_sizes, int n_in,
                              void* d_out, int out_size) {
    const float* x   = (const float*)d_in[0];
    const void*  ei  = d_in[1];
    const float* W1  = (const float*)d_in[2];
    const float* as1 = (const float*)d_in[3];
    const float* ad1 = (const float*)d_in[4];
    const float* b1  = (const float*)d_in[5];
    const float* W2  = (const float*)d_in[6];
    const float* as2 = (const float*)d_in[7];
    const float* ad2 = (const float*)d_in[8];
    const float* b2  = (const float*)d_in[9];
    const float* Wp  = (const float*)d_in[10];
    const float* bp  = (const float*)d_in[11];
    float* out = (float*)d_out;

    const int nodeWarpBlocks = (NN * 32 + 255) / 256;   // warp per node

    k_init<<<(NN + 255) / 256, 256>>>((const int*)ei);
    k_conv<<<(ET + 255) / 256, 256>>>(ei);
    k_cvtW<<<(INCH * J1 / 4 + 255) / 256, 256>>>(W1);
    k_scan_a<<<NCHUNK, SCAN_CHUNK>>>();
    k_scan_b<<<1, 64>>>();
    k_scan_c<<<NCHUNK, SCAN_CHUNK>>>();
    k_scatter<<<(ET + 255) / 256, 256>>>();
    k_gemm1<<<PADN / 64, 256>>>(x, as1, ad1);
    k_fagg1<<<nodeWarpBlocks, 256>>>();
    k_gemm2<<<NN / 8, 256>>>(W2, b1, as2, ad2);
    k_fagg2<<<nodeWarpBlocks, 256>>>(b2, Wp, bp, out);
}

// round 13
// speedup vs baseline: 3.9849x; 1.2268x over previous
#include <cuda_runtime.h>
#include <cuda_bf16.h>
#include <cuda_fp16.h>
#include <mma.h>
using namespace nvcuda;

#define NN     50000
#define PADN   50048          // 64-row padded for wmma tiles
#define ER     1600000
#define ET     1650000        // edges + self loops
#define INCH   128
#define J1     96             // HEADS*HID
#define HEADS  3
#define HID    32
#define OC     32
#define NEG    0.2f

#define NW1    24             // h1 fp8x4 words per node (96 ch)
#define NW2    8              // h2 fp8x4 words per node (32 ch)

#define SCAN_CHUNK 1024
#define NCHUNK ((NN + SCAN_CHUNK - 1) / SCAN_CHUNK)   // 49

// ---------------- scratch (device globals; no allocation allowed) ----------------
__device__ int   g_fmt;                       // 0 = int64 edge buffer, 1 = int32
__device__ __align__(16) int           g_src [ET];
__device__ __align__(16) int           g_dst [ET];
__device__ __align__(16) int           g_deg [NN];
__device__ __align__(16) int           g_off [NN + 1];
__device__ __align__(16) int           g_cur [NN];
__device__ __align__(16) int           g_csum[NCHUNK];
__device__ __align__(16) int           g_csrc[ET];        // CSR: src ids sorted by dst
__device__ __align__(16) __nv_bfloat16 g_W1b [INCH * J1]; // W1 in bf16
__device__ __align__(16) __nv_bfloat16 g_W2b [J1 * OC];   // W2 in bf16
__device__ __align__(16) unsigned      g_h1b [NN * NW1];  // h1 packed fp8x4 (e4m3)
__device__ __align__(16) float         g_as1 [NN * 4];    // padded float4 (3 heads)
__device__ __align__(16) float         g_ad1 [NN * 4];
__device__ __align__(16) float         g_o1  [NN * J1];
__device__ __align__(16) unsigned      g_h2b [NN * NW2];  // h2 packed fp8x4 (e4m3)
__device__ __align__(16) float         g_as2 [NN];
__device__ __align__(16) float         g_ad2 [NN];

// ---------------- helpers ----------------
__device__ __forceinline__ float bsum(float v) {
    v += __shfl_xor_sync(0xffffffffu, v, 16);
    v += __shfl_xor_sync(0xffffffffu, v, 8);
    v += __shfl_xor_sync(0xffffffffu, v, 4);
    v += __shfl_xor_sync(0xffffffffu, v, 2);
    v += __shfl_xor_sync(0xffffffffu, v, 1);
    return v;
}
__device__ __forceinline__ int clampi(int v) {
    return v < 0 ? 0 : (v >= NN ? NN - 1 : v);
}
__device__ __forceinline__ float lrelu_exp(float v) {
    v = v > 0.f ? v : NEG * v;
    return __expf(v);
}
__device__ __forceinline__ unsigned packbf(float a, float b) {
    __nv_bfloat162 t = __floats2bfloat162_rn(a, b);
    return *(unsigned*)&t;
}
__device__ __forceinline__ unsigned pack4_fp8(float c0, float c1, float c2, float c3) {
    unsigned short lo, hi;
    asm("cvt.rn.satfinite.e4m3x2.f32 %0, %1, %2;" : "=h"(lo) : "f"(c1), "f"(c0));
    asm("cvt.rn.satfinite.e4m3x2.f32 %0, %1, %2;" : "=h"(hi) : "f"(c3), "f"(c2));
    return ((unsigned)hi << 16) | (unsigned)lo;
}
__device__ __forceinline__ float4 unpack4_fp8(unsigned u) {
    unsigned h0, h1;
    unsigned short lo = (unsigned short)(u & 0xffffu), hi = (unsigned short)(u >> 16);
    asm("cvt.rn.f16x2.e4m3x2 %0, %1;" : "=r"(h0) : "h"(lo));
    asm("cvt.rn.f16x2.e4m3x2 %0, %1;" : "=r"(h1) : "h"(hi));
    __half2 a = *(__half2*)&h0, b = *(__half2*)&h1;
    float2 fa = __half22float2(a), fb = __half22float2(b);
    return make_float4(fa.x, fa.y, fb.x, fb.y);
}

// ---------------- kernels ----------------
__global__ void k_init(const int* __restrict__ ei32) {
    int i = blockIdx.x * blockDim.x + threadIdx.x;
    if (i < NN) g_deg[i] = 0;
    if (blockIdx.x == 0) {
        __shared__ int nz;
        if (threadIdx.x == 0) nz = 0;
        __syncthreads();
        for (int k = threadIdx.x; k < 2048; k += blockDim.x)
            if (ei32[2 * k * 391 + 1] != 0) atomicOr(&nz, 1);
        __syncthreads();
        if (threadIdx.x == 0) g_fmt = nz ? 1 : 0;
    }
}

__global__ void k_conv(const void* __restrict__ eiv) {
    int e = blockIdx.x * blockDim.x + threadIdx.x;
    if (e >= ET) return;
    int s, d;
    if (e < ER) {
        if (g_fmt == 0) {
            const long long* ei = (const long long*)eiv;
            s = (int)ei[e]; d = (int)ei[ER + e];
        } else {
            const int* ei = (const int*)eiv;
            s = ei[e]; d = ei[ER + e];
        }
        s = clampi(s); d = clampi(d);
    } else {
        s = e - ER; d = s;
    }
    g_src[e] = s;
    g_dst[e] = d;
    atomicAdd(&g_deg[d], 1);
}

// convert W1 and W2 to bf16
__global__ void k_cvtW(const float* __restrict__ W1, const float* __restrict__ W2) {
    int i4 = blockIdx.x * blockDim.x + threadIdx.x;
    int i = i4 * 4;
    if (i < INCH * J1) {
        float4 w = *(const float4*)&W1[i];
        *(uint2*)&g_W1b[i] = make_uint2(packbf(w.x, w.y), packbf(w.z, w.w));
    }
    if (i < J1 * OC) {
        float4 w = *(const float4*)&W2[i];
        *(uint2*)&g_W2b[i] = make_uint2(packbf(w.x, w.y), packbf(w.z, w.w));
    }
}

// ---- two-level exclusive scan of g_deg -> g_off ----
__global__ void k_scan_a() {
    __shared__ int warpsums[32];
    int tid = threadIdx.x, lane = tid & 31, wid = tid >> 5;
    int i = blockIdx.x * SCAN_CHUNK + tid;
    int v = (i < NN) ? g_deg[i] : 0;
    int x = v;
    #pragma unroll
    for (int o = 1; o < 32; o <<= 1) {
        int y = __shfl_up_sync(0xffffffffu, x, o);
        if (lane >= o) x += y;
    }
    if (lane == 31) warpsums[wid] = x;
    __syncthreads();
    if (wid == 0) {
        int sv = warpsums[lane];
        #pragma unroll
        for (int o = 1; o < 32; o <<= 1) {
            int y = __shfl_up_sync(0xffffffffu, sv, o);
            if (lane >= o) sv += y;
        }
        warpsums[lane] = sv;
    }
    __syncthreads();
    int incl = x + (wid > 0 ? warpsums[wid - 1] : 0);
    if (i < NN) g_off[i] = incl - v;
    if (tid == SCAN_CHUNK - 1) g_csum[blockIdx.x] = incl;
}

__global__ void k_scan_b() {
    __shared__ int sh[NCHUNK];
    int tid = threadIdx.x;
    if (tid < NCHUNK) sh[tid] = g_csum[tid];
    __syncthreads();
    if (tid == 0) {
        int run = 0;
        #pragma unroll
        for (int c = 0; c < NCHUNK; c++) { int t = sh[c]; sh[c] = run; run += t; }
        g_off[NN] = run;
    }
    __syncthreads();
    if (tid < NCHUNK) g_csum[tid] = sh[tid];
}

__global__ void k_scan_c() {
    int i = blockIdx.x * SCAN_CHUNK + threadIdx.x;
    if (i >= NN) return;
    int o = g_off[i] + g_csum[blockIdx.x];
    g_off[i] = o;
    g_cur[i] = o;
}

__global__ void k_scatter() {
    int e = blockIdx.x * blockDim.x + threadIdx.x;
    if (e >= ET) return;
    int d = g_dst[e];
    int pos = atomicAdd(&g_cur[d], 1);
    g_csrc[pos] = g_src[e];
}

// h1 = x @ W1 via wmma bf16; x converted fp32->bf16 in-kernel (smem stage).
__global__ void k_gemm1(const float* __restrict__ x,
                        const float* __restrict__ aS, const float* __restrict__ aD) {
    __shared__ __nv_bfloat16 Ash[64][136];
    __shared__ float Csh[64][96];
    int tid = threadIdx.x;
    int wid = tid >> 5, tx = tid & 31;
    int base = blockIdx.x * 64;

    #pragma unroll
    for (int i = 0; i < 8; i++) {
        int idx4 = tid + 256 * i;
        int row = idx4 >> 5, c4 = (idx4 & 31) * 4;
        int gr = base + row;
        float4 v = (gr < NN) ? *(const float4*)&x[gr * INCH + c4]
                             : make_float4(0.f, 0.f, 0.f, 0.f);
        *(uint2*)&Ash[row][c4] = make_uint2(packbf(v.x, v.y), packbf(v.z, v.w));
    }
    __syncthreads();

    int mt  = wid >> 1;
    int nt0 = (wid & 1) * 3;
    wmma::fragment<wmma::matrix_a, 16, 16, 16, __nv_bfloat16, wmma::row_major> fa;
    wmma::fragment<wmma::matrix_b, 16, 16, 16, __nv_bfloat16, wmma::row_major> fb;
    wmma::fragment<wmma::accumulator, 16, 16, 16, float> fc[3];
    #pragma unroll
    for (int t = 0; t < 3; t++) wmma::fill_fragment(fc[t], 0.f);
    #pragma unroll
    for (int k0 = 0; k0 < INCH; k0 += 16) {
        wmma::load_matrix_sync(fa, &Ash[mt * 16][k0], 136);
        #pragma unroll
        for (int t = 0; t < 3; t++) {
            wmma::load_matrix_sync(fb, g_W1b + k0 * J1 + (nt0 + t) * 16, J1);
            wmma::mma_sync(fc[t], fa, fb, fc[t]);
        }
    }
    #pragma unroll
    for (int t = 0; t < 3; t++)
        wmma::store_matrix_sync(&Csh[mt * 16][(nt0 + t) * 16], fc[t], J1, wmma::mem_row_major);
    __syncthreads();

    float aSv[3], aDv[3];
    #pragma unroll
    for (int c = 0; c < 3; c++) { aSv[c] = aS[c * 32 + tx]; aDv[c] = aD[c * 32 + tx]; }
    #pragma unroll
    for (int i = 0; i < 8; i++) {
        int lrow = wid * 8 + i;
        int row = base + lrow;
        if (row >= NN) continue;            // warp-uniform
        #pragma unroll
        for (int c = 0; c < 3; c++) {
            float v0 = Csh[lrow][c * 32 + tx];
            float v1 = __shfl_down_sync(0xffffffffu, v0, 1);
            float v2 = __shfl_down_sync(0xffffffffu, v0, 2);
            float v3 = __shfl_down_sync(0xffffffffu, v0, 3);
            if (!(tx & 3))
                g_h1b[row * NW1 + c * 8 + (tx >> 2)] = pack4_fp8(v0, v1, v2, v3);
            float vs = bsum(v0 * aSv[c]);
            float vd = bsum(v0 * aDv[c]);
            if (tx == 0) { g_as1[row * 4 + c] = vs; g_ad1[row * 4 + c] = vd; }
        }
    }
}

// Fused layer-1 softmax + aggregation. Warp per dst node.
// 4 edges per inner iteration: subgroup sub (8 lanes) handles one edge;
// lane owns words l8 (head0), l8+8 (head1), l8+16 (head2).
__global__ void k_fagg1() {
    int d = (int)((blockIdx.x * blockDim.x + threadIdx.x) >> 5);
    int lane = threadIdx.x & 31;
    if (d >= NN) return;
    int sub = lane >> 3, l8 = lane & 7;
    int beg = g_off[d], end = g_off[d + 1];
    float4 adv = *(const float4*)&g_ad1[d * 4];
    float4 a0 = {0.f,0.f,0.f,0.f}, a1 = {0.f,0.f,0.f,0.f}, a2 = {0.f,0.f,0.f,0.f};
    float sp0 = 0.f, sp1 = 0.f, sp2 = 0.f;
    for (int j = beg; j < end; j += 32) {
        int n = end - j; if (n > 32) n = 32;
        int s = 0; float p0 = 0.f, p1 = 0.f, p2 = 0.f;
        if (lane < n) {
            s = g_csrc[j + lane];
            float4 a = *(const float4*)&g_as1[s * 4];
            p0 = lrelu_exp(a.x + adv.x);
            p1 = lrelu_exp(a.y + adv.y);
            p2 = lrelu_exp(a.z + adv.z);
            sp0 += p0; sp1 += p1; sp2 += p2;
        }
        for (int i = 0; i < n; i += 4) {
            int e2 = (i + sub) & 31;
            int   si = __shfl_sync(0xffffffffu, s,  e2);
            float q0 = __shfl_sync(0xffffffffu, p0, e2);
            float q1 = __shfl_sync(0xffffffffu, p1, e2);
            float q2 = __shfl_sync(0xffffffffu, p2, e2);
            if (i + sub < n) {
                const unsigned* hw = &g_h1b[si * NW1 + l8];
                float4 v0 = unpack4_fp8(hw[0]);
                float4 v1 = unpack4_fp8(hw[8]);
                float4 v2 = unpack4_fp8(hw[16]);
                a0.x += q0 * v0.x; a0.y += q0 * v0.y; a0.z += q0 * v0.z; a0.w += q0 * v0.w;
                a1.x += q1 * v1.x; a1.y += q1 * v1.y; a1.z += q1 * v1.z; a1.w += q1 * v1.w;
                a2.x += q2 * v2.x; a2.y += q2 * v2.y; a2.z += q2 * v2.z; a2.w += q2 * v2.w;
            }
        }
    }
    // combine 4 subgroup accumulators (lanes with equal l8)
    #pragma unroll
    for (int o = 8; o <= 16; o <<= 1) {
        a0.x += __shfl_xor_sync(0xffffffffu, a0.x, o); a0.y += __shfl_xor_sync(0xffffffffu, a0.y, o);
        a0.z += __shfl_xor_sync(0xffffffffu, a0.z, o); a0.w += __shfl_xor_sync(0xffffffffu, a0.w, o);
        a1.x += __shfl_xor_sync(0xffffffffu, a1.x, o); a1.y += __shfl_xor_sync(0xffffffffu, a1.y, o);
        a1.z += __shfl_xor_sync(0xffffffffu, a1.z, o); a1.w += __shfl_xor_sync(0xffffffffu, a1.w, o);
        a2.x += __shfl_xor_sync(0xffffffffu, a2.x, o); a2.y += __shfl_xor_sync(0xffffffffu, a2.y, o);
        a2.z += __shfl_xor_sync(0xffffffffu, a2.z, o); a2.w += __shfl_xor_sync(0xffffffffu, a2.w, o);
    }
    sp0 = bsum(sp0); sp1 = bsum(sp1); sp2 = bsum(sp2);
    float r0 = 1.f / (sp0 + 1e-16f);
    float r1 = 1.f / (sp1 + 1e-16f);
    float r2 = 1.f / (sp2 + 1e-16f);
    if (sub == 0) {
        float4 o0 = { a0.x * r0, a0.y * r0, a0.z * r0, a0.w * r0 };
        float4 o1v = { a1.x * r1, a1.y * r1, a1.z * r1, a1.w * r1 };
        float4 o2v = { a2.x * r2, a2.y * r2, a2.z * r2, a2.w * r2 };
        *(float4*)&g_o1[d * J1 + 4 * l8]        = o0;
        *(float4*)&g_o1[d * J1 + 4 * (l8 + 8)]  = o1v;
        *(float4*)&g_o1[d * J1 + 4 * (l8 + 16)] = o2v;
    }
}

// h2 = elu(o1 + b1) @ W2 via wmma bf16; a_s2/a_d2; h2 stored fp8x4.
// Block 256 thr / 8 warps, M-tile 64, N=32. Warp: mt = wid>>1, nt = wid&1.
__global__ void k_gemm2(const float* __restrict__ b1,
                        const float* __restrict__ aS, const float* __restrict__ aD) {
    __shared__ __nv_bfloat16 Xb[64][104];   // ELU(o1+b1) in bf16, padded
    __shared__ float Csh[64][32];
    int tid = threadIdx.x;
    int wid = tid >> 5, tx = tid & 31;
    int base = blockIdx.x * 64;

    // stage: 64 rows x 96 cols, 6 float4 per thread
    #pragma unroll
    for (int i = 0; i < 6; i++) {
        int idx4 = tid + 256 * i;                 // 1536 float4s
        int row = idx4 / 24, c4 = (idx4 % 24) * 4;
        int gr = base + row;
        float4 v = (gr < NN) ? *(const float4*)&g_o1[gr * J1 + c4]
                             : make_float4(0.f, 0.f, 0.f, 0.f);
        float4 b = *(const float4*)&b1[c4];
        float e0 = v.x + b.x, e1 = v.y + b.y, e2 = v.z + b.z, e3 = v.w + b.w;
        e0 = e0 > 0.f ? e0 : (__expf(e0) - 1.f);
        e1 = e1 > 0.f ? e1 : (__expf(e1) - 1.f);
        e2 = e2 > 0.f ? e2 : (__expf(e2) - 1.f);
        e3 = e3 > 0.f ? e3 : (__expf(e3) - 1.f);
        *(uint2*)&Xb[row][c4] = make_uint2(packbf(e0, e1), packbf(e2, e3));
    }
    __syncthreads();

    int mt = wid >> 1, nt = wid & 1;
    wmma::fragment<wmma::matrix_a, 16, 16, 16, __nv_bfloat16, wmma::row_major> fa;
    wmma::fragment<wmma::matrix_b, 16, 16, 16, __nv_bfloat16, wmma::row_major> fb;
    wmma::fragment<wmma::accumulator, 16, 16, 16, float> fc;
    wmma::fill_fragment(fc, 0.f);
    #pragma unroll
    for (int k0 = 0; k0 < J1; k0 += 16) {
        wmma::load_matrix_sync(fa, &Xb[mt * 16][k0], 104);
        wmma::load_matrix_sync(fb, g_W2b + k0 * OC + nt * 16, OC);
        wmma::mma_sync(fc, fa, fb, fc);
    }
    wmma::store_matrix_sync(&Csh[mt * 16][nt * 16], fc, OC, wmma::mem_row_major);
    __syncthreads();

    float aws = aS[tx], awd = aD[tx];
    #pragma unroll
    for (int i = 0; i < 8; i++) {
        int lrow = wid * 8 + i;
        int row = base + lrow;
        if (row >= NN) continue;            // warp-uniform
        float v0 = Csh[lrow][tx];
        float v1 = __shfl_down_sync(0xffffffffu, v0, 1);
        float v2 = __shfl_down_sync(0xffffffffu, v0, 2);
        float v3 = __shfl_down_sync(0xffffffffu, v0, 3);
        if (!(tx & 3)) g_h2b[row * NW2 + (tx >> 2)] = pack4_fp8(v0, v1, v2, v3);
        float vs = bsum(v0 * aws);
        float vd = bsum(v0 * awd);
        if (tx == 0) { g_as2[row] = vs; g_ad2[row] = vd; }
    }
}

// Fused layer-2: softmax + aggregation + bias + project + sigmoid.
__global__ void k_fagg2(const float* __restrict__ b2, const float* __restrict__ Wp,
                        const float* __restrict__ bp, float* __restrict__ out) {
    int d = (int)((blockIdx.x * blockDim.x + threadIdx.x) >> 5);
    int lane = threadIdx.x & 31;
    if (d >= NN) return;
    int sub = lane >> 3, l8 = lane & 7;
    int beg = g_off[d], end = g_off[d + 1];
    float adv = g_ad2[d];
    float4 acc = {0.f, 0.f, 0.f, 0.f};
    float sp = 0.f;
    for (int j = beg; j < end; j += 32) {
        int n = end - j; if (n > 32) n = 32;
        int s = 0; float p = 0.f;
        if (lane < n) {
            s = g_csrc[j + lane];
            p = lrelu_exp(g_as2[s] + adv);
            sp += p;
        }
        for (int i = 0; i < n; i += 4) {
            int e2 = (i + sub) & 31;
            int   si = __shfl_sync(0xffffffffu, s, e2);
            float q  = __shfl_sync(0xffffffffu, p, e2);
            if (i + sub < n) {
                float4 v = unpack4_fp8(g_h2b[si * NW2 + l8]);
                acc.x += q * v.x; acc.y += q * v.y;
                acc.z += q * v.z; acc.w += q * v.w;
            }
        }
    }
    sp = bsum(sp);
    #pragma unroll
    for (int o = 8; o <= 16; o <<= 1) {
        acc.x += __shfl_xor_sync(0xffffffffu, acc.x, o);
        acc.y += __shfl_xor_sync(0xffffffffu, acc.y, o);
        acc.z += __shfl_xor_sync(0xffffffffu, acc.z, o);
        acc.w += __shfl_xor_sync(0xffffffffu, acc.w, o);
    }
    float r = 1.f / (sp + 1e-16f);
    float t = 0.f;
    if (sub == 0) {
        float o0 = acc.x * r + b2[4 * l8 + 0];
        float o1 = acc.y * r + b2[4 * l8 + 1];
        float o2 = acc.z * r + b2[4 * l8 + 2];
        float o3 = acc.w * r + b2[4 * l8 + 3];
        t = o0 * Wp[4 * l8 + 0] + o1 * Wp[4 * l8 + 1]
          + o2 * Wp[4 * l8 + 2] + o3 * Wp[4 * l8 + 3];
    }
    t = bsum(t);
    if (lane == 0) out[d] = 1.f / (1.f + __expf(-t - bp[0]));
}

// ---------------- launch ----------------
extern "C" void kernel_launch(void* const* d_in, const int* in_sizes, int n_in,
                              void* d_out, int out_size) {
    const float* x   = (const float*)d_in[0];
    const void*  ei  = d_in[1];
    const float* W1  = (const float*)d_in[2];
    const float* as1 = (const float*)d_in[3];
    const float* ad1 = (const float*)d_in[4];
    const float* b1  = (const float*)d_in[5];
    const float* W2  = (const float*)d_in[6];
    const float* as2 = (const float*)d_in[7];
    const float* ad2 = (const float*)d_in[8];
    const float* b2  = (const float*)d_in[9];
    const float* Wp  = (const float*)d_in[10];
    const float* bp  = (const float*)d_in[11];
    float* out = (float*)d_out;

    const int nodeWarpBlocks = (NN * 32 + 255) / 256;   // warp per node

    k_init<<<(NN + 255) / 256, 256>>>((const int*)ei);
    k_conv<<<(ET + 255) / 256, 256>>>(ei);
    k_cvtW<<<(INCH * J1 / 4 + 255) / 256, 256>>>(W1, W2);
    k_scan_a<<<NCHUNK, SCAN_CHUNK>>>();
    k_scan_b<<<1, 64>>>();
    k_scan_c<<<NCHUNK, SCAN_CHUNK>>>();
    k_scatter<<<(ET + 255) / 256, 256>>>();
    k_gemm1<<<PADN / 64, 256>>>(x, as1, ad1);
    k_fagg1<<<nodeWarpBlocks, 256>>>();
    k_gemm2<<<PADN / 64, 256>>>(b1, as2, ad2);
    k_fagg2<<<nodeWarpBlocks, 256>>>(b2, Wp, bp, out);
}

// round 14
// speedup vs baseline: 4.1227x; 1.0346x over previous
#include <cuda_runtime.h>
#include <cuda_bf16.h>
#include <cuda_fp16.h>
#include <mma.h>
using namespace nvcuda;

#define NN     50000
#define PADN   50048          // 64-row padded for wmma tiles
#define ER     1600000
#define ET     1650000        // edges + self loops
#define INCH   128
#define J1     96             // HEADS*HID
#define HEADS  3
#define HID    32
#define OC     32
#define NEG    0.2f

#define NW1    24             // h1 fp8x4 words per node (96 ch)
#define NW2    8              // h2 fp8x4 words per node (32 ch)
#define NO1    48             // o1 bf16x2 words per node (96 ch)

#define SCAN_CHUNK 1024
#define NCHUNK ((NN + SCAN_CHUNK - 1) / SCAN_CHUNK)   // 49

// ---------------- scratch (device globals; no allocation allowed) ----------------
__device__ int   g_fmt;                       // 0 = int64 edge buffer, 1 = int32
__device__ __align__(16) int           g_deg [NN];
__device__ __align__(16) int           g_off [NN + 1];
__device__ __align__(16) int           g_cur [NN];
__device__ __align__(16) int           g_csum[NCHUNK];
__device__ __align__(16) int           g_csrc[ET];        // CSR: src ids sorted by dst
__device__ __align__(16) __nv_bfloat16 g_W1b [INCH * J1]; // W1 in bf16
__device__ __align__(16) __nv_bfloat16 g_W2b [J1 * OC];   // W2 in bf16
__device__ __align__(16) unsigned      g_h1b [NN * NW1];  // h1 packed fp8x4 (e4m3)
__device__ __align__(16) float         g_as1 [NN * 4];    // padded float4 (3 heads)
__device__ __align__(16) float         g_ad1 [NN * 4];
__device__ __align__(16) unsigned      g_o1b [NN * NO1];  // o1 packed bf16x2
__device__ __align__(16) unsigned      g_h2b [NN * NW2];  // h2 packed fp8x4 (e4m3)
__device__ __align__(16) float         g_as2 [NN];
__device__ __align__(16) float         g_ad2 [NN];

// ---------------- helpers ----------------
__device__ __forceinline__ float bsum(float v) {
    v += __shfl_xor_sync(0xffffffffu, v, 16);
    v += __shfl_xor_sync(0xffffffffu, v, 8);
    v += __shfl_xor_sync(0xffffffffu, v, 4);
    v += __shfl_xor_sync(0xffffffffu, v, 2);
    v += __shfl_xor_sync(0xffffffffu, v, 1);
    return v;
}
__device__ __forceinline__ int clampi(int v) {
    return v < 0 ? 0 : (v >= NN ? NN - 1 : v);
}
__device__ __forceinline__ float lrelu_exp(float v) {
    v = v > 0.f ? v : NEG * v;
    return __expf(v);
}
__device__ __forceinline__ unsigned packbf(float a, float b) {
    __nv_bfloat162 t = __floats2bfloat162_rn(a, b);
    return *(unsigned*)&t;
}
__device__ __forceinline__ float2 unpackbf(unsigned u) {
    __nv_bfloat162 t = *(__nv_bfloat162*)&u;
    return __bfloat1622float2(t);
}
__device__ __forceinline__ unsigned pack4_fp8(float c0, float c1, float c2, float c3) {
    unsigned short lo, hi;
    asm("cvt.rn.satfinite.e4m3x2.f32 %0, %1, %2;" : "=h"(lo) : "f"(c1), "f"(c0));
    asm("cvt.rn.satfinite.e4m3x2.f32 %0, %1, %2;" : "=h"(hi) : "f"(c3), "f"(c2));
    return ((unsigned)hi << 16) | (unsigned)lo;
}
__device__ __forceinline__ float4 unpack4_fp8(unsigned u) {
    unsigned h0, h1;
    unsigned short lo = (unsigned short)(u & 0xffffu), hi = (unsigned short)(u >> 16);
    asm("cvt.rn.f16x2.e4m3x2 %0, %1;" : "=r"(h0) : "h"(lo));
    asm("cvt.rn.f16x2.e4m3x2 %0, %1;" : "=r"(h1) : "h"(hi));
    __half2 a = *(__half2*)&h0, b = *(__half2*)&h1;
    float2 fa = __half22float2(a), fb = __half22float2(b);
    return make_float4(fa.x, fa.y, fb.x, fb.y);
}

// ---------------- kernels ----------------
// init: zero degrees; detect edge dtype (block 0); convert W1/W2 to bf16.
__global__ void k_init(const int* __restrict__ ei32,
                       const float* __restrict__ W1, const float* __restrict__ W2) {
    int i = blockIdx.x * blockDim.x + threadIdx.x;
    if (i < NN) g_deg[i] = 0;
    int w = i * 4;
    if (w < INCH * J1) {
        float4 v = *(const float4*)&W1[w];
        *(uint2*)&g_W1b[w] = make_uint2(packbf(v.x, v.y), packbf(v.z, v.w));
    }
    if (w < J1 * OC) {
        float4 v = *(const float4*)&W2[w];
        *(uint2*)&g_W2b[w] = make_uint2(packbf(v.x, v.y), packbf(v.z, v.w));
    }
    if (blockIdx.x == 0) {
        __shared__ int nz;
        if (threadIdx.x == 0) nz = 0;
        __syncthreads();
        for (int k = threadIdx.x; k < 2048; k += blockDim.x)
            if (ei32[2 * k * 391 + 1] != 0) atomicOr(&nz, 1);
        __syncthreads();
        if (threadIdx.x == 0) g_fmt = nz ? 1 : 0;
    }
}

// histogram of dst degrees (reads ONLY the dst half of the raw edge buffer;
// self-loop +1 is folded into the scan)
__global__ void k_hist(const void* __restrict__ eiv) {
    int e = blockIdx.x * blockDim.x + threadIdx.x;
    if (e >= ER) return;
    int d;
    if (g_fmt == 0) d = (int)((const long long*)eiv)[ER + e];
    else            d = ((const int*)eiv)[ER + e];
    atomicAdd(&g_deg[clampi(d)], 1);
}

// ---- two-level exclusive scan of (g_deg + 1 self loop) -> g_off ----
__global__ void k_scan_a() {
    __shared__ int warpsums[32];
    int tid = threadIdx.x, lane = tid & 31, wid = tid >> 5;
    int i = blockIdx.x * SCAN_CHUNK + tid;
    int v = (i < NN) ? (g_deg[i] + 1) : 0;    // +1: self loop
    int x = v;
    #pragma unroll
    for (int o = 1; o < 32; o <<= 1) {
        int y = __shfl_up_sync(0xffffffffu, x, o);
        if (lane >= o) x += y;
    }
    if (lane == 31) warpsums[wid] = x;
    __syncthreads();
    if (wid == 0) {
        int sv = warpsums[lane];
        #pragma unroll
        for (int o = 1; o < 32; o <<= 1) {
            int y = __shfl_up_sync(0xffffffffu, sv, o);
            if (lane >= o) sv += y;
        }
        warpsums[lane] = sv;
    }
    __syncthreads();
    int incl = x + (wid > 0 ? warpsums[wid - 1] : 0);
    if (i < NN) g_off[i] = incl - v;
    if (tid == SCAN_CHUNK - 1) g_csum[blockIdx.x] = incl;
}

__global__ void k_scan_b() {
    __shared__ int sh[NCHUNK];
    int tid = threadIdx.x;
    if (tid < NCHUNK) sh[tid] = g_csum[tid];
    __syncthreads();
    if (tid == 0) {
        int run = 0;
        #pragma unroll
        for (int c = 0; c < NCHUNK; c++) { int t = sh[c]; sh[c] = run; run += t; }
        g_off[NN] = run;
    }
    __syncthreads();
    if (tid < NCHUNK) g_csum[tid] = sh[tid];
}

__global__ void k_scan_c() {
    int i = blockIdx.x * SCAN_CHUNK + threadIdx.x;
    if (i >= NN) return;
    int o = g_off[i] + g_csum[blockIdx.x];
    g_off[i] = o;
    g_cur[i] = o;
}

// scatter: decode raw edge buffer directly (src+dst), CSR-place src by dst.
__global__ void k_scatter(const void* __restrict__ eiv) {
    int e = blockIdx.x * blockDim.x + threadIdx.x;
    if (e >= ET) return;
    int s, d;
    if (e < ER) {
        if (g_fmt == 0) {
            const long long* ei = (const long long*)eiv;
            s = (int)ei[e]; d = (int)ei[ER + e];
        } else {
            const int* ei = (const int*)eiv;
            s = ei[e]; d = ei[ER + e];
        }
        s = clampi(s); d = clampi(d);
    } else {
        s = e - ER; d = s;
    }
    int pos = atomicAdd(&g_cur[d], 1);
    g_csrc[pos] = s;
}

// h1 = x @ W1 via wmma bf16; x converted fp32->bf16 in-kernel (smem stage).
__global__ void k_gemm1(const float* __restrict__ x,
                        const float* __restrict__ aS, const float* __restrict__ aD) {
    __shared__ __nv_bfloat16 Ash[64][136];
    __shared__ float Csh[64][96];
    int tid = threadIdx.x;
    int wid = tid >> 5, tx = tid & 31;
    int base = blockIdx.x * 64;

    #pragma unroll
    for (int i = 0; i < 8; i++) {
        int idx4 = tid + 256 * i;
        int row = idx4 >> 5, c4 = (idx4 & 31) * 4;
        int gr = base + row;
        float4 v = (gr < NN) ? *(const float4*)&x[gr * INCH + c4]
                             : make_float4(0.f, 0.f, 0.f, 0.f);
        *(uint2*)&Ash[row][c4] = make_uint2(packbf(v.x, v.y), packbf(v.z, v.w));
    }
    __syncthreads();

    int mt  = wid >> 1;
    int nt0 = (wid & 1) * 3;
    wmma::fragment<wmma::matrix_a, 16, 16, 16, __nv_bfloat16, wmma::row_major> fa;
    wmma::fragment<wmma::matrix_b, 16, 16, 16, __nv_bfloat16, wmma::row_major> fb;
    wmma::fragment<wmma::accumulator, 16, 16, 16, float> fc[3];
    #pragma unroll
    for (int t = 0; t < 3; t++) wmma::fill_fragment(fc[t], 0.f);
    #pragma unroll
    for (int k0 = 0; k0 < INCH; k0 += 16) {
        wmma::load_matrix_sync(fa, &Ash[mt * 16][k0], 136);
        #pragma unroll
        for (int t = 0; t < 3; t++) {
            wmma::load_matrix_sync(fb, g_W1b + k0 * J1 + (nt0 + t) * 16, J1);
            wmma::mma_sync(fc[t], fa, fb, fc[t]);
        }
    }
    #pragma unroll
    for (int t = 0; t < 3; t++)
        wmma::store_matrix_sync(&Csh[mt * 16][(nt0 + t) * 16], fc[t], J1, wmma::mem_row_major);
    __syncthreads();

    float aSv[3], aDv[3];
    #pragma unroll
    for (int c = 0; c < 3; c++) { aSv[c] = aS[c * 32 + tx]; aDv[c] = aD[c * 32 + tx]; }
    #pragma unroll
    for (int i = 0; i < 8; i++) {
        int lrow = wid * 8 + i;
        int row = base + lrow;
        if (row >= NN) continue;            // warp-uniform
        #pragma unroll
        for (int c = 0; c < 3; c++) {
            float v0 = Csh[lrow][c * 32 + tx];
            float v1 = __shfl_down_sync(0xffffffffu, v0, 1);
            float v2 = __shfl_down_sync(0xffffffffu, v0, 2);
            float v3 = __shfl_down_sync(0xffffffffu, v0, 3);
            if (!(tx & 3))
                g_h1b[row * NW1 + c * 8 + (tx >> 2)] = pack4_fp8(v0, v1, v2, v3);
            float vs = bsum(v0 * aSv[c]);
            float vd = bsum(v0 * aDv[c]);
            if (tx == 0) { g_as1[row * 4 + c] = vs; g_ad1[row * 4 + c] = vd; }
        }
    }
}

// Fused layer-1 softmax + aggregation. Warp per dst node.
// 4 edges per inner iteration; o1 written as packed bf16x2.
__global__ void k_fagg1() {
    int d = (int)((blockIdx.x * blockDim.x + threadIdx.x) >> 5);
    int lane = threadIdx.x & 31;
    if (d >= NN) return;
    int sub = lane >> 3, l8 = lane & 7;
    int beg = g_off[d], end = g_off[d + 1];
    float4 adv = *(const float4*)&g_ad1[d * 4];
    float4 a0 = {0.f,0.f,0.f,0.f}, a1 = {0.f,0.f,0.f,0.f}, a2 = {0.f,0.f,0.f,0.f};
    float sp0 = 0.f, sp1 = 0.f, sp2 = 0.f;
    for (int j = beg; j < end; j += 32) {
        int n = end - j; if (n > 32) n = 32;
        int s = 0; float p0 = 0.f, p1 = 0.f, p2 = 0.f;
        if (lane < n) {
            s = g_csrc[j + lane];
            float4 a = *(const float4*)&g_as1[s * 4];
            p0 = lrelu_exp(a.x + adv.x);
            p1 = lrelu_exp(a.y + adv.y);
            p2 = lrelu_exp(a.z + adv.z);
            sp0 += p0; sp1 += p1; sp2 += p2;
        }
        for (int i = 0; i < n; i += 4) {
            int e2 = (i + sub) & 31;
            int   si = __shfl_sync(0xffffffffu, s,  e2);
            float q0 = __shfl_sync(0xffffffffu, p0, e2);
            float q1 = __shfl_sync(0xffffffffu, p1, e2);
            float q2 = __shfl_sync(0xffffffffu, p2, e2);
            if (i + sub < n) {
                const unsigned* hw = &g_h1b[si * NW1 + l8];
                float4 v0 = unpack4_fp8(hw[0]);
                float4 v1 = unpack4_fp8(hw[8]);
                float4 v2 = unpack4_fp8(hw[16]);
                a0.x += q0 * v0.x; a0.y += q0 * v0.y; a0.z += q0 * v0.z; a0.w += q0 * v0.w;
                a1.x += q1 * v1.x; a1.y += q1 * v1.y; a1.z += q1 * v1.z; a1.w += q1 * v1.w;
                a2.x += q2 * v2.x; a2.y += q2 * v2.y; a2.z += q2 * v2.z; a2.w += q2 * v2.w;
            }
        }
    }
    #pragma unroll
    for (int o = 8; o <= 16; o <<= 1) {
        a0.x += __shfl_xor_sync(0xffffffffu, a0.x, o); a0.y += __shfl_xor_sync(0xffffffffu, a0.y, o);
        a0.z += __shfl_xor_sync(0xffffffffu, a0.z, o); a0.w += __shfl_xor_sync(0xffffffffu, a0.w, o);
        a1.x += __shfl_xor_sync(0xffffffffu, a1.x, o); a1.y += __shfl_xor_sync(0xffffffffu, a1.y, o);
        a1.z += __shfl_xor_sync(0xffffffffu, a1.z, o); a1.w += __shfl_xor_sync(0xffffffffu, a1.w, o);
        a2.x += __shfl_xor_sync(0xffffffffu, a2.x, o); a2.y += __shfl_xor_sync(0xffffffffu, a2.y, o);
        a2.z += __shfl_xor_sync(0xffffffffu, a2.z, o); a2.w += __shfl_xor_sync(0xffffffffu, a2.w, o);
    }
    sp0 = bsum(sp0); sp1 = bsum(sp1); sp2 = bsum(sp2);
    float r0 = 1.f / (sp0 + 1e-16f);
    float r1 = 1.f / (sp1 + 1e-16f);
    float r2 = 1.f / (sp2 + 1e-16f);
    if (sub == 0) {
        unsigned* ob = &g_o1b[d * NO1];
        *(uint2*)&ob[2 * l8]      = make_uint2(packbf(a0.x * r0, a0.y * r0), packbf(a0.z * r0, a0.w * r0));
        *(uint2*)&ob[16 + 2 * l8] = make_uint2(packbf(a1.x * r1, a1.y * r1), packbf(a1.z * r1, a1.w * r1));
        *(uint2*)&ob[32 + 2 * l8] = make_uint2(packbf(a2.x * r2, a2.y * r2), packbf(a2.z * r2, a2.w * r2));
    }
}

// h2 = elu(o1 + b1) @ W2 via wmma bf16; o1 read as bf16, bias+ELU in fp32.
__global__ void k_gemm2(const float* __restrict__ b1,
                        const float* __restrict__ aS, const float* __restrict__ aD) {
    __shared__ __nv_bfloat16 Xb[64][104];
    __shared__ float Csh[64][32];
    int tid = threadIdx.x;
    int wid = tid >> 5, tx = tid & 31;
    int base = blockIdx.x * 64;

    // stage: 64 rows x 48 words, uint4 per thread-iter (8 channels), 3 iters
    #pragma unroll
    for (int i = 0; i < 3; i++) {
        int idx = tid + 256 * i;              // 0..767
        int row = idx / 12, g = idx % 12;     // 12 uint4 groups of 8 ch
        int gr = base + row;
        uint4 w = (gr < NN) ? *(const uint4*)&g_o1b[gr * NO1 + 4 * g]
                            : make_uint4(0u, 0u, 0u, 0u);
        float2 f0 = unpackbf(w.x), f1 = unpackbf(w.y), f2 = unpackbf(w.z), f3 = unpackbf(w.w);
        float4 ba = *(const float4*)&b1[8 * g];
        float4 bb = *(const float4*)&b1[8 * g + 4];
        float e0 = f0.x + ba.x, e1 = f0.y + ba.y, e2 = f1.x + ba.z, e3 = f1.y + ba.w;
        float e4 = f2.x + bb.x, e5 = f2.y + bb.y, e6 = f3.x + bb.z, e7 = f3.y + bb.w;
        e0 = e0 > 0.f ? e0 : (__expf(e0) - 1.f);
        e1 = e1 > 0.f ? e1 : (__expf(e1) - 1.f);
        e2 = e2 > 0.f ? e2 : (__expf(e2) - 1.f);
        e3 = e3 > 0.f ? e3 : (__expf(e3) - 1.f);
        e4 = e4 > 0.f ? e4 : (__expf(e4) - 1.f);
        e5 = e5 > 0.f ? e5 : (__expf(e5) - 1.f);
        e6 = e6 > 0.f ? e6 : (__expf(e6) - 1.f);
        e7 = e7 > 0.f ? e7 : (__expf(e7) - 1.f);
        uint4 o;
        o.x = packbf(e0, e1); o.y = packbf(e2, e3);
        o.z = packbf(e4, e5); o.w = packbf(e6, e7);
        *(uint4*)&Xb[row][8 * g] = o;
    }
    __syncthreads();

    int mt = wid >> 1, nt = wid & 1;
    wmma::fragment<wmma::matrix_a, 16, 16, 16, __nv_bfloat16, wmma::row_major> fa;
    wmma::fragment<wmma::matrix_b, 16, 16, 16, __nv_bfloat16, wmma::row_major> fb;
    wmma::fragment<wmma::accumulator, 16, 16, 16, float> fc;
    wmma::fill_fragment(fc, 0.f);
    #pragma unroll
    for (int k0 = 0; k0 < J1; k0 += 16) {
        wmma::load_matrix_sync(fa, &Xb[mt * 16][k0], 104);
        wmma::load_matrix_sync(fb, g_W2b + k0 * OC + nt * 16, OC);
        wmma::mma_sync(fc, fa, fb, fc);
    }
    wmma::store_matrix_sync(&Csh[mt * 16][nt * 16], fc, OC, wmma::mem_row_major);
    __syncthreads();

    float aws = aS[tx], awd = aD[tx];
    #pragma unroll
    for (int i = 0; i < 8; i++) {
        int lrow = wid * 8 + i;
        int row = base + lrow;
        if (row >= NN) continue;            // warp-uniform
        float v0 = Csh[lrow][tx];
        float v1 = __shfl_down_sync(0xffffffffu, v0, 1);
        float v2 = __shfl_down_sync(0xffffffffu, v0, 2);
        float v3 = __shfl_down_sync(0xffffffffu, v0, 3);
        if (!(tx & 3)) g_h2b[row * NW2 + (tx >> 2)] = pack4_fp8(v0, v1, v2, v3);
        float vs = bsum(v0 * aws);
        float vd = bsum(v0 * awd);
        if (tx == 0) { g_as2[row] = vs; g_ad2[row] = vd; }
    }
}

// Fused layer-2: softmax + aggregation + bias + project + sigmoid.
__global__ void k_fagg2(const float* __restrict__ b2, const float* __restrict__ Wp,
                        const float* __restrict__ bp, float* __restrict__ out) {
    int d = (int)((blockIdx.x * blockDim.x + threadIdx.x) >> 5);
    int lane = threadIdx.x & 31;
    if (d >= NN) return;
    int sub = lane >> 3, l8 = lane & 7;
    int beg = g_off[d], end = g_off[d + 1];
    float adv = g_ad2[d];
    float4 acc = {0.f, 0.f, 0.f, 0.f};
    float sp = 0.f;
    for (int j = beg; j < end; j += 32) {
        int n = end - j; if (n > 32) n = 32;
        int s = 0; float p = 0.f;
        if (lane < n) {
            s = g_csrc[j + lane];
            p = lrelu_exp(g_as2[s] + adv);
            sp += p;
        }
        for (int i = 0; i < n; i += 4) {
            int e2 = (i + sub) & 31;
            int   si = __shfl_sync(0xffffffffu, s, e2);
            float q  = __shfl_sync(0xffffffffu, p, e2);
            if (i + sub < n) {
                float4 v = unpack4_fp8(g_h2b[si * NW2 + l8]);
                acc.x += q * v.x; acc.y += q * v.y;
                acc.z += q * v.z; acc.w += q * v.w;
            }
        }
    }
    sp = bsum(sp);
    #pragma unroll
    for (int o = 8; o <= 16; o <<= 1) {
        acc.x += __shfl_xor_sync(0xffffffffu, acc.x, o);
        acc.y += __shfl_xor_sync(0xffffffffu, acc.y, o);
        acc.z += __shfl_xor_sync(0xffffffffu, acc.z, o);
        acc.w += __shfl_xor_sync(0xffffffffu, acc.w, o);
    }
    float r = 1.f / (sp + 1e-16f);
    float t = 0.f;
    if (sub == 0) {
        float o0 = acc.x * r + b2[4 * l8 + 0];
        float o1 = acc.y * r + b2[4 * l8 + 1];
        float o2 = acc.z * r + b2[4 * l8 + 2];
        float o3 = acc.w * r + b2[4 * l8 + 3];
        t = o0 * Wp[4 * l8 + 0] + o1 * Wp[4 * l8 + 1]
          + o2 * Wp[4 * l8 + 2] + o3 * Wp[4 * l8 + 3];
    }
    t = bsum(t);
    if (lane == 0) out[d] = 1.f / (1.f + __expf(-t - bp[0]));
}

// ---------------- launch ----------------
extern "C" void kernel_launch(void* const* d_in, const int* in_sizes, int n_in,
                              void* d_out, int out_size) {
    const float* x   = (const float*)d_in[0];
    const void*  ei  = d_in[1];
    const float* W1  = (const float*)d_in[2];
    const float* as1 = (const float*)d_in[3];
    const float* ad1 = (const float*)d_in[4];
    const float* b1  = (const float*)d_in[5];
    const float* W2  = (const float*)d_in[6];
    const float* as2 = (const float*)d_in[7];
    const float* ad2 = (const float*)d_in[8];
    const float* b2  = (const float*)d_in[9];
    const float* Wp  = (const float*)d_in[10];
    const float* bp  = (const float*)d_in[11];
    float* out = (float*)d_out;

    const int nodeWarpBlocks = (NN * 32 + 255) / 256;   // warp per node

    k_init<<<(NN + 255) / 256, 256>>>((const int*)ei, W1, W2);
    k_hist<<<(ER + 255) / 256, 256>>>(ei);
    k_scan_a<<<NCHUNK, SCAN_CHUNK>>>();
    k_scan_b<<<1, 64>>>();
    k_scan_c<<<NCHUNK, SCAN_CHUNK>>>();
    k_scatter<<<(ET + 255) / 256, 256>>>(ei);
    k_gemm1<<<PADN / 64, 256>>>(x, as1, ad1);
    k_fagg1<<<nodeWarpBlocks, 256>>>();
    k_gemm2<<<PADN / 64, 256>>>(b1, as2, ad2);
    k_fagg2<<<nodeWarpBlocks, 256>>>(b2, Wp, bp, out);
}

// round 15
// speedup vs baseline: 4.1314x; 1.0021x over previous
#include <cuda_runtime.h>
#include <cuda_bf16.h>
#include <cuda_fp16.h>
#include <mma.h>
using namespace nvcuda;

#define NN     50000
#define PADN   50048          // 64-row padded for wmma tiles
#define ER     1600000
#define ET     1650000        // edges + self loops
#define INCH   128
#define J1     96             // HEADS*HID
#define HEADS  3
#define HID    32
#define OC     32
#define NEG    0.2f

#define NW1    24             // h1 fp8x4 words per node (96 ch)
#define NW2    8              // h2 fp8x4 words per node (32 ch)
#define NO1    48             // o1 bf16x2 words per node (96 ch)

#define SCAN_CHUNK 1024
#define NCHUNK ((NN + SCAN_CHUNK - 1) / SCAN_CHUNK)   // 49

// ---------------- scratch (device globals; no allocation allowed) ----------------
__device__ int   g_fmt;                       // 0 = int64 edge buffer, 1 = int32
__device__ __align__(16) int                g_deg [NN];
__device__ __align__(16) int                g_off [NN + 1];
__device__ __align__(16) int                g_cur [NN];
__device__ __align__(16) unsigned long long g_stat[NCHUNK];  // decoupled-lookback status
__device__ __align__(16) int                g_csrc[ET];      // CSR: src ids sorted by dst
__device__ __align__(16) __nv_bfloat16      g_W1b [INCH * J1];
__device__ __align__(16) __nv_bfloat16      g_W2b [J1 * OC];
__device__ __align__(16) unsigned           g_h1b [NN * NW1]; // h1 fp8x4 (e4m3)
__device__ __align__(16) float              g_as1 [NN * 4];
__device__ __align__(16) float              g_ad1 [NN * 4];
__device__ __align__(16) unsigned           g_o1b [NN * NO1]; // o1 bf16x2
__device__ __align__(16) unsigned           g_h2b [NN * NW2]; // h2 fp8x4 (e4m3)
__device__ __align__(16) float              g_as2 [NN];
__device__ __align__(16) float              g_ad2 [NN];

// ---------------- helpers ----------------
__device__ __forceinline__ float bsum(float v) {
    v += __shfl_xor_sync(0xffffffffu, v, 16);
    v += __shfl_xor_sync(0xffffffffu, v, 8);
    v += __shfl_xor_sync(0xffffffffu, v, 4);
    v += __shfl_xor_sync(0xffffffffu, v, 2);
    v += __shfl_xor_sync(0xffffffffu, v, 1);
    return v;
}
__device__ __forceinline__ int clampi(int v) {
    return v < 0 ? 0 : (v >= NN ? NN - 1 : v);
}
__device__ __forceinline__ float lrelu_exp(float v) {
    v = v > 0.f ? v : NEG * v;
    return __expf(v);
}
__device__ __forceinline__ unsigned packbf(float a, float b) {
    __nv_bfloat162 t = __floats2bfloat162_rn(a, b);
    return *(unsigned*)&t;
}
__device__ __forceinline__ float2 unpackbf(unsigned u) {
    __nv_bfloat162 t = *(__nv_bfloat162*)&u;
    return __bfloat1622float2(t);
}
__device__ __forceinline__ unsigned pack4_fp8(float c0, float c1, float c2, float c3) {
    unsigned short lo, hi;
    asm("cvt.rn.satfinite.e4m3x2.f32 %0, %1, %2;" : "=h"(lo) : "f"(c1), "f"(c0));
    asm("cvt.rn.satfinite.e4m3x2.f32 %0, %1, %2;" : "=h"(hi) : "f"(c3), "f"(c2));
    return ((unsigned)hi << 16) | (unsigned)lo;
}
__device__ __forceinline__ float4 unpack4_fp8(unsigned u) {
    unsigned h0, h1;
    unsigned short lo = (unsigned short)(u & 0xffffu), hi = (unsigned short)(u >> 16);
    asm("cvt.rn.f16x2.e4m3x2 %0, %1;" : "=r"(h0) : "h"(lo));
    asm("cvt.rn.f16x2.e4m3x2 %0, %1;" : "=r"(h1) : "h"(hi));
    __half2 a = *(__half2*)&h0, b = *(__half2*)&h1;
    float2 fa = __half22float2(a), fb = __half22float2(b);
    return make_float4(fa.x, fa.y, fb.x, fb.y);
}

// ---------------- kernels ----------------
// init: zero deg + scan status; detect edge dtype (block 0); convert W1/W2; off[NN]=ET.
__global__ void k_init(const int* __restrict__ ei32,
                       const float* __restrict__ W1, const float* __restrict__ W2) {
    int i = blockIdx.x * blockDim.x + threadIdx.x;
    if (i < NN) g_deg[i] = 0;
    if (i < NCHUNK) g_stat[i] = 0ull;
    if (i == 0) g_off[NN] = ET;
    int w = i * 4;
    if (w < INCH * J1) {
        float4 v = *(const float4*)&W1[w];
        *(uint2*)&g_W1b[w] = make_uint2(packbf(v.x, v.y), packbf(v.z, v.w));
    }
    if (w < J1 * OC) {
        float4 v = *(const float4*)&W2[w];
        *(uint2*)&g_W2b[w] = make_uint2(packbf(v.x, v.y), packbf(v.z, v.w));
    }
    if (blockIdx.x == 0) {
        __shared__ int nz;
        if (threadIdx.x == 0) nz = 0;
        __syncthreads();
        for (int k = threadIdx.x; k < 2048; k += blockDim.x)
            if (ei32[2 * k * 391 + 1] != 0) atomicOr(&nz, 1);
        __syncthreads();
        if (threadIdx.x == 0) g_fmt = nz ? 1 : 0;
    }
}

// histogram of dst degrees; 2 edges per thread (dst half only).
__global__ void k_hist(const void* __restrict__ eiv) {
    int t = blockIdx.x * blockDim.x + threadIdx.x;
    if (t >= ER / 2) return;
    int d0, d1;
    if (g_fmt == 0) {
        longlong2 v = ((const longlong2*)eiv)[ER / 2 + t];
        d0 = (int)v.x; d1 = (int)v.y;
    } else {
        int2 v = ((const int2*)eiv)[ER / 2 + t];
        d0 = v.x; d1 = v.y;
    }
    atomicAdd(&g_deg[clampi(d0)], 1);
    atomicAdd(&g_deg[clampi(d1)], 1);
}

// Single-pass exclusive scan of (deg+1) with decoupled lookback.
// 49 blocks (one resident wave). Also fills g_cur and places self-loops.
__global__ void k_scan() {
    __shared__ int warpsums[32];
    __shared__ int sh_T, sh_run;
    int tid = threadIdx.x, lane = tid & 31, wid = tid >> 5;
    int bid = blockIdx.x;
    int i = bid * SCAN_CHUNK + tid;
    int v = (i < NN) ? (g_deg[i] + 1) : 0;    // +1: self loop
    int x = v;
    #pragma unroll
    for (int o = 1; o < 32; o <<= 1) {
        int y = __shfl_up_sync(0xffffffffu, x, o);
        if (lane >= o) x += y;
    }
    if (lane == 31) warpsums[wid] = x;
    __syncthreads();
    if (wid == 0) {
        int sv = warpsums[lane];
        #pragma unroll
        for (int o = 1; o < 32; o <<= 1) {
            int y = __shfl_up_sync(0xffffffffu, sv, o);
            if (lane >= o) sv += y;
        }
        warpsums[lane] = sv;
    }
    __syncthreads();
    int incl = x + (wid > 0 ? warpsums[wid - 1] : 0);
    if (tid == SCAN_CHUNK - 1) sh_T = incl;
    __syncthreads();
    int T = sh_T;
    // publish aggregate (or inclusive for block 0)
    if (tid == 0) {
        unsigned long long st = ((unsigned long long)T << 2) | (bid == 0 ? 2ull : 1ull);
        __threadfence();
        atomicExch(&g_stat[bid], st);
        if (bid == 0) sh_run = 0;
    }
    if (bid > 0 && tid < 32) {
        int running = 0;
        int j = bid - 1;
        while (true) {
            int idx = j - (int)tid;
            unsigned long long st;
            do {
                st = (idx >= 0) ? atomicAdd(&g_stat[idx], 0ull) : 2ull;
            } while (__any_sync(0xffffffffu, (st & 3ull) == 0ull));
            unsigned pm = __ballot_sync(0xffffffffu, (st & 3ull) == 2ull);
            int firstP = __ffs(pm) - 1;        // lowest lane with a prefix (largest idx)
            int contrib = ((int)tid <= firstP || firstP < 0) ? (int)(st >> 2) : 0;
            #pragma unroll
            for (int o = 16; o; o >>= 1) contrib += __shfl_xor_sync(0xffffffffu, contrib, o);
            running += contrib;
            if (firstP >= 0) break;
            j -= 32;
        }
        if (tid == 0) {
            sh_run = running;
            unsigned long long st2 = (((unsigned long long)(running + T)) << 2) | 2ull;
            __threadfence();
            atomicExch(&g_stat[bid], st2);
        }
    }
    __syncthreads();
    int off = sh_run + incl - v;
    if (i < NN) {
        g_off[i] = off;
        g_cur[i] = off;                 // real edges fill off .. off+deg-1
        g_csrc[off + v - 1] = i;        // self loop at the last slot
    }
}

// scatter real edges only; 2 edges per thread.
__global__ void k_scatter(const void* __restrict__ eiv) {
    int t = blockIdx.x * blockDim.x + threadIdx.x;
    if (t >= ER / 2) return;
    int s0, s1, d0, d1;
    if (g_fmt == 0) {
        longlong2 sp = ((const longlong2*)eiv)[t];
        longlong2 dp = ((const longlong2*)eiv)[ER / 2 + t];
        s0 = (int)sp.x; s1 = (int)sp.y; d0 = (int)dp.x; d1 = (int)dp.y;
    } else {
        int2 sp = ((const int2*)eiv)[t];
        int2 dp = ((const int2*)eiv)[ER / 2 + t];
        s0 = sp.x; s1 = sp.y; d0 = dp.x; d1 = dp.y;
    }
    s0 = clampi(s0); s1 = clampi(s1); d0 = clampi(d0); d1 = clampi(d1);
    int p0 = atomicAdd(&g_cur[d0], 1);
    g_csrc[p0] = s0;
    int p1 = atomicAdd(&g_cur[d1], 1);
    g_csrc[p1] = s1;
}

// h1 = x @ W1 via wmma bf16; x converted fp32->bf16 in-kernel (smem stage).
__global__ void k_gemm1(const float* __restrict__ x,
                        const float* __restrict__ aS, const float* __restrict__ aD) {
    __shared__ __nv_bfloat16 Ash[64][136];
    __shared__ float Csh[64][96];
    int tid = threadIdx.x;
    int wid = tid >> 5, tx = tid & 31;
    int base = blockIdx.x * 64;

    #pragma unroll
    for (int i = 0; i < 8; i++) {
        int idx4 = tid + 256 * i;
        int row = idx4 >> 5, c4 = (idx4 & 31) * 4;
        int gr = base + row;
        float4 v = (gr < NN) ? *(const float4*)&x[gr * INCH + c4]
                             : make_float4(0.f, 0.f, 0.f, 0.f);
        *(uint2*)&Ash[row][c4] = make_uint2(packbf(v.x, v.y), packbf(v.z, v.w));
    }
    __syncthreads();

    int mt  = wid >> 1;
    int nt0 = (wid & 1) * 3;
    wmma::fragment<wmma::matrix_a, 16, 16, 16, __nv_bfloat16, wmma::row_major> fa;
    wmma::fragment<wmma::matrix_b, 16, 16, 16, __nv_bfloat16, wmma::row_major> fb;
    wmma::fragment<wmma::accumulator, 16, 16, 16, float> fc[3];
    #pragma unroll
    for (int t = 0; t < 3; t++) wmma::fill_fragment(fc[t], 0.f);
    #pragma unroll
    for (int k0 = 0; k0 < INCH; k0 += 16) {
        wmma::load_matrix_sync(fa, &Ash[mt * 16][k0], 136);
        #pragma unroll
        for (int t = 0; t < 3; t++) {
            wmma::load_matrix_sync(fb, g_W1b + k0 * J1 + (nt0 + t) * 16, J1);
            wmma::mma_sync(fc[t], fa, fb, fc[t]);
        }
    }
    #pragma unroll
    for (int t = 0; t < 3; t++)
        wmma::store_matrix_sync(&Csh[mt * 16][(nt0 + t) * 16], fc[t], J1, wmma::mem_row_major);
    __syncthreads();

    float aSv[3], aDv[3];
    #pragma unroll
    for (int c = 0; c < 3; c++) { aSv[c] = aS[c * 32 + tx]; aDv[c] = aD[c * 32 + tx]; }
    #pragma unroll
    for (int i = 0; i < 8; i++) {
        int lrow = wid * 8 + i;
        int row = base + lrow;
        if (row >= NN) continue;            // warp-uniform
        #pragma unroll
        for (int c = 0; c < 3; c++) {
            float v0 = Csh[lrow][c * 32 + tx];
            float v1 = __shfl_down_sync(0xffffffffu, v0, 1);
            float v2 = __shfl_down_sync(0xffffffffu, v0, 2);
            float v3 = __shfl_down_sync(0xffffffffu, v0, 3);
            if (!(tx & 3))
                g_h1b[row * NW1 + c * 8 + (tx >> 2)] = pack4_fp8(v0, v1, v2, v3);
            float vs = bsum(v0 * aSv[c]);
            float vd = bsum(v0 * aDv[c]);
            if (tx == 0) { g_as1[row * 4 + c] = vs; g_ad1[row * 4 + c] = vd; }
        }
    }
}

// Fused layer-1 softmax + aggregation. Warp per dst node.
__global__ void k_fagg1() {
    int d = (int)((blockIdx.x * blockDim.x + threadIdx.x) >> 5);
    int lane = threadIdx.x & 31;
    if (d >= NN) return;
    int sub = lane >> 3, l8 = lane & 7;
    int beg = g_off[d], end = g_off[d + 1];
    float4 adv = *(const float4*)&g_ad1[d * 4];
    float4 a0 = {0.f,0.f,0.f,0.f}, a1 = {0.f,0.f,0.f,0.f}, a2 = {0.f,0.f,0.f,0.f};
    float sp0 = 0.f, sp1 = 0.f, sp2 = 0.f;
    for (int j = beg; j < end; j += 32) {
        int n = end - j; if (n > 32) n = 32;
        int s = 0; float p0 = 0.f, p1 = 0.f, p2 = 0.f;
        if (lane < n) {
            s = g_csrc[j + lane];
            float4 a = *(const float4*)&g_as1[s * 4];
            p0 = lrelu_exp(a.x + adv.x);
            p1 = lrelu_exp(a.y + adv.y);
            p2 = lrelu_exp(a.z + adv.z);
            sp0 += p0; sp1 += p1; sp2 += p2;
        }
        for (int i = 0; i < n; i += 4) {
            int e2 = (i + sub) & 31;
            int   si = __shfl_sync(0xffffffffu, s,  e2);
            float q0 = __shfl_sync(0xffffffffu, p0, e2);
            float q1 = __shfl_sync(0xffffffffu, p1, e2);
            float q2 = __shfl_sync(0xffffffffu, p2, e2);
            if (i + sub < n) {
                const unsigned* hw = &g_h1b[si * NW1 + l8];
                float4 v0 = unpack4_fp8(hw[0]);
                float4 v1 = unpack4_fp8(hw[8]);
                float4 v2 = unpack4_fp8(hw[16]);
                a0.x += q0 * v0.x; a0.y += q0 * v0.y; a0.z += q0 * v0.z; a0.w += q0 * v0.w;
                a1.x += q1 * v1.x; a1.y += q1 * v1.y; a1.z += q1 * v1.z; a1.w += q1 * v1.w;
                a2.x += q2 * v2.x; a2.y += q2 * v2.y; a2.z += q2 * v2.z; a2.w += q2 * v2.w;
            }
        }
    }
    #pragma unroll
    for (int o = 8; o <= 16; o <<= 1) {
        a0.x += __shfl_xor_sync(0xffffffffu, a0.x, o); a0.y += __shfl_xor_sync(0xffffffffu, a0.y, o);
        a0.z += __shfl_xor_sync(0xffffffffu, a0.z, o); a0.w += __shfl_xor_sync(0xffffffffu, a0.w, o);
        a1.x += __shfl_xor_sync(0xffffffffu, a1.x, o); a1.y += __shfl_xor_sync(0xffffffffu, a1.y, o);
        a1.z += __shfl_xor_sync(0xffffffffu, a1.z, o); a1.w += __shfl_xor_sync(0xffffffffu, a1.w, o);
        a2.x += __shfl_xor_sync(0xffffffffu, a2.x, o); a2.y += __shfl_xor_sync(0xffffffffu, a2.y, o);
        a2.z += __shfl_xor_sync(0xffffffffu, a2.z, o); a2.w += __shfl_xor_sync(0xffffffffu, a2.w, o);
    }
    sp0 = bsum(sp0); sp1 = bsum(sp1); sp2 = bsum(sp2);
    float r0 = 1.f / (sp0 + 1e-16f);
    float r1 = 1.f / (sp1 + 1e-16f);
    float r2 = 1.f / (sp2 + 1e-16f);
    if (sub == 0) {
        unsigned* ob = &g_o1b[d * NO1];
        *(uint2*)&ob[2 * l8]      = make_uint2(packbf(a0.x * r0, a0.y * r0), packbf(a0.z * r0, a0.w * r0));
        *(uint2*)&ob[16 + 2 * l8] = make_uint2(packbf(a1.x * r1, a1.y * r1), packbf(a1.z * r1, a1.w * r1));
        *(uint2*)&ob[32 + 2 * l8] = make_uint2(packbf(a2.x * r2, a2.y * r2), packbf(a2.z * r2, a2.w * r2));
    }
}

// h2 = elu(o1 + b1) @ W2 via wmma bf16; o1 read as bf16, bias+ELU in fp32.
__global__ void k_gemm2(const float* __restrict__ b1,
                        const float* __restrict__ aS, const float* __restrict__ aD) {
    __shared__ __nv_bfloat16 Xb[64][104];
    __shared__ float Csh[64][32];
    int tid = threadIdx.x;
    int wid = tid >> 5, tx = tid & 31;
    int base = blockIdx.x * 64;

    #pragma unroll
    for (int i = 0; i < 3; i++) {
        int idx = tid + 256 * i;
        int row = idx / 12, g = idx % 12;
        int gr = base + row;
        uint4 w = (gr < NN) ? *(const uint4*)&g_o1b[gr * NO1 + 4 * g]
                            : make_uint4(0u, 0u, 0u, 0u);
        float2 f0 = unpackbf(w.x), f1 = unpackbf(w.y), f2 = unpackbf(w.z), f3 = unpackbf(w.w);
        float4 ba = *(const float4*)&b1[8 * g];
        float4 bb = *(const float4*)&b1[8 * g + 4];
        float e0 = f0.x + ba.x, e1 = f0.y + ba.y, e2 = f1.x + ba.z, e3 = f1.y + ba.w;
        float e4 = f2.x + bb.x, e5 = f2.y + bb.y, e6 = f3.x + bb.z, e7 = f3.y + bb.w;
        e0 = e0 > 0.f ? e0 : (__expf(e0) - 1.f);
        e1 = e1 > 0.f ? e1 : (__expf(e1) - 1.f);
        e2 = e2 > 0.f ? e2 : (__expf(e2) - 1.f);
        e3 = e3 > 0.f ? e3 : (__expf(e3) - 1.f);
        e4 = e4 > 0.f ? e4 : (__expf(e4) - 1.f);
        e5 = e5 > 0.f ? e5 : (__expf(e5) - 1.f);
        e6 = e6 > 0.f ? e6 : (__expf(e6) - 1.f);
        e7 = e7 > 0.f ? e7 : (__expf(e7) - 1.f);
        uint4 o;
        o.x = packbf(e0, e1); o.y = packbf(e2, e3);
        o.z = packbf(e4, e5); o.w = packbf(e6, e7);
        *(uint4*)&Xb[row][8 * g] = o;
    }
    __syncthreads();

    int mt = wid >> 1, nt = wid & 1;
    wmma::fragment<wmma::matrix_a, 16, 16, 16, __nv_bfloat16, wmma::row_major> fa;
    wmma::fragment<wmma::matrix_b, 16, 16, 16, __nv_bfloat16, wmma::row_major> fb;
    wmma::fragment<wmma::accumulator, 16, 16, 16, float> fc;
    wmma::fill_fragment(fc, 0.f);
    #pragma unroll
    for (int k0 = 0; k0 < J1; k0 += 16) {
        wmma::load_matrix_sync(fa, &Xb[mt * 16][k0], 104);
        wmma::load_matrix_sync(fb, g_W2b + k0 * OC + nt * 16, OC);
        wmma::mma_sync(fc, fa, fb, fc);
    }
    wmma::store_matrix_sync(&Csh[mt * 16][nt * 16], fc, OC, wmma::mem_row_major);
    __syncthreads();

    float aws = aS[tx], awd = aD[tx];
    #pragma unroll
    for (int i = 0; i < 8; i++) {
        int lrow = wid * 8 + i;
        int row = base + lrow;
        if (row >= NN) continue;            // warp-uniform
        float v0 = Csh[lrow][tx];
        float v1 = __shfl_down_sync(0xffffffffu, v0, 1);
        float v2 = __shfl_down_sync(0xffffffffu, v0, 2);
        float v3 = __shfl_down_sync(0xffffffffu, v0, 3);
        if (!(tx & 3)) g_h2b[row * NW2 + (tx >> 2)] = pack4_fp8(v0, v1, v2, v3);
        float vs = bsum(v0 * aws);
        float vd = bsum(v0 * awd);
        if (tx == 0) { g_as2[row] = vs; g_ad2[row] = vd; }
    }
}

// Fused layer-2: softmax + aggregation + bias + project + sigmoid.
__global__ void k_fagg2(const float* __restrict__ b2, const float* __restrict__ Wp,
                        const float* __restrict__ bp, float* __restrict__ out) {
    int d = (int)((blockIdx.x * blockDim.x + threadIdx.x) >> 5);
    int lane = threadIdx.x & 31;
    if (d >= NN) return;
    int sub = lane >> 3, l8 = lane & 7;
    int beg = g_off[d], end = g_off[d + 1];
    float adv = g_ad2[d];
    float4 acc = {0.f, 0.f, 0.f, 0.f};
    float sp = 0.f;
    for (int j = beg; j < end; j += 32) {
        int n = end - j; if (n > 32) n = 32;
        int s = 0; float p = 0.f;
        if (lane < n) {
            s = g_csrc[j + lane];
            p = lrelu_exp(g_as2[s] + adv);
            sp += p;
        }
        for (int i = 0; i < n; i += 4) {
            int e2 = (i + sub) & 31;
            int   si = __shfl_sync(0xffffffffu, s, e2);
            float q  = __shfl_sync(0xffffffffu, p, e2);
            if (i + sub < n) {
                float4 v = unpack4_fp8(g_h2b[si * NW2 + l8]);
                acc.x += q * v.x; acc.y += q * v.y;
                acc.z += q * v.z; acc.w += q * v.w;
            }
        }
    }
    sp = bsum(sp);
    #pragma unroll
    for (int o = 8; o <= 16; o <<= 1) {
        acc.x += __shfl_xor_sync(0xffffffffu, acc.x, o);
        acc.y += __shfl_xor_sync(0xffffffffu, acc.y, o);
        acc.z += __shfl_xor_sync(0xffffffffu, acc.z, o);
        acc.w += __shfl_xor_sync(0xffffffffu, acc.w, o);
    }
    float r = 1.f / (sp + 1e-16f);
    float t = 0.f;
    if (sub == 0) {
        float o0 = acc.x * r + b2[4 * l8 + 0];
        float o1 = acc.y * r + b2[4 * l8 + 1];
        float o2 = acc.z * r + b2[4 * l8 + 2];
        float o3 = acc.w * r + b2[4 * l8 + 3];
        t = o0 * Wp[4 * l8 + 0] + o1 * Wp[4 * l8 + 1]
          + o2 * Wp[4 * l8 + 2] + o3 * Wp[4 * l8 + 3];
    }
    t = bsum(t);
    if (lane == 0) out[d] = 1.f / (1.f + __expf(-t - bp[0]));
}

// ---------------- launch ----------------
extern "C" void kernel_launch(void* const* d_in, const int* in_sizes, int n_in,
                              void* d_out, int out_size) {
    const float* x   = (const float*)d_in[0];
    const void*  ei  = d_in[1];
    const float* W1  = (const float*)d_in[2];
    const float* as1 = (const float*)d_in[3];
    const float* ad1 = (const float*)d_in[4];
    const float* b1  = (const float*)d_in[5];
    const float* W2  = (const float*)d_in[6];
    const float* as2 = (const float*)d_in[7];
    const float* ad2 = (const float*)d_in[8];
    const float* b2  = (const float*)d_in[9];
    const float* Wp  = (const float*)d_in[10];
    const float* bp  = (const float*)d_in[11];
    float* out = (float*)d_out;

    const int nodeWarpBlocks = (NN * 32 + 255) / 256;   // warp per node
    const int edge2Blocks    = (ER / 2 + 255) / 256;    // 2 edges per thread

    k_init<<<(NN + 255) / 256, 256>>>((const int*)ei, W1, W2);
    k_hist<<<edge2Blocks, 256>>>(ei);
    k_scan<<<NCHUNK, SCAN_CHUNK>>>();
    k_scatter<<<edge2Blocks, 256>>>(ei);
    k_gemm1<<<PADN / 64, 256>>>(x, as1, ad1);
    k_fagg1<<<nodeWarpBlocks, 256>>>();
    k_gemm2<<<PADN / 64, 256>>>(b1, as2, ad2);
    k_fagg2<<<nodeWarpBlocks, 256>>>(b2, Wp, bp, out);
}